// round 12
// baseline (speedup 1.0000x reference)
#include <cuda_runtime.h>
#include <cuda_fp16.h>
#include <math.h>
#include <stdint.h>

#define DIMC 512
#define HC 8
#define HDC 64
#define BC 2
#define SC 512
#define BHC 16
#define EPSC 1e-5f

// ---------------- scratch (device globals; no allocation allowed) ----------------
__device__ float  g_qkv[BC * SC * 3 * DIMC];     // [1024][1536] fp32
__device__ float  g_W  [BHC * SC * SC];          // fp32 W
__device__ __half g_Wh [BHC * SC * SC];          // fp16 hi/lo of W
__device__ __half g_Wl [BHC * SC * SC];
__device__ __half g_Wth[BHC * SC * SC];          // fp16 hi/lo of W^T
__device__ __half g_Wtl[BHC * SC * SC];
__device__ __half g_Zth[BHC * SC * SC];          // fp16 hi/lo of Z^T
__device__ __half g_Ztl[BHC * SC * SC];
__device__ __half g_Xh0[BHC * SC * SC];          // X double buffer (hi/lo)
__device__ __half g_Xl0[BHC * SC * SC];
__device__ __half g_Xh1[BHC * SC * SC];
__device__ __half g_Xl1[BHC * SC * SC];
__device__ __half g_Xth0[BHC * SC * SC];         // X^T double buffer (hi/lo)
__device__ __half g_Xtl0[BHC * SC * SC];
__device__ __half g_Xth1[BHC * SC * SC];
__device__ __half g_Xtl1[BHC * SC * SC];
__device__ float  g_Xf [BHC * SC * SC];          // fp32 X5 = W_inv
__device__ __half g_xh [BC * SC * DIMC];         // splits of x
__device__ __half g_xl [BC * SC * DIMC];
__device__ __half g_wqh[3 * DIMC * DIMC];        // splits of qkv_w
__device__ __half g_wql[3 * DIMC * DIMC];
__device__ __half g_pwh[DIMC * DIMC];            // splits of proj_w
__device__ __half g_pwl[DIMC * DIMC];
__device__ __half g_gah[BC * SC * DIMC];         // splits of ga
__device__ __half g_gal[BC * SC * DIMC];
__device__ float  g_ctx [BHC * SC * HDC];
__device__ float  g_ctx2[BHC * SC * HDC];
__device__ float  g_scale[BHC];
__device__ float  g_mu  [HC * SC];
__device__ float  g_rstd[HC * SC];
__device__ float  g_cs_part[8][BHC][SC];         // ns_scale partials
__device__ float  g_rm_part[8][BHC];

// ============================ helpers ============================================
__device__ __forceinline__ uint32_t smem_to_u32(const void* p) {
    uint32_t a;
    asm("{ .reg .u64 t; cvta.to.shared.u64 t, %1; cvt.u32.u64 %0, t; }" : "=r"(a) : "l"(p));
    return a;
}
__device__ __forceinline__ void cpa16h(uint32_t dst, const __half* src) {
    asm volatile("cp.async.cg.shared.global [%0], [%1], 16;" :: "r"(dst), "l"(src));
}
__device__ __forceinline__ void cpa_commit() {
    asm volatile("cp.async.commit_group;" ::: "memory");
}
__device__ __forceinline__ void mma16(float d[4], const uint32_t a[4],
                                      uint32_t b0, uint32_t b1) {
    asm volatile(
        "mma.sync.aligned.m16n8k16.row.col.f32.f16.f16.f32 "
        "{%0,%1,%2,%3}, {%4,%5,%6,%7}, {%8,%9}, {%0,%1,%2,%3};"
        : "+f"(d[0]), "+f"(d[1]), "+f"(d[2]), "+f"(d[3])
        : "r"(a[0]), "r"(a[1]), "r"(a[2]), "r"(a[3]), "r"(b0), "r"(b1));
}
__device__ __forceinline__ void h_split(float v, __half& h, __half& l) {
    h = __float2half_rn(v);
    l = __float2half_rn(v - __half2float(h));
}

// ---------------- elementwise fp16 split ----------------------------------------
__global__ __launch_bounds__(256) void split_f16(
    const float* __restrict__ in, __half* __restrict__ oh, __half* __restrict__ ol)
{
    const int i = blockIdx.x * 256 + threadIdx.x;
    const float4 v = ((const float4*)in)[i];
    __half h0, h1, h2, h3, l0, l1, l2, l3;
    h_split(v.x, h0, l0); h_split(v.y, h1, l1);
    h_split(v.z, h2, l2); h_split(v.w, h3, l3);
    ((__half2*)oh)[2 * i]     = __halves2half2(h0, h1);
    ((__half2*)oh)[2 * i + 1] = __halves2half2(h2, h3);
    ((__half2*)ol)[2 * i]     = __halves2half2(l0, l1);
    ((__half2*)ol)[2 * i + 1] = __halves2half2(l2, l3);
}

// ================= fp16 multi-term GEMM (mma.sync m16n8k16), all NT ==============
// C[m][n] = sum_k A[m][k] * B[n][k].
// TERMS: 3 = AhBh+AhBl+AlBh, 2 = AhBh+AhBl, 1 = AhBh.
// TRIMA: 1 -> A lower-tri (k<=m): kb_end=(m0>>5)+4; 2 -> A upper-tri: kb_start=m0>>5.
// TRIMB: 1 -> B lower-tri (k<=n): kb_end=(n0>>5)+4.
// LO: write low-half output arrays (only needed when a 3-term GEMM consumes C).
// SWAP: 1 -> m0 on blockIdx.x / n0 on blockIdx.y (puts trim-cost axis on y so
//       co-resident CTA pairs (bid, bid+148), which differ by dy=1, balance).
#define MH_ROW 40                    // halves per smem row (32 + pad 8)
#define MH_ARR 5120                  // 128 * 40 halves per array
#define MH_STG_BYTES 40960           // 4 arrays * 10240 B
#define MH_SMEM 81920                // 2 stages

template<int TERMS>
__device__ __forceinline__ void mh_issue(
    const __half* __restrict__ Ah, const __half* __restrict__ Al,
    const __half* __restrict__ Bh, const __half* __restrict__ Bl,
    int lda, int ldb, int m0, int n0, int t, int k0, uint32_t base)
{
#pragma unroll
    for (int i = 0; i < 4; i++) {
        const int idx = t + i * 128;
        const int r = idx >> 2, c8 = (idx & 3) * 8;
        const uint32_t so = (uint32_t)(r * MH_ROW + c8) * 2u;
        cpa16h(base + so,          Ah + (long)(m0 + r) * lda + k0 + c8);
        if (TERMS == 3)
            cpa16h(base + 10240u + so, Al + (long)(m0 + r) * lda + k0 + c8);
        cpa16h(base + 20480u + so, Bh + (long)(n0 + r) * ldb + k0 + c8);
        if (TERMS >= 2)
            cpa16h(base + 30720u + so, Bl + (long)(n0 + r) * ldb + k0 + c8);
    }
    cpa_commit();
}

template<int TERMS, int TRIMA, int TRIMB, int ZDIAG, int SCALE, int BIAS,
         int OF32, int OH, int OT, int LO, int SWAP>
__global__ __launch_bounds__(128, 2) void mma_h(
    const __half* __restrict__ Ah, const __half* __restrict__ Al,
    const __half* __restrict__ Bh, const __half* __restrict__ Bl,
    __half* __restrict__ Ch, __half* __restrict__ Cl,
    __half* __restrict__ CtH, __half* __restrict__ CtL,
    float* __restrict__ Cf, const float* __restrict__ bias,
    int lda, int ldb, int ldc, long aB, long bB, long cB)
{
    extern __shared__ char dsm[];
    const uint32_t sb = smem_to_u32(dsm);
    const int t = threadIdx.x;
    const int w = t >> 5, lane = t & 31;
    const int tg = lane >> 2, tig = lane & 3;
    const int wm = (w & 1) * 64, wn = (w >> 1) * 64;
    const int m0 = (SWAP ? blockIdx.x : blockIdx.y) * 128;
    const int n0 = (SWAP ? blockIdx.y : blockIdx.x) * 128;
    const long zb = blockIdx.z;
    const __half* pAh = Ah + zb * aB;
    const __half* pAl = Al + zb * aB;
    const __half* pBh = Bh + zb * bB;
    const __half* pBl = Bl + zb * bB;

    int kbs = 0, kbe = 16;
    if (TRIMA == 1) { const int e = (m0 >> 5) + 4; if (e < kbe) kbe = e; }
    if (TRIMA == 2) kbs = m0 >> 5;
    if (TRIMB == 1) { const int e = (n0 >> 5) + 4; if (e < kbe) kbe = e; }

    float acc[4][8][4];
#pragma unroll
    for (int i = 0; i < 4; i++)
#pragma unroll
        for (int j = 0; j < 8; j++)
#pragma unroll
            for (int p = 0; p < 4; p++) acc[i][j][p] = 0.f;

    mh_issue<TERMS>(pAh, pAl, pBh, pBl, lda, ldb, m0, n0, t, kbs * 32,
                    sb + (kbs & 1) * MH_STG_BYTES);

    for (int kb = kbs; kb < kbe; kb++) {
        if (kb + 1 < kbe) {
            mh_issue<TERMS>(pAh, pAl, pBh, pBl, lda, ldb, m0, n0, t,
                            (kb + 1) * 32, sb + ((kb + 1) & 1) * MH_STG_BYTES);
            asm volatile("cp.async.wait_group 1;" ::: "memory");
        } else {
            asm volatile("cp.async.wait_group 0;" ::: "memory");
        }
        __syncthreads();

        const __half* S   = (const __half*)(dsm + (kb & 1) * MH_STG_BYTES);
        const __half* AsH = S;
        const __half* AsL = S + MH_ARR;
        const __half* BsH = S + 2 * MH_ARR;
        const __half* BsL = S + 3 * MH_ARR;

#pragma unroll
        for (int kk = 0; kk < 2; kk++) {
            const int ko = kk * 16 + 2 * tig;
            uint32_t ah[4][4], al[4][4];
#pragma unroll
            for (int mt = 0; mt < 4; mt++) {
                const int rr = (wm + 16 * mt + tg) * MH_ROW + ko;
                ah[mt][0] = *(const uint32_t*)(AsH + rr);
                ah[mt][1] = *(const uint32_t*)(AsH + rr + 8 * MH_ROW);
                ah[mt][2] = *(const uint32_t*)(AsH + rr + 8);
                ah[mt][3] = *(const uint32_t*)(AsH + rr + 8 * MH_ROW + 8);
                if (TERMS == 3) {
                    al[mt][0] = *(const uint32_t*)(AsL + rr);
                    al[mt][1] = *(const uint32_t*)(AsL + rr + 8 * MH_ROW);
                    al[mt][2] = *(const uint32_t*)(AsL + rr + 8);
                    al[mt][3] = *(const uint32_t*)(AsL + rr + 8 * MH_ROW + 8);
                }
            }
#pragma unroll
            for (int nt = 0; nt < 8; nt++) {
                const int rb = (wn + 8 * nt + tg) * MH_ROW + ko;
                const uint32_t bh0 = *(const uint32_t*)(BsH + rb);
                const uint32_t bh1 = *(const uint32_t*)(BsH + rb + 8);
                uint32_t bl0 = 0, bl1 = 0;
                if (TERMS >= 2) {
                    bl0 = *(const uint32_t*)(BsL + rb);
                    bl1 = *(const uint32_t*)(BsL + rb + 8);
                }
#pragma unroll
                for (int mt = 0; mt < 4; mt++) {
                    mma16(acc[mt][nt], ah[mt], bh0, bh1);            // Ah*Bh
                    if (TERMS >= 2) mma16(acc[mt][nt], ah[mt], bl0, bl1);  // Ah*Bl
                    if (TERMS == 3) mma16(acc[mt][nt], al[mt], bh0, bh1);  // Al*Bh
                }
            }
        }
        __syncthreads();
    }

    // ---------------- epilogue ----------------
    float s = 1.f;
    if (SCALE) s = g_scale[zb];
    __half* tsH = (__half*)dsm;
    __half* tsL = (__half*)(dsm + 34816);

#pragma unroll
    for (int mt = 0; mt < 4; mt++) {
        const int r = wm + 16 * mt + tg;
#pragma unroll
        for (int nt = 0; nt < 8; nt++) {
            const int c = wn + 8 * nt + 2 * tig;
            float v0 = acc[mt][nt][0], v1 = acc[mt][nt][1];
            float v2 = acc[mt][nt][2], v3 = acc[mt][nt][3];
            if (SCALE) { v0 *= s; v1 *= s; v2 *= s; v3 *= s; }
            if (ZDIAG) {
                const int gr = m0 + r, gc = n0 + c;
                v0 = (gr == gc)         ? 2.f - v0 : -v0;
                v1 = (gr == gc + 1)     ? 2.f - v1 : -v1;
                v2 = (gr + 8 == gc)     ? 2.f - v2 : -v2;
                v3 = (gr + 8 == gc + 1) ? 2.f - v3 : -v3;
            }
            if (OF32) {
                float b0 = 0.f, b1 = 0.f;
                if (BIAS) { b0 = bias[n0 + c]; b1 = bias[n0 + c + 1]; }
                float* cf = Cf + zb * cB;
                *(float2*)&cf[(long)(m0 + r) * ldc + n0 + c] = make_float2(v0 + b0, v1 + b1);
                *(float2*)&cf[(long)(m0 + r + 8) * ldc + n0 + c] = make_float2(v2 + b0, v3 + b1);
            }
            if (OH || OT) {
                __half h0, h1, h2, h3, l0, l1, l2, l3;
                if (LO) {
                    h_split(v0, h0, l0); h_split(v1, h1, l1);
                    h_split(v2, h2, l2); h_split(v3, h3, l3);
                } else {
                    h0 = __float2half_rn(v0); h1 = __float2half_rn(v1);
                    h2 = __float2half_rn(v2); h3 = __float2half_rn(v3);
                }
                if (OH) {
                    __half* ch = Ch + zb * cB;
                    *(__half2*)&ch[(long)(m0 + r) * ldc + n0 + c]     = __halves2half2(h0, h1);
                    *(__half2*)&ch[(long)(m0 + r + 8) * ldc + n0 + c] = __halves2half2(h2, h3);
                    if (LO) {
                        __half* cl = Cl + zb * cB;
                        *(__half2*)&cl[(long)(m0 + r) * ldc + n0 + c]     = __halves2half2(l0, l1);
                        *(__half2*)&cl[(long)(m0 + r + 8) * ldc + n0 + c] = __halves2half2(l2, l3);
                    }
                }
                if (OT) {
                    tsH[c * 136 + r]           = h0;
                    tsH[(c + 1) * 136 + r]     = h1;
                    tsH[c * 136 + r + 8]       = h2;
                    tsH[(c + 1) * 136 + r + 8] = h3;
                    if (LO) {
                        tsL[c * 136 + r]           = l0;
                        tsL[(c + 1) * 136 + r]     = l1;
                        tsL[c * 136 + r + 8]       = l2;
                        tsL[(c + 1) * 136 + r + 8] = l3;
                    }
                }
            }
        }
    }
    if (OT) {
        __syncthreads();
        const uint4* srcH = (const uint4*)(tsH + t * 136);
        uint4* dH = (uint4*)(CtH + zb * cB + (long)(n0 + t) * ldc + m0);
#pragma unroll
        for (int j = 0; j < 16; j++) dH[j] = srcH[j];
        if (LO) {
            const uint4* srcL = (const uint4*)(tsL + t * 136);
            uint4* dL = (uint4*)(CtL + zb * cB + (long)(n0 + t) * ldc + m0);
#pragma unroll
            for (int j = 0; j < 16; j++) dL[j] = srcL[j];
        }
    }
}

// ---------------- small-N SGEMM: 64(M)x64(N) tile, BK=16, 256 threads, 4x4 ------
// TRIMK: 1 -> (TRANSA path, A=W lower-tri) contributions need k >= m0.
// OSPLIT: 1 -> write fp16 hi/lo split (ChG/ClG) instead of fp32.
template<int TRANSA, int ANORM, int TRIMK, int OSPLIT>
__global__ __launch_bounds__(256) void sgemm_n64(
    const float* __restrict__ Ag, const float* __restrict__ Bg, float* __restrict__ Cg,
    __half* __restrict__ ChG, __half* __restrict__ ClG,
    int K, int lda, int ldb, int ldc,
    long aO, long aI, long bO, long bI, long cO, long cI)
{
    const int z = blockIdx.z;
    const float* A = Ag + (long)(z >> 3) * aO + (long)(z & 7) * aI;
    const float* B = Bg + (long)(z >> 3) * bO + (long)(z & 7) * bI;
    const long coff = (long)(z >> 3) * cO + (long)(z & 7) * cI;
    const float* mu   = g_mu   + (z & 7) * SC;
    const float* rstd = g_rstd + (z & 7) * SC;

    const int m0 = blockIdx.x * 64;
    const int t  = threadIdx.x;
    const int ty = t >> 4, tx = t & 15;

    __shared__ float As[16][64];
    __shared__ float Bs[16][64];

    float acc[4][4];
#pragma unroll
    for (int i = 0; i < 4; i++)
#pragma unroll
        for (int j = 0; j < 4; j++) acc[i][j] = 0.f;

    const int kstart = TRIMK ? m0 : 0;
    for (int k0 = kstart; k0 < K; k0 += 16) {
        if (TRANSA) {
            const int kr = t >> 4, mc = (t & 15) * 4;
            *(float4*)&As[kr][mc] = *(const float4*)&A[(long)(k0 + kr) * lda + m0 + mc];
        } else {
            const int ar = t >> 2, ac = (t & 3) * 4;
            float4 v = *(const float4*)&A[(long)(m0 + ar) * lda + k0 + ac];
            if (ANORM) {
                v.x = (v.x - mu[k0 + ac + 0]) * rstd[k0 + ac + 0];
                v.y = (v.y - mu[k0 + ac + 1]) * rstd[k0 + ac + 1];
                v.z = (v.z - mu[k0 + ac + 2]) * rstd[k0 + ac + 2];
                v.w = (v.w - mu[k0 + ac + 3]) * rstd[k0 + ac + 3];
            }
            As[ac + 0][ar] = v.x;
            As[ac + 1][ar] = v.y;
            As[ac + 2][ar] = v.z;
            As[ac + 3][ar] = v.w;
        }
        {
            const int kr = t >> 4, nc = (t & 15) * 4;
            *(float4*)&Bs[kr][nc] = *(const float4*)&B[(long)(k0 + kr) * ldb + nc];
        }
        __syncthreads();
#pragma unroll
        for (int kk = 0; kk < 16; kk++) {
            float a[4], b[4];
            *(float4*)a = *(const float4*)&As[kk][ty * 4];
            *(float4*)b = *(const float4*)&Bs[kk][tx * 4];
#pragma unroll
            for (int i = 0; i < 4; i++)
#pragma unroll
                for (int j = 0; j < 4; j++)
                    acc[i][j] = fmaf(a[i], b[j], acc[i][j]);
        }
        __syncthreads();
    }

#pragma unroll
    for (int i = 0; i < 4; i++) {
        const long rowo = (long)(m0 + ty * 4 + i) * ldc + tx * 4;
        if (OSPLIT) {
            __half* ch = ChG + coff;
            __half* cl = ClG + coff;
#pragma unroll
            for (int j = 0; j < 4; j += 2) {
                __half h0, h1, l0, l1;
                h_split(acc[i][j],     h0, l0);
                h_split(acc[i][j + 1], h1, l1);
                *(__half2*)&ch[rowo + j] = __halves2half2(h0, h1);
                *(__half2*)&cl[rowo + j] = __halves2half2(l0, l1);
            }
        } else {
            float* C = Cg + coff;
#pragma unroll
            for (int j = 0; j < 4; j++)
                C[rowo + j] = acc[i][j];
        }
    }
}

// ---------------- Laplacian: W = tril(exp(-L1/4)); writes W, Wh/l, Wth/l --------
__global__ __launch_bounds__(1024) void laplacian_kernel()
{
    const int z = blockIdx.z;
    const int b = z >> 3, h = z & 7;
    const int i0 = blockIdx.y * 32, j0 = blockIdx.x * 32;
    const int tx = threadIdx.x, ty = threadIdx.y;
    const int tid = ty * 32 + tx;

    float*  Wp  = g_W   + (long)z * SC * SC;
    __half* Whp = g_Wh  + (long)z * SC * SC;
    __half* Wlp = g_Wl  + (long)z * SC * SC;
    __half* Wth = g_Wth + (long)z * SC * SC;
    __half* Wtl = g_Wtl + (long)z * SC * SC;

    if (j0 > i0 + 31) {   // fully masked tile (uniform per block)
        const long o  = (long)(i0 + ty) * SC + j0 + tx;
        const long ot = (long)(j0 + ty) * SC + i0 + tx;
        Wp[o] = 0.f;
        Whp[o] = __float2half(0.f); Wlp[o] = __float2half(0.f);
        Wth[ot] = __float2half(0.f); Wtl[ot] = __float2half(0.f);
        return;
    }

    const float* qp = g_qkv + (long)b * SC * 3 * DIMC + h * HDC;
    const float* kp = g_qkv + (long)b * SC * 3 * DIMC + DIMC + h * HDC;

    __shared__ float qs[32][65];
    __shared__ float ks[32][65];
    __shared__ float tr[32][33];

    for (int idx = tid; idx < 2048; idx += 1024) {
        const int r = idx >> 6, d = idx & 63;
        qs[r][d] = qp[(long)(i0 + r) * (3 * DIMC) + d];
        ks[r][d] = kp[(long)(j0 + r) * (3 * DIMC) + d];
    }
    __syncthreads();

    const int i = i0 + ty, j = j0 + tx;
    float out = 0.f;
    if (j <= i) {
        float s = 0.f;
#pragma unroll
        for (int d = 0; d < 64; d++)
            s += fabsf(qs[ty][d] - ks[tx][d]);
        out = expf(-0.25f * s);
    }
    const long o = (long)i * SC + j;
    Wp[o] = out;
    __half hh, hl;
    h_split(out, hh, hl);
    Whp[o] = hh; Wlp[o] = hl;

    tr[ty][tx] = out;
    __syncthreads();
    const float tv = tr[tx][ty];              // = W(i0+tx, j0+ty)
    h_split(tv, hh, hl);
    const long ot = (long)(j0 + ty) * SC + i0 + tx;
    Wth[ot] = hh; Wtl[ot] = hl;
}

// ---------------- NS init scale, phase 1: per-slice partials --------------------
__global__ __launch_bounds__(512) void ns_scale_p1()
{
    const int sl = blockIdx.x, z = blockIdx.y;
    const float* W = g_W + (long)z * SC * SC;
    const int t = threadIdx.x, wid = t >> 5, lid = t & 31;
    const int r0 = sl * 64;

    float cs = 0.f;
    for (int i = r0; i < r0 + 64; i++) cs += W[(long)i * SC + t];
    g_cs_part[sl][z][t] = cs;

    float rmax = 0.f;
    for (int r = r0 + wid * 4; r < r0 + wid * 4 + 4; r++) {
        const float4* row = (const float4*)&W[(long)r * SC];
        float s = 0.f;
#pragma unroll
        for (int p = 0; p < 4; p++) {
            const float4 v = row[lid + p * 32];
            s += v.x + v.y + v.z + v.w;
        }
#pragma unroll
        for (int o = 16; o > 0; o >>= 1) s += __shfl_xor_sync(0xFFFFFFFFu, s, o);
        rmax = fmaxf(rmax, s);
    }
    __shared__ float red[16];
    if (lid == 0) red[wid] = rmax;
    __syncthreads();
    if (t == 0) {
        float m = red[0];
#pragma unroll
        for (int i = 1; i < 16; i++) m = fmaxf(m, red[i]);
        g_rm_part[sl][z] = m;
    }
}

// ---------------- NS init scale, phase 2: combine -------------------------------
__global__ __launch_bounds__(512) void ns_scale_p2()
{
    const int z = blockIdx.x, t = threadIdx.x;
    float cs = 0.f;
#pragma unroll
    for (int sl = 0; sl < 8; sl++) cs += g_cs_part[sl][z][t];

    __shared__ float red[512];
    red[t] = cs; __syncthreads();
    for (int s = 256; s > 0; s >>= 1) {
        if (t < s) red[t] = fmaxf(red[t], red[t + s]);
        __syncthreads();
    }
    if (t == 0) {
        float rmax = g_rm_part[0][z];
#pragma unroll
        for (int sl = 1; sl < 8; sl++) rmax = fmaxf(rmax, g_rm_part[sl][z]);
        g_scale[z] = 1.f / (red[0] * rmax);
    }
}

// ---------------- whitening stats per (h, key column j) -------------------------
__global__ __launch_bounds__(256) void stats_kernel()
{
    const int jc = blockIdx.x, h = blockIdx.y;
    const int t = threadIdx.x;
    const int j = jc * 64 + (t & 63);
    const int slice = t >> 6;

    float s = 0.f, s2 = 0.f;
    for (int b = 0; b < BC; b++) {
        const float* Wp = g_W + (long)(b * HC + h) * SC * SC + j;
        for (int i = slice * 128; i < slice * 128 + 128; i++) {
            const float v = Wp[(long)i * SC];
            s += v; s2 += v * v;
        }
    }
    __shared__ float S1[256], S2[256];
    S1[t] = s; S2[t] = s2;
    __syncthreads();
    if (slice == 0) {
        s  = S1[t] + S1[t + 64] + S1[t + 128] + S1[t + 192];
        s2 = S2[t] + S2[t + 64] + S2[t + 128] + S2[t + 192];
        const float n = (float)(BC * SC);
        const float m = s / n;
        const float var = (s2 - n * m * m) / (n - 1.f);
        g_mu[h * SC + j]   = m;
        g_rstd[h * SC + j] = rsqrtf(var + EPSC);
    }
}

// ---------------- launch --------------------------------------------------------
extern "C" void kernel_launch(void* const* d_in, const int* in_sizes, int n_in,
                              void* d_out, int out_size)
{
    (void)in_sizes; (void)n_in; (void)out_size;
    const float* x      = (const float*)d_in[0];
    const float* qkv_w  = (const float*)d_in[1];
    const float* qkv_b  = (const float*)d_in[2];
    const float* proj_w = (const float*)d_in[3];
    const float* proj_b = (const float*)d_in[4];
    float* out = (float*)d_out;

    static float *pQKV = nullptr, *pW, *pXf, *pCTX, *pCTX2;
    static __half *pWh, *pWl, *pWth, *pWtl, *pZth, *pZtl;
    static __half *pXh[2], *pXl[2], *pXth[2], *pXtl[2];
    static __half *pxh, *pxl, *pwqh, *pwql, *ppwh, *ppwl, *pgah, *pgal;
    if (!pQKV) {
        cudaGetSymbolAddress((void**)&pQKV, g_qkv);
        cudaGetSymbolAddress((void**)&pW,   g_W);
        cudaGetSymbolAddress((void**)&pWh,  g_Wh);
        cudaGetSymbolAddress((void**)&pWl,  g_Wl);
        cudaGetSymbolAddress((void**)&pWth, g_Wth);
        cudaGetSymbolAddress((void**)&pWtl, g_Wtl);
        cudaGetSymbolAddress((void**)&pZth, g_Zth);
        cudaGetSymbolAddress((void**)&pZtl, g_Ztl);
        cudaGetSymbolAddress((void**)&pXh[0],  g_Xh0);
        cudaGetSymbolAddress((void**)&pXl[0],  g_Xl0);
        cudaGetSymbolAddress((void**)&pXh[1],  g_Xh1);
        cudaGetSymbolAddress((void**)&pXl[1],  g_Xl1);
        cudaGetSymbolAddress((void**)&pXth[0], g_Xth0);
        cudaGetSymbolAddress((void**)&pXtl[0], g_Xtl0);
        cudaGetSymbolAddress((void**)&pXth[1], g_Xth1);
        cudaGetSymbolAddress((void**)&pXtl[1], g_Xtl1);
        cudaGetSymbolAddress((void**)&pXf,  g_Xf);
        cudaGetSymbolAddress((void**)&pxh,  g_xh);
        cudaGetSymbolAddress((void**)&pxl,  g_xl);
        cudaGetSymbolAddress((void**)&pwqh, g_wqh);
        cudaGetSymbolAddress((void**)&pwql, g_wql);
        cudaGetSymbolAddress((void**)&ppwh, g_pwh);
        cudaGetSymbolAddress((void**)&ppwl, g_pwl);
        cudaGetSymbolAddress((void**)&pgah, g_gah);
        cudaGetSymbolAddress((void**)&pgal, g_gal);
        cudaGetSymbolAddress((void**)&pCTX, g_ctx);
        cudaGetSymbolAddress((void**)&pCTX2,g_ctx2);
        cudaFuncSetAttribute(mma_h<3,0,0,0,0,1,1,0,0,0,0>, cudaFuncAttributeMaxDynamicSharedMemorySize, MH_SMEM);
        cudaFuncSetAttribute(mma_h<1,1,1,1,1,0,0,1,0,0,1>, cudaFuncAttributeMaxDynamicSharedMemorySize, MH_SMEM);
        cudaFuncSetAttribute(mma_h<1,2,0,0,1,0,0,1,1,0,0>, cudaFuncAttributeMaxDynamicSharedMemorySize, MH_SMEM);
        cudaFuncSetAttribute(mma_h<1,0,1,1,0,0,0,1,0,0,1>, cudaFuncAttributeMaxDynamicSharedMemorySize, MH_SMEM);
        cudaFuncSetAttribute(mma_h<1,0,0,0,0,0,0,1,1,0,0>, cudaFuncAttributeMaxDynamicSharedMemorySize, MH_SMEM);
        cudaFuncSetAttribute(mma_h<1,0,0,0,0,0,0,1,1,1,0>, cudaFuncAttributeMaxDynamicSharedMemorySize, MH_SMEM);
        cudaFuncSetAttribute(mma_h<3,0,1,1,0,0,0,1,0,1,1>, cudaFuncAttributeMaxDynamicSharedMemorySize, MH_SMEM);
        cudaFuncSetAttribute(mma_h<3,0,0,0,0,0,1,0,0,0,0>, cudaFuncAttributeMaxDynamicSharedMemorySize, MH_SMEM);
    }

    const long MS = (long)SC * SC;
    const long CS = (long)SC * HDC;

    // 0) split static operands
    split_f16<<<512, 256>>>(x, pxh, pxl);
    split_f16<<<768, 256>>>(qkv_w, pwqh, pwql);
    split_f16<<<256, 256>>>(proj_w, ppwh, ppwl);

    // 1) qkv = x @ qkv_w^T + qkv_b   (NT, 3-term, fp32 out)
    mma_h<3,0,0,0,0,1,1,0,0,0,0><<<dim3(12, 8, 1), 128, MH_SMEM>>>(
        pxh, pxl, pwqh, pwql, nullptr, nullptr, nullptr, nullptr,
        pQKV, qkv_b, 512, 512, 1536, 0, 0, 0);

    // 2) W = tril(exp(-L1/4)) + splits of W and W^T
    laplacian_kernel<<<dim3(16, 16, 16), dim3(32, 32)>>>();

    // 3) scale = 1/(n1*ninf), parallel two-phase
    ns_scale_p1<<<dim3(8, 16), 512>>>();
    ns_scale_p2<<<16, 512>>>();

    // 5) Newton-Schulz (dual-orientation, all NT):
    //    Zt = 2I - Xt@W^T ; X' = X@Z (B = Zt) ; Xt' via transposed epilogue.
    //    Precision: it0-3 1-term; it4 3-term. LO only where a 3-term consumer
    //    reads the result (it3 X', it4 Zt). SWAP=1 puts trim-cost axis on y.
    mma_h<1,1,1,1,1,0,0,1,0,0,1><<<dim3(4, 4, 16), 128, MH_SMEM>>>(   // Zt0 = 2I - s*(W W^T)
        pWh, pWl, pWh, pWl, pZth, pZtl, nullptr, nullptr, nullptr, nullptr,
        512, 512, 512, MS, MS, MS);
    mma_h<1,2,0,0,1,0,0,1,1,0,0><<<dim3(4, 4, 16), 128, MH_SMEM>>>(   // X1 = s*(Wt Z0)
        pWth, pWtl, pZth, pZtl, pXh[0], pXl[0], pXth[0], pXtl[0], nullptr, nullptr,
        512, 512, 512, MS, MS, MS);
    int cur = 0;
    for (int it = 1; it < 4; it++) {
        mma_h<1,0,1,1,0,0,0,1,0,0,1><<<dim3(4, 4, 16), 128, MH_SMEM>>>(   // Zt = 2I - Xt W^T
            pXth[cur], pXtl[cur], pWh, pWl, pZth, pZtl, nullptr, nullptr, nullptr, nullptr,
            512, 512, 512, MS, MS, MS);
        if (it < 3) {
            mma_h<1,0,0,0,0,0,0,1,1,0,0><<<dim3(4, 4, 16), 128, MH_SMEM>>>(   // X' = X Z
                pXh[cur], pXl[cur], pZth, pZtl,
                pXh[1 - cur], pXl[1 - cur], pXth[1 - cur], pXtl[1 - cur], nullptr, nullptr,
                512, 512, 512, MS, MS, MS);
        } else {
            mma_h<1,0,0,0,0,0,0,1,1,1,0><<<dim3(4, 4, 16), 128, MH_SMEM>>>(   // X4 (lo kept)
                pXh[cur], pXl[cur], pZth, pZtl,
                pXh[1 - cur], pXl[1 - cur], pXth[1 - cur], pXtl[1 - cur], nullptr, nullptr,
                512, 512, 512, MS, MS, MS);
        }
        cur = 1 - cur;
    }
    // it4: full accuracy -> fp32 X5
    mma_h<3,0,1,1,0,0,0,1,0,1,1><<<dim3(4, 4, 16), 128, MH_SMEM>>>(
        pXth[cur], pXtl[cur], pWh, pWl, pZth, pZtl, nullptr, nullptr, nullptr, nullptr,
        512, 512, 512, MS, MS, MS);
    mma_h<3,0,0,0,0,0,1,0,0,0,0><<<dim3(4, 4, 16), 128, MH_SMEM>>>(
        pXh[cur], pXl[cur], pZth, pZtl, nullptr, nullptr, nullptr, nullptr,
        pXf, nullptr, 512, 512, 512, MS, MS, MS);

    // 6) whitening stats
    stats_kernel<<<dim3(8, 8), 256>>>();

    // 7) ctx = W^T @ v   (A=W lower-tri via TRANSA access: k >= m0 only)
    sgemm_n64<1, 0, 1, 0><<<dim3(8, 1, 16), 256>>>(
        pW, pQKV + 2 * DIMC, pCTX, nullptr, nullptr, 512, 512, 3 * DIMC, HDC,
        8 * MS, MS, (long)SC * 3 * DIMC, HDC, 8 * CS, CS);

    // 8) ctx2 = W_inv @ ctx  (W_inv = X5, dense)
    sgemm_n64<0, 0, 0, 0><<<dim3(8, 1, 16), 256>>>(
        pXf, pCTX, pCTX2, nullptr, nullptr, 512, 512, HDC, HDC,
        8 * MS, MS, 8 * CS, CS, 8 * CS, CS);

    // 9) ga = W_norm @ ctx2 -> [b, s, h*64+d], fused fp16 split (no fp32 ga)
    sgemm_n64<0, 1, 0, 1><<<dim3(8, 1, 16), 256>>>(
        pW, pCTX2, nullptr, pgah, pgal, 512, 512, HDC, 512,
        8 * MS, MS, 8 * CS, CS, MS, HDC);

    // 10) out = ga @ proj_w^T + proj_b   (NT, 3-term, fp32 out)
    mma_h<3,0,0,0,0,1,1,0,0,0,0><<<dim3(4, 8, 1), 128, MH_SMEM>>>(
        pgah, pgal, ppwh, ppwl, nullptr, nullptr, nullptr, nullptr,
        out, proj_b, 512, 512, 512, 0, 0, 0);
}

// round 13
// speedup vs baseline: 1.5260x; 1.5260x over previous
#include <cuda_runtime.h>
#include <cuda_fp16.h>
#include <math.h>
#include <stdint.h>

#define DIMC 512
#define HC 8
#define HDC 64
#define BC 2
#define SC 512
#define BHC 16
#define EPSC 1e-5f

// ---------------- scratch (device globals; no allocation allowed) ----------------
__device__ float  g_qkv[BC * SC * 3 * DIMC];     // [1024][1536] fp32
__device__ float  g_W  [BHC * SC * SC];          // fp32 W
__device__ __half g_Wh [BHC * SC * SC];          // fp16 hi/lo of W
__device__ __half g_Wl [BHC * SC * SC];
__device__ __half g_Wth[BHC * SC * SC];          // fp16 hi/lo of W^T
__device__ __half g_Wtl[BHC * SC * SC];
__device__ __half g_Zth[BHC * SC * SC];          // fp16 hi/lo of Z^T
__device__ __half g_Ztl[BHC * SC * SC];
__device__ __half g_Xh0[BHC * SC * SC];          // X double buffer (hi/lo)
__device__ __half g_Xl0[BHC * SC * SC];
__device__ __half g_Xh1[BHC * SC * SC];
__device__ __half g_Xl1[BHC * SC * SC];
__device__ __half g_Xth0[BHC * SC * SC];         // X^T double buffer (hi/lo)
__device__ __half g_Xtl0[BHC * SC * SC];
__device__ __half g_Xth1[BHC * SC * SC];
__device__ __half g_Xtl1[BHC * SC * SC];
__device__ float  g_Xf [BHC * SC * SC];          // fp32 X5 = W_inv
__device__ __half g_xh [BC * SC * DIMC];         // splits of x
__device__ __half g_xl [BC * SC * DIMC];
__device__ __half g_wqh[3 * DIMC * DIMC];        // splits of qkv_w
__device__ __half g_wql[3 * DIMC * DIMC];
__device__ __half g_pwh[DIMC * DIMC];            // splits of proj_w
__device__ __half g_pwl[DIMC * DIMC];
__device__ __half g_gah[BC * SC * DIMC];         // splits of ga
__device__ __half g_gal[BC * SC * DIMC];
__device__ float  g_ctx [BHC * SC * HDC];
__device__ float  g_ctx2[BHC * SC * HDC];
__device__ float  g_scale[BHC];
__device__ float  g_mu  [HC * SC];
__device__ float  g_rstd[HC * SC];
__device__ float  g_cs_part[8][BHC][SC];         // ns_scale partials
__device__ float  g_rm_part[8][BHC];

// ============================ helpers ============================================
__device__ __forceinline__ uint32_t smem_to_u32(const void* p) {
    uint32_t a;
    asm("{ .reg .u64 t; cvta.to.shared.u64 t, %1; cvt.u32.u64 %0, t; }" : "=r"(a) : "l"(p));
    return a;
}
__device__ __forceinline__ void cpa16h(uint32_t dst, const __half* src) {
    asm volatile("cp.async.cg.shared.global [%0], [%1], 16;" :: "r"(dst), "l"(src));
}
__device__ __forceinline__ void cpa_commit() {
    asm volatile("cp.async.commit_group;" ::: "memory");
}
__device__ __forceinline__ void mma16(float d[4], const uint32_t a[4],
                                      uint32_t b0, uint32_t b1) {
    asm volatile(
        "mma.sync.aligned.m16n8k16.row.col.f32.f16.f16.f32 "
        "{%0,%1,%2,%3}, {%4,%5,%6,%7}, {%8,%9}, {%0,%1,%2,%3};"
        : "+f"(d[0]), "+f"(d[1]), "+f"(d[2]), "+f"(d[3])
        : "r"(a[0]), "r"(a[1]), "r"(a[2]), "r"(a[3]), "r"(b0), "r"(b1));
}
__device__ __forceinline__ void h_split(float v, __half& h, __half& l) {
    h = __float2half_rn(v);
    l = __float2half_rn(v - __half2float(h));
}

// ---------------- elementwise fp16 split ----------------------------------------
__global__ __launch_bounds__(256) void split_f16(
    const float* __restrict__ in, __half* __restrict__ oh, __half* __restrict__ ol)
{
    const int i = blockIdx.x * 256 + threadIdx.x;
    const float4 v = ((const float4*)in)[i];
    __half h0, h1, h2, h3, l0, l1, l2, l3;
    h_split(v.x, h0, l0); h_split(v.y, h1, l1);
    h_split(v.z, h2, l2); h_split(v.w, h3, l3);
    ((__half2*)oh)[2 * i]     = __halves2half2(h0, h1);
    ((__half2*)oh)[2 * i + 1] = __halves2half2(h2, h3);
    ((__half2*)ol)[2 * i]     = __halves2half2(l0, l1);
    ((__half2*)ol)[2 * i + 1] = __halves2half2(l2, l3);
}

// ================= fp16 multi-term GEMM (mma.sync m16n8k16), all NT ==============
// C[m][n] = sum_k A[m][k] * B[n][k].
// TERMS: 3 = AhBh+AhBl+AlBh, 2 = AhBh+AhBl, 1 = AhBh.
// TRIMA: 1 -> A lower-tri (k<=m): kb_end=(m0>>5)+4; 2 -> A upper-tri: kb_start=m0>>5.
// TRIMB: 1 -> B lower-tri (k<=n): kb_end=(n0>>5)+4.
// LO: write low-half output arrays (only needed when a 3-term GEMM consumes C).
#define MH_ROW 40                    // halves per smem row (32 + pad 8)
#define MH_ARR 5120                  // 128 * 40 halves per array
#define MH_STG_BYTES 40960           // 4 arrays * 10240 B
#define MH_SMEM 81920                // 2 stages

template<int TERMS>
__device__ __forceinline__ void mh_issue(
    const __half* __restrict__ Ah, const __half* __restrict__ Al,
    const __half* __restrict__ Bh, const __half* __restrict__ Bl,
    int lda, int ldb, int m0, int n0, int t, int k0, uint32_t base)
{
#pragma unroll
    for (int i = 0; i < 4; i++) {
        const int idx = t + i * 128;
        const int r = idx >> 2, c8 = (idx & 3) * 8;
        const uint32_t so = (uint32_t)(r * MH_ROW + c8) * 2u;
        cpa16h(base + so,          Ah + (long)(m0 + r) * lda + k0 + c8);
        if (TERMS == 3)
            cpa16h(base + 10240u + so, Al + (long)(m0 + r) * lda + k0 + c8);
        cpa16h(base + 20480u + so, Bh + (long)(n0 + r) * ldb + k0 + c8);
        if (TERMS >= 2)
            cpa16h(base + 30720u + so, Bl + (long)(n0 + r) * ldb + k0 + c8);
    }
    cpa_commit();
}

template<int TERMS, int TRIMA, int TRIMB, int ZDIAG, int SCALE, int BIAS,
         int OF32, int OH, int OT, int LO>
__global__ __launch_bounds__(128, 2) void mma_h(
    const __half* __restrict__ Ah, const __half* __restrict__ Al,
    const __half* __restrict__ Bh, const __half* __restrict__ Bl,
    __half* __restrict__ Ch, __half* __restrict__ Cl,
    __half* __restrict__ CtH, __half* __restrict__ CtL,
    float* __restrict__ Cf, const float* __restrict__ bias,
    int lda, int ldb, int ldc, long aB, long bB, long cB)
{
    extern __shared__ char dsm[];
    const uint32_t sb = smem_to_u32(dsm);
    const int t = threadIdx.x;
    const int w = t >> 5, lane = t & 31;
    const int tg = lane >> 2, tig = lane & 3;
    const int wm = (w & 1) * 64, wn = (w >> 1) * 64;
    const int m0 = blockIdx.y * 128, n0 = blockIdx.x * 128;
    const long zb = blockIdx.z;
    const __half* pAh = Ah + zb * aB;
    const __half* pAl = Al + zb * aB;
    const __half* pBh = Bh + zb * bB;
    const __half* pBl = Bl + zb * bB;

    int kbs = 0, kbe = 16;
    if (TRIMA == 1) { const int e = (m0 >> 5) + 4; if (e < kbe) kbe = e; }
    if (TRIMA == 2) kbs = m0 >> 5;
    if (TRIMB == 1) { const int e = (n0 >> 5) + 4; if (e < kbe) kbe = e; }

    float acc[4][8][4];
#pragma unroll
    for (int i = 0; i < 4; i++)
#pragma unroll
        for (int j = 0; j < 8; j++)
#pragma unroll
            for (int p = 0; p < 4; p++) acc[i][j][p] = 0.f;

    mh_issue<TERMS>(pAh, pAl, pBh, pBl, lda, ldb, m0, n0, t, kbs * 32,
                    sb + (kbs & 1) * MH_STG_BYTES);

    for (int kb = kbs; kb < kbe; kb++) {
        if (kb + 1 < kbe) {
            mh_issue<TERMS>(pAh, pAl, pBh, pBl, lda, ldb, m0, n0, t,
                            (kb + 1) * 32, sb + ((kb + 1) & 1) * MH_STG_BYTES);
            asm volatile("cp.async.wait_group 1;" ::: "memory");
        } else {
            asm volatile("cp.async.wait_group 0;" ::: "memory");
        }
        __syncthreads();

        const __half* S   = (const __half*)(dsm + (kb & 1) * MH_STG_BYTES);
        const __half* AsH = S;
        const __half* AsL = S + MH_ARR;
        const __half* BsH = S + 2 * MH_ARR;
        const __half* BsL = S + 3 * MH_ARR;

#pragma unroll
        for (int kk = 0; kk < 2; kk++) {
            const int ko = kk * 16 + 2 * tig;
            uint32_t ah[4][4], al[4][4];
#pragma unroll
            for (int mt = 0; mt < 4; mt++) {
                const int rr = (wm + 16 * mt + tg) * MH_ROW + ko;
                ah[mt][0] = *(const uint32_t*)(AsH + rr);
                ah[mt][1] = *(const uint32_t*)(AsH + rr + 8 * MH_ROW);
                ah[mt][2] = *(const uint32_t*)(AsH + rr + 8);
                ah[mt][3] = *(const uint32_t*)(AsH + rr + 8 * MH_ROW + 8);
                if (TERMS == 3) {
                    al[mt][0] = *(const uint32_t*)(AsL + rr);
                    al[mt][1] = *(const uint32_t*)(AsL + rr + 8 * MH_ROW);
                    al[mt][2] = *(const uint32_t*)(AsL + rr + 8);
                    al[mt][3] = *(const uint32_t*)(AsL + rr + 8 * MH_ROW + 8);
                }
            }
#pragma unroll
            for (int nt = 0; nt < 8; nt++) {
                const int rb = (wn + 8 * nt + tg) * MH_ROW + ko;
                const uint32_t bh0 = *(const uint32_t*)(BsH + rb);
                const uint32_t bh1 = *(const uint32_t*)(BsH + rb + 8);
                uint32_t bl0 = 0, bl1 = 0;
                if (TERMS >= 2) {
                    bl0 = *(const uint32_t*)(BsL + rb);
                    bl1 = *(const uint32_t*)(BsL + rb + 8);
                }
#pragma unroll
                for (int mt = 0; mt < 4; mt++) {
                    mma16(acc[mt][nt], ah[mt], bh0, bh1);            // Ah*Bh
                    if (TERMS >= 2) mma16(acc[mt][nt], ah[mt], bl0, bl1);  // Ah*Bl
                    if (TERMS == 3) mma16(acc[mt][nt], al[mt], bh0, bh1);  // Al*Bh
                }
            }
        }
        __syncthreads();
    }

    // ---------------- epilogue ----------------
    float s = 1.f;
    if (SCALE) s = g_scale[zb];
    __half* tsH = (__half*)dsm;
    __half* tsL = (__half*)(dsm + 34816);

#pragma unroll
    for (int mt = 0; mt < 4; mt++) {
        const int r = wm + 16 * mt + tg;
#pragma unroll
        for (int nt = 0; nt < 8; nt++) {
            const int c = wn + 8 * nt + 2 * tig;
            float v0 = acc[mt][nt][0], v1 = acc[mt][nt][1];
            float v2 = acc[mt][nt][2], v3 = acc[mt][nt][3];
            if (SCALE) { v0 *= s; v1 *= s; v2 *= s; v3 *= s; }
            if (ZDIAG) {
                const int gr = m0 + r, gc = n0 + c;
                v0 = (gr == gc)         ? 2.f - v0 : -v0;
                v1 = (gr == gc + 1)     ? 2.f - v1 : -v1;
                v2 = (gr + 8 == gc)     ? 2.f - v2 : -v2;
                v3 = (gr + 8 == gc + 1) ? 2.f - v3 : -v3;
            }
            if (OF32) {
                float b0 = 0.f, b1 = 0.f;
                if (BIAS) { b0 = bias[n0 + c]; b1 = bias[n0 + c + 1]; }
                float* cf = Cf + zb * cB;
                *(float2*)&cf[(long)(m0 + r) * ldc + n0 + c] = make_float2(v0 + b0, v1 + b1);
                *(float2*)&cf[(long)(m0 + r + 8) * ldc + n0 + c] = make_float2(v2 + b0, v3 + b1);
            }
            if (OH || OT) {
                __half h0, h1, h2, h3, l0, l1, l2, l3;
                if (LO) {
                    h_split(v0, h0, l0); h_split(v1, h1, l1);
                    h_split(v2, h2, l2); h_split(v3, h3, l3);
                } else {
                    h0 = __float2half_rn(v0); h1 = __float2half_rn(v1);
                    h2 = __float2half_rn(v2); h3 = __float2half_rn(v3);
                }
                if (OH) {
                    __half* ch = Ch + zb * cB;
                    *(__half2*)&ch[(long)(m0 + r) * ldc + n0 + c]     = __halves2half2(h0, h1);
                    *(__half2*)&ch[(long)(m0 + r + 8) * ldc + n0 + c] = __halves2half2(h2, h3);
                    if (LO) {
                        __half* cl = Cl + zb * cB;
                        *(__half2*)&cl[(long)(m0 + r) * ldc + n0 + c]     = __halves2half2(l0, l1);
                        *(__half2*)&cl[(long)(m0 + r + 8) * ldc + n0 + c] = __halves2half2(l2, l3);
                    }
                }
                if (OT) {
                    tsH[c * 136 + r]           = h0;
                    tsH[(c + 1) * 136 + r]     = h1;
                    tsH[c * 136 + r + 8]       = h2;
                    tsH[(c + 1) * 136 + r + 8] = h3;
                    if (LO) {
                        tsL[c * 136 + r]           = l0;
                        tsL[(c + 1) * 136 + r]     = l1;
                        tsL[c * 136 + r + 8]       = l2;
                        tsL[(c + 1) * 136 + r + 8] = l3;
                    }
                }
            }
        }
    }
    if (OT) {
        __syncthreads();
        const uint4* srcH = (const uint4*)(tsH + t * 136);
        uint4* dH = (uint4*)(CtH + zb * cB + (long)(n0 + t) * ldc + m0);
#pragma unroll
        for (int j = 0; j < 16; j++) dH[j] = srcH[j];
        if (LO) {
            const uint4* srcL = (const uint4*)(tsL + t * 136);
            uint4* dL = (uint4*)(CtL + zb * cB + (long)(n0 + t) * ldc + m0);
#pragma unroll
            for (int j = 0; j < 16; j++) dL[j] = srcL[j];
        }
    }
}

// ---------------- small-N SGEMM: 64(M)x64(N) tile, BK=16, 256 threads, 4x4 ------
// TRIMK: 1 -> (TRANSA path, A=W lower-tri) contributions need k >= m0.
// OSPLIT: 1 -> write fp16 hi/lo split (ChG/ClG) instead of fp32.
template<int TRANSA, int ANORM, int TRIMK, int OSPLIT>
__global__ __launch_bounds__(256) void sgemm_n64(
    const float* __restrict__ Ag, const float* __restrict__ Bg, float* __restrict__ Cg,
    __half* __restrict__ ChG, __half* __restrict__ ClG,
    int K, int lda, int ldb, int ldc,
    long aO, long aI, long bO, long bI, long cO, long cI)
{
    const int z = blockIdx.z;
    const float* A = Ag + (long)(z >> 3) * aO + (long)(z & 7) * aI;
    const float* B = Bg + (long)(z >> 3) * bO + (long)(z & 7) * bI;
    const long coff = (long)(z >> 3) * cO + (long)(z & 7) * cI;
    const float* mu   = g_mu   + (z & 7) * SC;
    const float* rstd = g_rstd + (z & 7) * SC;

    const int m0 = blockIdx.x * 64;
    const int t  = threadIdx.x;
    const int ty = t >> 4, tx = t & 15;

    __shared__ float As[16][64];
    __shared__ float Bs[16][64];

    float acc[4][4];
#pragma unroll
    for (int i = 0; i < 4; i++)
#pragma unroll
        for (int j = 0; j < 4; j++) acc[i][j] = 0.f;

    const int kstart = TRIMK ? m0 : 0;
    for (int k0 = kstart; k0 < K; k0 += 16) {
        if (TRANSA) {
            const int kr = t >> 4, mc = (t & 15) * 4;
            *(float4*)&As[kr][mc] = *(const float4*)&A[(long)(k0 + kr) * lda + m0 + mc];
        } else {
            const int ar = t >> 2, ac = (t & 3) * 4;
            float4 v = *(const float4*)&A[(long)(m0 + ar) * lda + k0 + ac];
            if (ANORM) {
                v.x = (v.x - mu[k0 + ac + 0]) * rstd[k0 + ac + 0];
                v.y = (v.y - mu[k0 + ac + 1]) * rstd[k0 + ac + 1];
                v.z = (v.z - mu[k0 + ac + 2]) * rstd[k0 + ac + 2];
                v.w = (v.w - mu[k0 + ac + 3]) * rstd[k0 + ac + 3];
            }
            As[ac + 0][ar] = v.x;
            As[ac + 1][ar] = v.y;
            As[ac + 2][ar] = v.z;
            As[ac + 3][ar] = v.w;
        }
        {
            const int kr = t >> 4, nc = (t & 15) * 4;
            *(float4*)&Bs[kr][nc] = *(const float4*)&B[(long)(k0 + kr) * ldb + nc];
        }
        __syncthreads();
#pragma unroll
        for (int kk = 0; kk < 16; kk++) {
            float a[4], b[4];
            *(float4*)a = *(const float4*)&As[kk][ty * 4];
            *(float4*)b = *(const float4*)&Bs[kk][tx * 4];
#pragma unroll
            for (int i = 0; i < 4; i++)
#pragma unroll
                for (int j = 0; j < 4; j++)
                    acc[i][j] = fmaf(a[i], b[j], acc[i][j]);
        }
        __syncthreads();
    }

#pragma unroll
    for (int i = 0; i < 4; i++) {
        const long rowo = (long)(m0 + ty * 4 + i) * ldc + tx * 4;
        if (OSPLIT) {
            __half* ch = ChG + coff;
            __half* cl = ClG + coff;
#pragma unroll
            for (int j = 0; j < 4; j += 2) {
                __half h0, h1, l0, l1;
                h_split(acc[i][j],     h0, l0);
                h_split(acc[i][j + 1], h1, l1);
                *(__half2*)&ch[rowo + j] = __halves2half2(h0, h1);
                *(__half2*)&cl[rowo + j] = __halves2half2(l0, l1);
            }
        } else {
            float* C = Cg + coff;
#pragma unroll
            for (int j = 0; j < 4; j++)
                C[rowo + j] = acc[i][j];
        }
    }
}

// ---------------- Laplacian: W = tril(exp(-L1/4)); writes W, Wh/l, Wth/l --------
__global__ __launch_bounds__(1024) void laplacian_kernel()
{
    const int z = blockIdx.z;
    const int b = z >> 3, h = z & 7;
    const int i0 = blockIdx.y * 32, j0 = blockIdx.x * 32;
    const int tx = threadIdx.x, ty = threadIdx.y;
    const int tid = ty * 32 + tx;

    float*  Wp  = g_W   + (long)z * SC * SC;
    __half* Whp = g_Wh  + (long)z * SC * SC;
    __half* Wlp = g_Wl  + (long)z * SC * SC;
    __half* Wth = g_Wth + (long)z * SC * SC;
    __half* Wtl = g_Wtl + (long)z * SC * SC;

    if (j0 > i0 + 31) {   // fully masked tile (uniform per block)
        const long o  = (long)(i0 + ty) * SC + j0 + tx;
        const long ot = (long)(j0 + ty) * SC + i0 + tx;
        Wp[o] = 0.f;
        Whp[o] = __float2half(0.f); Wlp[o] = __float2half(0.f);
        Wth[ot] = __float2half(0.f); Wtl[ot] = __float2half(0.f);
        return;
    }

    const float* qp = g_qkv + (long)b * SC * 3 * DIMC + h * HDC;
    const float* kp = g_qkv + (long)b * SC * 3 * DIMC + DIMC + h * HDC;

    __shared__ float qs[32][65];
    __shared__ float ks[32][65];
    __shared__ float tr[32][33];

    for (int idx = tid; idx < 2048; idx += 1024) {
        const int r = idx >> 6, d = idx & 63;
        qs[r][d] = qp[(long)(i0 + r) * (3 * DIMC) + d];
        ks[r][d] = kp[(long)(j0 + r) * (3 * DIMC) + d];
    }
    __syncthreads();

    const int i = i0 + ty, j = j0 + tx;
    float out = 0.f;
    if (j <= i) {
        float s = 0.f;
#pragma unroll
        for (int d = 0; d < 64; d++)
            s += fabsf(qs[ty][d] - ks[tx][d]);
        out = expf(-0.25f * s);
    }
    const long o = (long)i * SC + j;
    Wp[o] = out;
    __half hh, hl;
    h_split(out, hh, hl);
    Whp[o] = hh; Wlp[o] = hl;

    tr[ty][tx] = out;
    __syncthreads();
    const float tv = tr[tx][ty];              // = W(i0+tx, j0+ty)
    h_split(tv, hh, hl);
    const long ot = (long)(j0 + ty) * SC + i0 + tx;
    Wth[ot] = hh; Wtl[ot] = hl;
}

// ---------------- NS init scale, phase 1: per-slice partials --------------------
__global__ __launch_bounds__(512) void ns_scale_p1()
{
    const int sl = blockIdx.x, z = blockIdx.y;
    const float* W = g_W + (long)z * SC * SC;
    const int t = threadIdx.x, wid = t >> 5, lid = t & 31;
    const int r0 = sl * 64;

    float cs = 0.f;
    for (int i = r0; i < r0 + 64; i++) cs += W[(long)i * SC + t];
    g_cs_part[sl][z][t] = cs;

    float rmax = 0.f;
    for (int r = r0 + wid * 4; r < r0 + wid * 4 + 4; r++) {
        const float4* row = (const float4*)&W[(long)r * SC];
        float s = 0.f;
#pragma unroll
        for (int p = 0; p < 4; p++) {
            const float4 v = row[lid + p * 32];
            s += v.x + v.y + v.z + v.w;
        }
#pragma unroll
        for (int o = 16; o > 0; o >>= 1) s += __shfl_xor_sync(0xFFFFFFFFu, s, o);
        rmax = fmaxf(rmax, s);
    }
    __shared__ float red[16];
    if (lid == 0) red[wid] = rmax;
    __syncthreads();
    if (t == 0) {
        float m = red[0];
#pragma unroll
        for (int i = 1; i < 16; i++) m = fmaxf(m, red[i]);
        g_rm_part[sl][z] = m;
    }
}

// ---------------- NS init scale, phase 2: combine -------------------------------
__global__ __launch_bounds__(512) void ns_scale_p2()
{
    const int z = blockIdx.x, t = threadIdx.x;
    float cs = 0.f;
#pragma unroll
    for (int sl = 0; sl < 8; sl++) cs += g_cs_part[sl][z][t];

    __shared__ float red[512];
    red[t] = cs; __syncthreads();
    for (int s = 256; s > 0; s >>= 1) {
        if (t < s) red[t] = fmaxf(red[t], red[t + s]);
        __syncthreads();
    }
    if (t == 0) {
        float rmax = g_rm_part[0][z];
#pragma unroll
        for (int sl = 1; sl < 8; sl++) rmax = fmaxf(rmax, g_rm_part[sl][z]);
        g_scale[z] = 1.f / (red[0] * rmax);
    }
}

// ---------------- whitening stats per (h, key column j) -------------------------
__global__ __launch_bounds__(256) void stats_kernel()
{
    const int jc = blockIdx.x, h = blockIdx.y;
    const int t = threadIdx.x;
    const int j = jc * 64 + (t & 63);
    const int slice = t >> 6;

    float s = 0.f, s2 = 0.f;
    for (int b = 0; b < BC; b++) {
        const float* Wp = g_W + (long)(b * HC + h) * SC * SC + j;
        for (int i = slice * 128; i < slice * 128 + 128; i++) {
            const float v = Wp[(long)i * SC];
            s += v; s2 += v * v;
        }
    }
    __shared__ float S1[256], S2[256];
    S1[t] = s; S2[t] = s2;
    __syncthreads();
    if (slice == 0) {
        s  = S1[t] + S1[t + 64] + S1[t + 128] + S1[t + 192];
        s2 = S2[t] + S2[t + 64] + S2[t + 128] + S2[t + 192];
        const float n = (float)(BC * SC);
        const float m = s / n;
        const float var = (s2 - n * m * m) / (n - 1.f);
        g_mu[h * SC + j]   = m;
        g_rstd[h * SC + j] = rsqrtf(var + EPSC);
    }
}

// ---------------- launch --------------------------------------------------------
extern "C" void kernel_launch(void* const* d_in, const int* in_sizes, int n_in,
                              void* d_out, int out_size)
{
    (void)in_sizes; (void)n_in; (void)out_size;
    const float* x      = (const float*)d_in[0];
    const float* qkv_w  = (const float*)d_in[1];
    const float* qkv_b  = (const float*)d_in[2];
    const float* proj_w = (const float*)d_in[3];
    const float* proj_b = (const float*)d_in[4];
    float* out = (float*)d_out;

    static float *pQKV = nullptr, *pW, *pXf, *pCTX, *pCTX2;
    static __half *pWh, *pWl, *pWth, *pWtl, *pZth, *pZtl;
    static __half *pXh[2], *pXl[2], *pXth[2], *pXtl[2];
    static __half *pxh, *pxl, *pwqh, *pwql, *ppwh, *ppwl, *pgah, *pgal;
    if (!pQKV) {
        cudaGetSymbolAddress((void**)&pQKV, g_qkv);
        cudaGetSymbolAddress((void**)&pW,   g_W);
        cudaGetSymbolAddress((void**)&pWh,  g_Wh);
        cudaGetSymbolAddress((void**)&pWl,  g_Wl);
        cudaGetSymbolAddress((void**)&pWth, g_Wth);
        cudaGetSymbolAddress((void**)&pWtl, g_Wtl);
        cudaGetSymbolAddress((void**)&pZth, g_Zth);
        cudaGetSymbolAddress((void**)&pZtl, g_Ztl);
        cudaGetSymbolAddress((void**)&pXh[0],  g_Xh0);
        cudaGetSymbolAddress((void**)&pXl[0],  g_Xl0);
        cudaGetSymbolAddress((void**)&pXh[1],  g_Xh1);
        cudaGetSymbolAddress((void**)&pXl[1],  g_Xl1);
        cudaGetSymbolAddress((void**)&pXth[0], g_Xth0);
        cudaGetSymbolAddress((void**)&pXtl[0], g_Xtl0);
        cudaGetSymbolAddress((void**)&pXth[1], g_Xth1);
        cudaGetSymbolAddress((void**)&pXtl[1], g_Xtl1);
        cudaGetSymbolAddress((void**)&pXf,  g_Xf);
        cudaGetSymbolAddress((void**)&pxh,  g_xh);
        cudaGetSymbolAddress((void**)&pxl,  g_xl);
        cudaGetSymbolAddress((void**)&pwqh, g_wqh);
        cudaGetSymbolAddress((void**)&pwql, g_wql);
        cudaGetSymbolAddress((void**)&ppwh, g_pwh);
        cudaGetSymbolAddress((void**)&ppwl, g_pwl);
        cudaGetSymbolAddress((void**)&pgah, g_gah);
        cudaGetSymbolAddress((void**)&pgal, g_gal);
        cudaGetSymbolAddress((void**)&pCTX, g_ctx);
        cudaGetSymbolAddress((void**)&pCTX2,g_ctx2);
        cudaFuncSetAttribute(mma_h<3,0,0,0,0,1,1,0,0,0>, cudaFuncAttributeMaxDynamicSharedMemorySize, MH_SMEM);
        cudaFuncSetAttribute(mma_h<1,1,1,1,1,0,0,1,0,0>, cudaFuncAttributeMaxDynamicSharedMemorySize, MH_SMEM);
        cudaFuncSetAttribute(mma_h<1,2,0,0,1,0,0,1,1,0>, cudaFuncAttributeMaxDynamicSharedMemorySize, MH_SMEM);
        cudaFuncSetAttribute(mma_h<1,0,1,1,0,0,0,1,0,0>, cudaFuncAttributeMaxDynamicSharedMemorySize, MH_SMEM);
        cudaFuncSetAttribute(mma_h<1,0,0,0,0,0,0,1,1,0>, cudaFuncAttributeMaxDynamicSharedMemorySize, MH_SMEM);
        cudaFuncSetAttribute(mma_h<1,0,0,0,0,0,0,1,1,1>, cudaFuncAttributeMaxDynamicSharedMemorySize, MH_SMEM);
        cudaFuncSetAttribute(mma_h<3,0,1,1,0,0,0,1,0,1>, cudaFuncAttributeMaxDynamicSharedMemorySize, MH_SMEM);
        cudaFuncSetAttribute(mma_h<3,0,0,0,0,0,1,0,0,0>, cudaFuncAttributeMaxDynamicSharedMemorySize, MH_SMEM);
    }

    const long MS = (long)SC * SC;
    const long CS = (long)SC * HDC;

    // 0) split static operands
    split_f16<<<512, 256>>>(x, pxh, pxl);
    split_f16<<<768, 256>>>(qkv_w, pwqh, pwql);
    split_f16<<<256, 256>>>(proj_w, ppwh, ppwl);

    // 1) qkv = x @ qkv_w^T + qkv_b   (NT, 3-term, fp32 out)
    mma_h<3,0,0,0,0,1,1,0,0,0><<<dim3(12, 8, 1), 128, MH_SMEM>>>(
        pxh, pxl, pwqh, pwql, nullptr, nullptr, nullptr, nullptr,
        pQKV, qkv_b, 512, 512, 1536, 0, 0, 0);

    // 2) W = tril(exp(-L1/4)) + splits of W and W^T
    laplacian_kernel<<<dim3(16, 16, 16), dim3(32, 32)>>>();

    // 3) scale = 1/(n1*ninf), parallel two-phase
    ns_scale_p1<<<dim3(8, 16), 512>>>();
    ns_scale_p2<<<16, 512>>>();

    // 5) Newton-Schulz (dual-orientation, all NT):
    //    Zt = 2I - Xt@W^T ; X' = X@Z (B = Zt) ; Xt' via transposed epilogue.
    //    Precision: it0-3 1-term; it4 3-term. LO only where a 3-term consumer
    //    reads the result (it3 X', it4 Zt). CTA mapping identical to R11 (no SWAP).
    mma_h<1,1,1,1,1,0,0,1,0,0><<<dim3(4, 4, 16), 128, MH_SMEM>>>(   // Zt0 = 2I - s*(W W^T)
        pWh, pWl, pWh, pWl, pZth, pZtl, nullptr, nullptr, nullptr, nullptr,
        512, 512, 512, MS, MS, MS);
    mma_h<1,2,0,0,1,0,0,1,1,0><<<dim3(4, 4, 16), 128, MH_SMEM>>>(   // X1 = s*(Wt Z0)
        pWth, pWtl, pZth, pZtl, pXh[0], pXl[0], pXth[0], pXtl[0], nullptr, nullptr,
        512, 512, 512, MS, MS, MS);
    int cur = 0;
    for (int it = 1; it < 4; it++) {
        mma_h<1,0,1,1,0,0,0,1,0,0><<<dim3(4, 4, 16), 128, MH_SMEM>>>(   // Zt = 2I - Xt W^T
            pXth[cur], pXtl[cur], pWh, pWl, pZth, pZtl, nullptr, nullptr, nullptr, nullptr,
            512, 512, 512, MS, MS, MS);
        if (it < 3) {
            mma_h<1,0,0,0,0,0,0,1,1,0><<<dim3(4, 4, 16), 128, MH_SMEM>>>(   // X' = X Z
                pXh[cur], pXl[cur], pZth, pZtl,
                pXh[1 - cur], pXl[1 - cur], pXth[1 - cur], pXtl[1 - cur], nullptr, nullptr,
                512, 512, 512, MS, MS, MS);
        } else {
            mma_h<1,0,0,0,0,0,0,1,1,1><<<dim3(4, 4, 16), 128, MH_SMEM>>>(   // X4 (lo kept)
                pXh[cur], pXl[cur], pZth, pZtl,
                pXh[1 - cur], pXl[1 - cur], pXth[1 - cur], pXtl[1 - cur], nullptr, nullptr,
                512, 512, 512, MS, MS, MS);
        }
        cur = 1 - cur;
    }
    // it4: full accuracy -> fp32 X5
    mma_h<3,0,1,1,0,0,0,1,0,1><<<dim3(4, 4, 16), 128, MH_SMEM>>>(
        pXth[cur], pXtl[cur], pWh, pWl, pZth, pZtl, nullptr, nullptr, nullptr, nullptr,
        512, 512, 512, MS, MS, MS);
    mma_h<3,0,0,0,0,0,1,0,0,0><<<dim3(4, 4, 16), 128, MH_SMEM>>>(
        pXh[cur], pXl[cur], pZth, pZtl, nullptr, nullptr, nullptr, nullptr,
        pXf, nullptr, 512, 512, 512, MS, MS, MS);

    // 6) whitening stats
    stats_kernel<<<dim3(8, 8), 256>>>();

    // 7) ctx = W^T @ v   (A=W lower-tri via TRANSA access: k >= m0 only)
    sgemm_n64<1, 0, 1, 0><<<dim3(8, 1, 16), 256>>>(
        pW, pQKV + 2 * DIMC, pCTX, nullptr, nullptr, 512, 512, 3 * DIMC, HDC,
        8 * MS, MS, (long)SC * 3 * DIMC, HDC, 8 * CS, CS);

    // 8) ctx2 = W_inv @ ctx  (W_inv = X5, dense)
    sgemm_n64<0, 0, 0, 0><<<dim3(8, 1, 16), 256>>>(
        pXf, pCTX, pCTX2, nullptr, nullptr, 512, 512, HDC, HDC,
        8 * MS, MS, 8 * CS, CS, 8 * CS, CS);

    // 9) ga = W_norm @ ctx2 -> [b, s, h*64+d], fused fp16 split (no fp32 ga)
    sgemm_n64<0, 1, 0, 1><<<dim3(8, 1, 16), 256>>>(
        pW, pCTX2, nullptr, pgah, pgal, 512, 512, HDC, 512,
        8 * MS, MS, 8 * CS, CS, MS, HDC);

    // 10) out = ga @ proj_w^T + proj_b   (NT, 3-term, fp32 out)
    mma_h<3,0,0,0,0,1,1,0,0,0><<<dim3(4, 8, 1), 128, MH_SMEM>>>(
        pgah, pgal, ppwh, ppwl, nullptr, nullptr, nullptr, nullptr,
        out, proj_b, 512, 512, 512, 0, 0, 0);
}

// round 14
// speedup vs baseline: 1.6044x; 1.0513x over previous
#include <cuda_runtime.h>
#include <cuda_fp16.h>
#include <math.h>
#include <stdint.h>

#define DIMC 512
#define HC 8
#define HDC 64
#define BC 2
#define SC 512
#define BHC 16
#define EPSC 1e-5f

// ---------------- scratch (device globals; no allocation allowed) ----------------
__device__ float  g_qkv[BC * SC * 3 * DIMC];     // [1024][1536] fp32
__device__ float  g_W  [BHC * SC * SC];          // fp32 W
__device__ __half g_Wh [BHC * SC * SC];          // fp16 hi/lo of W
__device__ __half g_Wl [BHC * SC * SC];
__device__ __half g_Wth[BHC * SC * SC];          // fp16 hi/lo of W^T
__device__ __half g_Wtl[BHC * SC * SC];
__device__ __half g_Zth[BHC * SC * SC];          // fp16 hi/lo of Z^T
__device__ __half g_Ztl[BHC * SC * SC];
__device__ __half g_Xh0[BHC * SC * SC];          // X double buffer (hi/lo)
__device__ __half g_Xl0[BHC * SC * SC];
__device__ __half g_Xh1[BHC * SC * SC];
__device__ __half g_Xl1[BHC * SC * SC];
__device__ __half g_Xth0[BHC * SC * SC];         // X^T double buffer (hi/lo)
__device__ __half g_Xtl0[BHC * SC * SC];
__device__ __half g_Xth1[BHC * SC * SC];
__device__ __half g_Xtl1[BHC * SC * SC];
__device__ float  g_Xf [BHC * SC * SC];          // fp32 X5 = W_inv
__device__ __half g_xh [BC * SC * DIMC];         // splits of x
__device__ __half g_xl [BC * SC * DIMC];
__device__ __half g_wqh[3 * DIMC * DIMC];        // splits of qkv_w
__device__ __half g_wql[3 * DIMC * DIMC];
__device__ __half g_pwh[DIMC * DIMC];            // splits of proj_w
__device__ __half g_pwl[DIMC * DIMC];
__device__ __half g_gah[BC * SC * DIMC];         // splits of ga
__device__ __half g_gal[BC * SC * DIMC];
__device__ float  g_ctx [BHC * SC * HDC];
__device__ float  g_ctx2[BHC * SC * HDC];
__device__ float  g_scale[BHC];
__device__ float  g_mu  [HC * SC];
__device__ float  g_rstd[HC * SC];
__device__ float  g_cs_part[8][BHC][SC];         // ns_scale partials
__device__ float  g_rm_part[8][BHC];

// ============================ helpers ============================================
__device__ __forceinline__ uint32_t smem_to_u32(const void* p) {
    uint32_t a;
    asm("{ .reg .u64 t; cvta.to.shared.u64 t, %1; cvt.u32.u64 %0, t; }" : "=r"(a) : "l"(p));
    return a;
}
__device__ __forceinline__ void cpa16h(uint32_t dst, const __half* src) {
    asm volatile("cp.async.cg.shared.global [%0], [%1], 16;" :: "r"(dst), "l"(src));
}
__device__ __forceinline__ void cpa_commit() {
    asm volatile("cp.async.commit_group;" ::: "memory");
}
__device__ __forceinline__ void mma16(float d[4], const uint32_t a[4],
                                      uint32_t b0, uint32_t b1) {
    asm volatile(
        "mma.sync.aligned.m16n8k16.row.col.f32.f16.f16.f32 "
        "{%0,%1,%2,%3}, {%4,%5,%6,%7}, {%8,%9}, {%0,%1,%2,%3};"
        : "+f"(d[0]), "+f"(d[1]), "+f"(d[2]), "+f"(d[3])
        : "r"(a[0]), "r"(a[1]), "r"(a[2]), "r"(a[3]), "r"(b0), "r"(b1));
}
#define LDM4(r0, r1, r2, r3, addr) \
    asm volatile("ldmatrix.sync.aligned.m8n8.x4.shared.b16 {%0,%1,%2,%3}, [%4];" \
        : "=r"(r0), "=r"(r1), "=r"(r2), "=r"(r3) : "r"(addr))
__device__ __forceinline__ void h_split(float v, __half& h, __half& l) {
    h = __float2half_rn(v);
    l = __float2half_rn(v - __half2float(h));
}

// ---------------- elementwise fp16 split ----------------------------------------
__global__ __launch_bounds__(256) void split_f16(
    const float* __restrict__ in, __half* __restrict__ oh, __half* __restrict__ ol)
{
    const int i = blockIdx.x * 256 + threadIdx.x;
    const float4 v = ((const float4*)in)[i];
    __half h0, h1, h2, h3, l0, l1, l2, l3;
    h_split(v.x, h0, l0); h_split(v.y, h1, l1);
    h_split(v.z, h2, l2); h_split(v.w, h3, l3);
    ((__half2*)oh)[2 * i]     = __halves2half2(h0, h1);
    ((__half2*)oh)[2 * i + 1] = __halves2half2(h2, h3);
    ((__half2*)ol)[2 * i]     = __halves2half2(l0, l1);
    ((__half2*)ol)[2 * i + 1] = __halves2half2(l2, l3);
}

// ================= fp16 multi-term GEMM (mma.sync m16n8k16), all NT ==============
// C[m][n] = sum_k A[m][k] * B[n][k].
// TERMS: 3 = AhBh+AhBl+AlBh, 1 = AhBh (ldmatrix fast path).
// TRIMA: 1 -> A lower-tri (k<=m): kb_end=(m0>>5)+4; 2 -> A upper-tri: kb_start=m0>>5.
// TRIMB: 1 -> B lower-tri (k<=n): kb_end=(n0>>5)+4.
// LO: write low-half output arrays (only needed when a 3-term GEMM consumes C).
#define MH_ROW 40                    // halves per smem row (32 + pad 8)
#define MH_ARR 5120                  // 128 * 40 halves per array
#define MH_STG_BYTES 40960           // 4 arrays * 10240 B
#define MH_SMEM 81920                // 2 stages

template<int TERMS>
__device__ __forceinline__ void mh_issue(
    const __half* __restrict__ Ah, const __half* __restrict__ Al,
    const __half* __restrict__ Bh, const __half* __restrict__ Bl,
    int lda, int ldb, int m0, int n0, int t, int k0, uint32_t base)
{
#pragma unroll
    for (int i = 0; i < 4; i++) {
        const int idx = t + i * 128;
        const int r = idx >> 2, c8 = (idx & 3) * 8;
        const uint32_t so = (uint32_t)(r * MH_ROW + c8) * 2u;
        cpa16h(base + so,          Ah + (long)(m0 + r) * lda + k0 + c8);
        if (TERMS == 3)
            cpa16h(base + 10240u + so, Al + (long)(m0 + r) * lda + k0 + c8);
        cpa16h(base + 20480u + so, Bh + (long)(n0 + r) * ldb + k0 + c8);
        if (TERMS >= 2)
            cpa16h(base + 30720u + so, Bl + (long)(n0 + r) * ldb + k0 + c8);
    }
    cpa_commit();
}

template<int TERMS, int TRIMA, int TRIMB, int ZDIAG, int SCALE, int BIAS,
         int OF32, int OH, int OT, int LO>
__global__ __launch_bounds__(128, 2) void mma_h(
    const __half* __restrict__ Ah, const __half* __restrict__ Al,
    const __half* __restrict__ Bh, const __half* __restrict__ Bl,
    __half* __restrict__ Ch, __half* __restrict__ Cl,
    __half* __restrict__ CtH, __half* __restrict__ CtL,
    float* __restrict__ Cf, const float* __restrict__ bias,
    int lda, int ldb, int ldc, long aB, long bB, long cB)
{
    extern __shared__ char dsm[];
    const uint32_t sb = smem_to_u32(dsm);
    const int t = threadIdx.x;
    const int w = t >> 5, lane = t & 31;
    const int tg = lane >> 2, tig = lane & 3;
    const int wm = (w & 1) * 64, wn = (w >> 1) * 64;
    const int m0 = blockIdx.y * 128, n0 = blockIdx.x * 128;
    const long zb = blockIdx.z;
    const __half* pAh = Ah + zb * aB;
    const __half* pAl = Al + zb * aB;
    const __half* pBh = Bh + zb * bB;
    const __half* pBl = Bl + zb * bB;

    // ldmatrix per-lane base offsets (bytes) within a stage (TERMS==1 fast path)
    const uint32_t aLane = (uint32_t)(((wm + (lane & 15)) * MH_ROW + (lane >> 4) * 8) * 2);
    const uint32_t bLane = 20480u + (uint32_t)(((wn + (lane & 7) + ((lane >> 4) & 1) * 8) * MH_ROW
                                               + ((lane >> 3) & 1) * 8) * 2);

    int kbs = 0, kbe = 16;
    if (TRIMA == 1) { const int e = (m0 >> 5) + 4; if (e < kbe) kbe = e; }
    if (TRIMA == 2) kbs = m0 >> 5;
    if (TRIMB == 1) { const int e = (n0 >> 5) + 4; if (e < kbe) kbe = e; }

    float acc[4][8][4];
#pragma unroll
    for (int i = 0; i < 4; i++)
#pragma unroll
        for (int j = 0; j < 8; j++)
#pragma unroll
            for (int p = 0; p < 4; p++) acc[i][j][p] = 0.f;

    mh_issue<TERMS>(pAh, pAl, pBh, pBl, lda, ldb, m0, n0, t, kbs * 32,
                    sb + (kbs & 1) * MH_STG_BYTES);

    for (int kb = kbs; kb < kbe; kb++) {
        if (kb + 1 < kbe) {
            mh_issue<TERMS>(pAh, pAl, pBh, pBl, lda, ldb, m0, n0, t,
                            (kb + 1) * 32, sb + ((kb + 1) & 1) * MH_STG_BYTES);
            asm volatile("cp.async.wait_group 1;" ::: "memory");
        } else {
            asm volatile("cp.async.wait_group 0;" ::: "memory");
        }
        __syncthreads();

        const uint32_t stg = sb + (kb & 1) * MH_STG_BYTES;
        const __half* S   = (const __half*)(dsm + (kb & 1) * MH_STG_BYTES);
        const __half* AsH = S;
        const __half* AsL = S + MH_ARR;
        const __half* BsH = S + 2 * MH_ARR;
        const __half* BsL = S + 3 * MH_ARR;

#pragma unroll
        for (int kk = 0; kk < 2; kk++) {
            if (TERMS == 1) {
                // ldmatrix fast path: 8 LDM4 + 32 HMMA per kk
                const uint32_t kOff = (uint32_t)(kk * 32);
                uint32_t ah[4][4], bh4[4][4];
#pragma unroll
                for (int mt = 0; mt < 4; mt++) {
                    const uint32_t ad = stg + aLane + (uint32_t)(mt * 16 * MH_ROW * 2) + kOff;
                    LDM4(ah[mt][0], ah[mt][1], ah[mt][2], ah[mt][3], ad);
                }
#pragma unroll
                for (int np = 0; np < 4; np++) {
                    const uint32_t bd = stg + bLane + (uint32_t)(np * 16 * MH_ROW * 2) + kOff;
                    LDM4(bh4[np][0], bh4[np][1], bh4[np][2], bh4[np][3], bd);
                }
#pragma unroll
                for (int nt = 0; nt < 8; nt++) {
                    const int np = nt >> 1, sel = (nt & 1) * 2;
#pragma unroll
                    for (int mt = 0; mt < 4; mt++)
                        mma16(acc[mt][nt], ah[mt], bh4[np][sel], bh4[np][sel + 1]);
                }
            } else {
                const int ko = kk * 16 + 2 * tig;
                uint32_t ah[4][4], al[4][4];
#pragma unroll
                for (int mt = 0; mt < 4; mt++) {
                    const int rr = (wm + 16 * mt + tg) * MH_ROW + ko;
                    ah[mt][0] = *(const uint32_t*)(AsH + rr);
                    ah[mt][1] = *(const uint32_t*)(AsH + rr + 8 * MH_ROW);
                    ah[mt][2] = *(const uint32_t*)(AsH + rr + 8);
                    ah[mt][3] = *(const uint32_t*)(AsH + rr + 8 * MH_ROW + 8);
                    if (TERMS == 3) {
                        al[mt][0] = *(const uint32_t*)(AsL + rr);
                        al[mt][1] = *(const uint32_t*)(AsL + rr + 8 * MH_ROW);
                        al[mt][2] = *(const uint32_t*)(AsL + rr + 8);
                        al[mt][3] = *(const uint32_t*)(AsL + rr + 8 * MH_ROW + 8);
                    }
                }
#pragma unroll
                for (int nt = 0; nt < 8; nt++) {
                    const int rb = (wn + 8 * nt + tg) * MH_ROW + ko;
                    const uint32_t bh0 = *(const uint32_t*)(BsH + rb);
                    const uint32_t bh1 = *(const uint32_t*)(BsH + rb + 8);
                    uint32_t bl0 = 0, bl1 = 0;
                    if (TERMS >= 2) {
                        bl0 = *(const uint32_t*)(BsL + rb);
                        bl1 = *(const uint32_t*)(BsL + rb + 8);
                    }
#pragma unroll
                    for (int mt = 0; mt < 4; mt++) {
                        mma16(acc[mt][nt], ah[mt], bh0, bh1);            // Ah*Bh
                        if (TERMS >= 2) mma16(acc[mt][nt], ah[mt], bl0, bl1);  // Ah*Bl
                        if (TERMS == 3) mma16(acc[mt][nt], al[mt], bh0, bh1);  // Al*Bh
                    }
                }
            }
        }
        __syncthreads();
    }

    // ---------------- epilogue ----------------
    float s = 1.f;
    if (SCALE) s = g_scale[zb];
    __half* tsH = (__half*)dsm;
    __half* tsL = (__half*)(dsm + 34816);

#pragma unroll
    for (int mt = 0; mt < 4; mt++) {
        const int r = wm + 16 * mt + tg;
#pragma unroll
        for (int nt = 0; nt < 8; nt++) {
            const int c = wn + 8 * nt + 2 * tig;
            float v0 = acc[mt][nt][0], v1 = acc[mt][nt][1];
            float v2 = acc[mt][nt][2], v3 = acc[mt][nt][3];
            if (SCALE) { v0 *= s; v1 *= s; v2 *= s; v3 *= s; }
            if (ZDIAG) {
                const int gr = m0 + r, gc = n0 + c;
                v0 = (gr == gc)         ? 2.f - v0 : -v0;
                v1 = (gr == gc + 1)     ? 2.f - v1 : -v1;
                v2 = (gr + 8 == gc)     ? 2.f - v2 : -v2;
                v3 = (gr + 8 == gc + 1) ? 2.f - v3 : -v3;
            }
            if (OF32) {
                float b0 = 0.f, b1 = 0.f;
                if (BIAS) { b0 = bias[n0 + c]; b1 = bias[n0 + c + 1]; }
                float* cf = Cf + zb * cB;
                *(float2*)&cf[(long)(m0 + r) * ldc + n0 + c] = make_float2(v0 + b0, v1 + b1);
                *(float2*)&cf[(long)(m0 + r + 8) * ldc + n0 + c] = make_float2(v2 + b0, v3 + b1);
            }
            if (OH || OT) {
                __half h0, h1, h2, h3, l0, l1, l2, l3;
                if (LO) {
                    h_split(v0, h0, l0); h_split(v1, h1, l1);
                    h_split(v2, h2, l2); h_split(v3, h3, l3);
                } else {
                    h0 = __float2half_rn(v0); h1 = __float2half_rn(v1);
                    h2 = __float2half_rn(v2); h3 = __float2half_rn(v3);
                }
                if (OH) {
                    __half* ch = Ch + zb * cB;
                    *(__half2*)&ch[(long)(m0 + r) * ldc + n0 + c]     = __halves2half2(h0, h1);
                    *(__half2*)&ch[(long)(m0 + r + 8) * ldc + n0 + c] = __halves2half2(h2, h3);
                    if (LO) {
                        __half* cl = Cl + zb * cB;
                        *(__half2*)&cl[(long)(m0 + r) * ldc + n0 + c]     = __halves2half2(l0, l1);
                        *(__half2*)&cl[(long)(m0 + r + 8) * ldc + n0 + c] = __halves2half2(l2, l3);
                    }
                }
                if (OT) {
                    tsH[c * 136 + r]           = h0;
                    tsH[(c + 1) * 136 + r]     = h1;
                    tsH[c * 136 + r + 8]       = h2;
                    tsH[(c + 1) * 136 + r + 8] = h3;
                    if (LO) {
                        tsL[c * 136 + r]           = l0;
                        tsL[(c + 1) * 136 + r]     = l1;
                        tsL[c * 136 + r + 8]       = l2;
                        tsL[(c + 1) * 136 + r + 8] = l3;
                    }
                }
            }
        }
    }
    if (OT) {
        __syncthreads();
        const uint4* srcH = (const uint4*)(tsH + t * 136);
        uint4* dH = (uint4*)(CtH + zb * cB + (long)(n0 + t) * ldc + m0);
#pragma unroll
        for (int j = 0; j < 16; j++) dH[j] = srcH[j];
        if (LO) {
            const uint4* srcL = (const uint4*)(tsL + t * 136);
            uint4* dL = (uint4*)(CtL + zb * cB + (long)(n0 + t) * ldc + m0);
#pragma unroll
            for (int j = 0; j < 16; j++) dL[j] = srcL[j];
        }
    }
}

// ---------------- small-N SGEMM: 64(M)x64(N) tile, BK=16, 256 threads, 4x4 ------
// TRIMK: 1 -> (TRANSA path, A=W lower-tri) contributions need k >= m0.
// OSPLIT: 1 -> write fp16 hi/lo split (ChG/ClG) instead of fp32.
template<int TRANSA, int ANORM, int TRIMK, int OSPLIT>
__global__ __launch_bounds__(256) void sgemm_n64(
    const float* __restrict__ Ag, const float* __restrict__ Bg, float* __restrict__ Cg,
    __half* __restrict__ ChG, __half* __restrict__ ClG,
    int K, int lda, int ldb, int ldc,
    long aO, long aI, long bO, long bI, long cO, long cI)
{
    const int z = blockIdx.z;
    const float* A = Ag + (long)(z >> 3) * aO + (long)(z & 7) * aI;
    const float* B = Bg + (long)(z >> 3) * bO + (long)(z & 7) * bI;
    const long coff = (long)(z >> 3) * cO + (long)(z & 7) * cI;
    const float* mu   = g_mu   + (z & 7) * SC;
    const float* rstd = g_rstd + (z & 7) * SC;

    const int m0 = blockIdx.x * 64;
    const int t  = threadIdx.x;
    const int ty = t >> 4, tx = t & 15;

    __shared__ float As[16][64];
    __shared__ float Bs[16][64];

    float acc[4][4];
#pragma unroll
    for (int i = 0; i < 4; i++)
#pragma unroll
        for (int j = 0; j < 4; j++) acc[i][j] = 0.f;

    const int kstart = TRIMK ? m0 : 0;
    for (int k0 = kstart; k0 < K; k0 += 16) {
        if (TRANSA) {
            const int kr = t >> 4, mc = (t & 15) * 4;
            *(float4*)&As[kr][mc] = *(const float4*)&A[(long)(k0 + kr) * lda + m0 + mc];
        } else {
            const int ar = t >> 2, ac = (t & 3) * 4;
            float4 v = *(const float4*)&A[(long)(m0 + ar) * lda + k0 + ac];
            if (ANORM) {
                v.x = (v.x - mu[k0 + ac + 0]) * rstd[k0 + ac + 0];
                v.y = (v.y - mu[k0 + ac + 1]) * rstd[k0 + ac + 1];
                v.z = (v.z - mu[k0 + ac + 2]) * rstd[k0 + ac + 2];
                v.w = (v.w - mu[k0 + ac + 3]) * rstd[k0 + ac + 3];
            }
            As[ac + 0][ar] = v.x;
            As[ac + 1][ar] = v.y;
            As[ac + 2][ar] = v.z;
            As[ac + 3][ar] = v.w;
        }
        {
            const int kr = t >> 4, nc = (t & 15) * 4;
            *(float4*)&Bs[kr][nc] = *(const float4*)&B[(long)(k0 + kr) * ldb + nc];
        }
        __syncthreads();
#pragma unroll
        for (int kk = 0; kk < 16; kk++) {
            float a[4], b[4];
            *(float4*)a = *(const float4*)&As[kk][ty * 4];
            *(float4*)b = *(const float4*)&Bs[kk][tx * 4];
#pragma unroll
            for (int i = 0; i < 4; i++)
#pragma unroll
                for (int j = 0; j < 4; j++)
                    acc[i][j] = fmaf(a[i], b[j], acc[i][j]);
        }
        __syncthreads();
    }

#pragma unroll
    for (int i = 0; i < 4; i++) {
        const long rowo = (long)(m0 + ty * 4 + i) * ldc + tx * 4;
        if (OSPLIT) {
            __half* ch = ChG + coff;
            __half* cl = ClG + coff;
#pragma unroll
            for (int j = 0; j < 4; j += 2) {
                __half h0, h1, l0, l1;
                h_split(acc[i][j],     h0, l0);
                h_split(acc[i][j + 1], h1, l1);
                *(__half2*)&ch[rowo + j] = __halves2half2(h0, h1);
                *(__half2*)&cl[rowo + j] = __halves2half2(l0, l1);
            }
        } else {
            float* C = Cg + coff;
#pragma unroll
            for (int j = 0; j < 4; j++)
                C[rowo + j] = acc[i][j];
        }
    }
}

// ---------------- Laplacian: W = tril(exp(-L1/4)); writes W, Wh/l, Wth/l --------
__global__ __launch_bounds__(1024) void laplacian_kernel()
{
    const int z = blockIdx.z;
    const int b = z >> 3, h = z & 7;
    const int i0 = blockIdx.y * 32, j0 = blockIdx.x * 32;
    const int tx = threadIdx.x, ty = threadIdx.y;
    const int tid = ty * 32 + tx;

    float*  Wp  = g_W   + (long)z * SC * SC;
    __half* Whp = g_Wh  + (long)z * SC * SC;
    __half* Wlp = g_Wl  + (long)z * SC * SC;
    __half* Wth = g_Wth + (long)z * SC * SC;
    __half* Wtl = g_Wtl + (long)z * SC * SC;

    if (j0 > i0 + 31) {   // fully masked tile (uniform per block)
        const long o  = (long)(i0 + ty) * SC + j0 + tx;
        const long ot = (long)(j0 + ty) * SC + i0 + tx;
        Wp[o] = 0.f;
        Whp[o] = __float2half(0.f); Wlp[o] = __float2half(0.f);
        Wth[ot] = __float2half(0.f); Wtl[ot] = __float2half(0.f);
        return;
    }

    const float* qp = g_qkv + (long)b * SC * 3 * DIMC + h * HDC;
    const float* kp = g_qkv + (long)b * SC * 3 * DIMC + DIMC + h * HDC;

    __shared__ float qs[32][65];
    __shared__ float ks[32][65];
    __shared__ float tr[32][33];

    for (int idx = tid; idx < 2048; idx += 1024) {
        const int r = idx >> 6, d = idx & 63;
        qs[r][d] = qp[(long)(i0 + r) * (3 * DIMC) + d];
        ks[r][d] = kp[(long)(j0 + r) * (3 * DIMC) + d];
    }
    __syncthreads();

    const int i = i0 + ty, j = j0 + tx;
    float out = 0.f;
    if (j <= i) {
        float s = 0.f;
#pragma unroll
        for (int d = 0; d < 64; d++)
            s += fabsf(qs[ty][d] - ks[tx][d]);
        out = expf(-0.25f * s);
    }
    const long o = (long)i * SC + j;
    Wp[o] = out;
    __half hh, hl;
    h_split(out, hh, hl);
    Whp[o] = hh; Wlp[o] = hl;

    tr[ty][tx] = out;
    __syncthreads();
    const float tv = tr[tx][ty];              // = W(i0+tx, j0+ty)
    h_split(tv, hh, hl);
    const long ot = (long)(j0 + ty) * SC + i0 + tx;
    Wth[ot] = hh; Wtl[ot] = hl;
}

// ---------------- NS init scale, phase 1: per-slice partials --------------------
__global__ __launch_bounds__(512) void ns_scale_p1()
{
    const int sl = blockIdx.x, z = blockIdx.y;
    const float* W = g_W + (long)z * SC * SC;
    const int t = threadIdx.x, wid = t >> 5, lid = t & 31;
    const int r0 = sl * 64;

    float cs = 0.f;
    for (int i = r0; i < r0 + 64; i++) cs += W[(long)i * SC + t];
    g_cs_part[sl][z][t] = cs;

    float rmax = 0.f;
    for (int r = r0 + wid * 4; r < r0 + wid * 4 + 4; r++) {
        const float4* row = (const float4*)&W[(long)r * SC];
        float s = 0.f;
#pragma unroll
        for (int p = 0; p < 4; p++) {
            const float4 v = row[lid + p * 32];
            s += v.x + v.y + v.z + v.w;
        }
#pragma unroll
        for (int o = 16; o > 0; o >>= 1) s += __shfl_xor_sync(0xFFFFFFFFu, s, o);
        rmax = fmaxf(rmax, s);
    }
    __shared__ float red[16];
    if (lid == 0) red[wid] = rmax;
    __syncthreads();
    if (t == 0) {
        float m = red[0];
#pragma unroll
        for (int i = 1; i < 16; i++) m = fmaxf(m, red[i]);
        g_rm_part[sl][z] = m;
    }
}

// ---------------- NS init scale, phase 2: combine -------------------------------
__global__ __launch_bounds__(512) void ns_scale_p2()
{
    const int z = blockIdx.x, t = threadIdx.x;
    float cs = 0.f;
#pragma unroll
    for (int sl = 0; sl < 8; sl++) cs += g_cs_part[sl][z][t];

    __shared__ float red[512];
    red[t] = cs; __syncthreads();
    for (int s = 256; s > 0; s >>= 1) {
        if (t < s) red[t] = fmaxf(red[t], red[t + s]);
        __syncthreads();
    }
    if (t == 0) {
        float rmax = g_rm_part[0][z];
#pragma unroll
        for (int sl = 1; sl < 8; sl++) rmax = fmaxf(rmax, g_rm_part[sl][z]);
        g_scale[z] = 1.f / (red[0] * rmax);
    }
}

// ---------------- whitening stats per (h, key column j) -------------------------
__global__ __launch_bounds__(256) void stats_kernel()
{
    const int jc = blockIdx.x, h = blockIdx.y;
    const int t = threadIdx.x;
    const int j = jc * 64 + (t & 63);
    const int slice = t >> 6;

    float s = 0.f, s2 = 0.f;
    for (int b = 0; b < BC; b++) {
        const float* Wp = g_W + (long)(b * HC + h) * SC * SC + j;
        for (int i = slice * 128; i < slice * 128 + 128; i++) {
            const float v = Wp[(long)i * SC];
            s += v; s2 += v * v;
        }
    }
    __shared__ float S1[256], S2[256];
    S1[t] = s; S2[t] = s2;
    __syncthreads();
    if (slice == 0) {
        s  = S1[t] + S1[t + 64] + S1[t + 128] + S1[t + 192];
        s2 = S2[t] + S2[t + 64] + S2[t + 128] + S2[t + 192];
        const float n = (float)(BC * SC);
        const float m = s / n;
        const float var = (s2 - n * m * m) / (n - 1.f);
        g_mu[h * SC + j]   = m;
        g_rstd[h * SC + j] = rsqrtf(var + EPSC);
    }
}

// ---------------- launch --------------------------------------------------------
extern "C" void kernel_launch(void* const* d_in, const int* in_sizes, int n_in,
                              void* d_out, int out_size)
{
    (void)in_sizes; (void)n_in; (void)out_size;
    const float* x      = (const float*)d_in[0];
    const float* qkv_w  = (const float*)d_in[1];
    const float* qkv_b  = (const float*)d_in[2];
    const float* proj_w = (const float*)d_in[3];
    const float* proj_b = (const float*)d_in[4];
    float* out = (float*)d_out;

    static float *pQKV = nullptr, *pW, *pXf, *pCTX, *pCTX2;
    static __half *pWh, *pWl, *pWth, *pWtl, *pZth, *pZtl;
    static __half *pXh[2], *pXl[2], *pXth[2], *pXtl[2];
    static __half *pxh, *pxl, *pwqh, *pwql, *ppwh, *ppwl, *pgah, *pgal;
    if (!pQKV) {
        cudaGetSymbolAddress((void**)&pQKV, g_qkv);
        cudaGetSymbolAddress((void**)&pW,   g_W);
        cudaGetSymbolAddress((void**)&pWh,  g_Wh);
        cudaGetSymbolAddress((void**)&pWl,  g_Wl);
        cudaGetSymbolAddress((void**)&pWth, g_Wth);
        cudaGetSymbolAddress((void**)&pWtl, g_Wtl);
        cudaGetSymbolAddress((void**)&pZth, g_Zth);
        cudaGetSymbolAddress((void**)&pZtl, g_Ztl);
        cudaGetSymbolAddress((void**)&pXh[0],  g_Xh0);
        cudaGetSymbolAddress((void**)&pXl[0],  g_Xl0);
        cudaGetSymbolAddress((void**)&pXh[1],  g_Xh1);
        cudaGetSymbolAddress((void**)&pXl[1],  g_Xl1);
        cudaGetSymbolAddress((void**)&pXth[0], g_Xth0);
        cudaGetSymbolAddress((void**)&pXtl[0], g_Xtl0);
        cudaGetSymbolAddress((void**)&pXth[1], g_Xth1);
        cudaGetSymbolAddress((void**)&pXtl[1], g_Xtl1);
        cudaGetSymbolAddress((void**)&pXf,  g_Xf);
        cudaGetSymbolAddress((void**)&pxh,  g_xh);
        cudaGetSymbolAddress((void**)&pxl,  g_xl);
        cudaGetSymbolAddress((void**)&pwqh, g_wqh);
        cudaGetSymbolAddress((void**)&pwql, g_wql);
        cudaGetSymbolAddress((void**)&ppwh, g_pwh);
        cudaGetSymbolAddress((void**)&ppwl, g_pwl);
        cudaGetSymbolAddress((void**)&pgah, g_gah);
        cudaGetSymbolAddress((void**)&pgal, g_gal);
        cudaGetSymbolAddress((void**)&pCTX, g_ctx);
        cudaGetSymbolAddress((void**)&pCTX2,g_ctx2);
        cudaFuncSetAttribute(mma_h<3,0,0,0,0,1,1,0,0,0>, cudaFuncAttributeMaxDynamicSharedMemorySize, MH_SMEM);
        cudaFuncSetAttribute(mma_h<1,1,1,1,1,0,0,1,0,0>, cudaFuncAttributeMaxDynamicSharedMemorySize, MH_SMEM);
        cudaFuncSetAttribute(mma_h<1,2,0,0,1,0,0,1,1,0>, cudaFuncAttributeMaxDynamicSharedMemorySize, MH_SMEM);
        cudaFuncSetAttribute(mma_h<1,0,1,1,0,0,0,1,0,0>, cudaFuncAttributeMaxDynamicSharedMemorySize, MH_SMEM);
        cudaFuncSetAttribute(mma_h<1,0,0,0,0,0,0,1,1,0>, cudaFuncAttributeMaxDynamicSharedMemorySize, MH_SMEM);
        cudaFuncSetAttribute(mma_h<1,0,0,0,0,0,0,1,1,1>, cudaFuncAttributeMaxDynamicSharedMemorySize, MH_SMEM);
        cudaFuncSetAttribute(mma_h<3,0,1,1,0,0,0,1,0,1>, cudaFuncAttributeMaxDynamicSharedMemorySize, MH_SMEM);
        cudaFuncSetAttribute(mma_h<3,0,0,0,0,0,1,0,0,0>, cudaFuncAttributeMaxDynamicSharedMemorySize, MH_SMEM);
    }

    const long MS = (long)SC * SC;
    const long CS = (long)SC * HDC;

    // 0) split static operands
    split_f16<<<512, 256>>>(x, pxh, pxl);
    split_f16<<<768, 256>>>(qkv_w, pwqh, pwql);
    split_f16<<<256, 256>>>(proj_w, ppwh, ppwl);

    // 1) qkv = x @ qkv_w^T + qkv_b   (NT, 3-term, fp32 out)
    mma_h<3,0,0,0,0,1,1,0,0,0><<<dim3(12, 8, 1), 128, MH_SMEM>>>(
        pxh, pxl, pwqh, pwql, nullptr, nullptr, nullptr, nullptr,
        pQKV, qkv_b, 512, 512, 1536, 0, 0, 0);

    // 2) W = tril(exp(-L1/4)) + splits of W and W^T
    laplacian_kernel<<<dim3(16, 16, 16), dim3(32, 32)>>>();

    // 3) scale = 1/(n1*ninf), parallel two-phase
    ns_scale_p1<<<dim3(8, 16), 512>>>();
    ns_scale_p2<<<16, 512>>>();

    // 5) Newton-Schulz (dual-orientation, all NT):
    //    Zt = 2I - Xt@W^T ; X' = X@Z (B = Zt) ; Xt' via transposed epilogue.
    //    Precision: it0-3 1-term (ldmatrix fast path); it4 3-term.
    //    LO only where a 3-term consumer reads the result (it3 X', it4 Zt).
    mma_h<1,1,1,1,1,0,0,1,0,0><<<dim3(4, 4, 16), 128, MH_SMEM>>>(   // Zt0 = 2I - s*(W W^T)
        pWh, pWl, pWh, pWl, pZth, pZtl, nullptr, nullptr, nullptr, nullptr,
        512, 512, 512, MS, MS, MS);
    mma_h<1,2,0,0,1,0,0,1,1,0><<<dim3(4, 4, 16), 128, MH_SMEM>>>(   // X1 = s*(Wt Z0)
        pWth, pWtl, pZth, pZtl, pXh[0], pXl[0], pXth[0], pXtl[0], nullptr, nullptr,
        512, 512, 512, MS, MS, MS);
    int cur = 0;
    for (int it = 1; it < 4; it++) {
        mma_h<1,0,1,1,0,0,0,1,0,0><<<dim3(4, 4, 16), 128, MH_SMEM>>>(   // Zt = 2I - Xt W^T
            pXth[cur], pXtl[cur], pWh, pWl, pZth, pZtl, nullptr, nullptr, nullptr, nullptr,
            512, 512, 512, MS, MS, MS);
        if (it < 3) {
            mma_h<1,0,0,0,0,0,0,1,1,0><<<dim3(4, 4, 16), 128, MH_SMEM>>>(   // X' = X Z
                pXh[cur], pXl[cur], pZth, pZtl,
                pXh[1 - cur], pXl[1 - cur], pXth[1 - cur], pXtl[1 - cur], nullptr, nullptr,
                512, 512, 512, MS, MS, MS);
        } else {
            mma_h<1,0,0,0,0,0,0,1,1,1><<<dim3(4, 4, 16), 128, MH_SMEM>>>(   // X4 (lo kept)
                pXh[cur], pXl[cur], pZth, pZtl,
                pXh[1 - cur], pXl[1 - cur], pXth[1 - cur], pXtl[1 - cur], nullptr, nullptr,
                512, 512, 512, MS, MS, MS);
        }
        cur = 1 - cur;
    }
    // it4: full accuracy -> fp32 X5
    mma_h<3,0,1,1,0,0,0,1,0,1><<<dim3(4, 4, 16), 128, MH_SMEM>>>(
        pXth[cur], pXtl[cur], pWh, pWl, pZth, pZtl, nullptr, nullptr, nullptr, nullptr,
        512, 512, 512, MS, MS, MS);
    mma_h<3,0,0,0,0,0,1,0,0,0><<<dim3(4, 4, 16), 128, MH_SMEM>>>(
        pXh[cur], pXl[cur], pZth, pZtl, nullptr, nullptr, nullptr, nullptr,
        pXf, nullptr, 512, 512, 512, MS, MS, MS);

    // 6) whitening stats
    stats_kernel<<<dim3(8, 8), 256>>>();

    // 7) ctx = W^T @ v   (A=W lower-tri via TRANSA access: k >= m0 only)
    sgemm_n64<1, 0, 1, 0><<<dim3(8, 1, 16), 256>>>(
        pW, pQKV + 2 * DIMC, pCTX, nullptr, nullptr, 512, 512, 3 * DIMC, HDC,
        8 * MS, MS, (long)SC * 3 * DIMC, HDC, 8 * CS, CS);

    // 8) ctx2 = W_inv @ ctx  (W_inv = X5, dense)
    sgemm_n64<0, 0, 0, 0><<<dim3(8, 1, 16), 256>>>(
        pXf, pCTX, pCTX2, nullptr, nullptr, 512, 512, HDC, HDC,
        8 * MS, MS, 8 * CS, CS, 8 * CS, CS);

    // 9) ga = W_norm @ ctx2 -> [b, s, h*64+d], fused fp16 split (no fp32 ga)
    sgemm_n64<0, 1, 0, 1><<<dim3(8, 1, 16), 256>>>(
        pW, pCTX2, nullptr, pgah, pgal, 512, 512, HDC, 512,
        8 * MS, MS, 8 * CS, CS, MS, HDC);

    // 10) out = ga @ proj_w^T + proj_b   (NT, 3-term, fp32 out)
    mma_h<3,0,0,0,0,1,1,0,0,0><<<dim3(4, 8, 1), 128, MH_SMEM>>>(
        pgah, pgal, ppwh, ppwl, nullptr, nullptr, nullptr, nullptr,
        out, proj_b, 512, 512, 512, 0, 0, 0);
}

// round 15
// speedup vs baseline: 1.7019x; 1.0608x over previous
#include <cuda_runtime.h>
#include <cuda_fp16.h>
#include <math.h>
#include <stdint.h>

#define DIMC 512
#define HC 8
#define HDC 64
#define BC 2
#define SC 512
#define BHC 16
#define EPSC 1e-5f

// ---------------- scratch (device globals; no allocation allowed) ----------------
__device__ float  g_qkv[BC * SC * 3 * DIMC];     // [1024][1536] fp32
__device__ float  g_W  [BHC * SC * SC];          // fp32 W
__device__ __half g_Wh [BHC * SC * SC];          // fp16 hi/lo of W
__device__ __half g_Wl [BHC * SC * SC];
__device__ __half g_Wth[BHC * SC * SC];          // fp16 hi/lo of W^T
__device__ __half g_Wtl[BHC * SC * SC];
__device__ __half g_Zth[BHC * SC * SC];          // fp16 hi/lo of Z^T
__device__ __half g_Ztl[BHC * SC * SC];
__device__ __half g_Xh0[BHC * SC * SC];          // X double buffer (hi/lo)
__device__ __half g_Xl0[BHC * SC * SC];
__device__ __half g_Xh1[BHC * SC * SC];
__device__ __half g_Xl1[BHC * SC * SC];
__device__ __half g_Xth0[BHC * SC * SC];         // X^T double buffer (hi/lo)
__device__ __half g_Xtl0[BHC * SC * SC];
__device__ __half g_Xth1[BHC * SC * SC];
__device__ __half g_Xtl1[BHC * SC * SC];
__device__ float  g_Xf [BHC * SC * SC];          // fp32 X5 = W_inv
__device__ __half g_xh [BC * SC * DIMC];         // splits of x
__device__ __half g_xl [BC * SC * DIMC];
__device__ __half g_wqh[3 * DIMC * DIMC];        // splits of qkv_w
__device__ __half g_wql[3 * DIMC * DIMC];
__device__ __half g_pwh[DIMC * DIMC];            // splits of proj_w
__device__ __half g_pwl[DIMC * DIMC];
__device__ __half g_gah[BC * SC * DIMC];         // splits of ga
__device__ __half g_gal[BC * SC * DIMC];
__device__ float  g_ctx [BHC * SC * HDC];
__device__ float  g_ctx2[BHC * SC * HDC];
__device__ float  g_scale[BHC];
__device__ float  g_mu  [HC * SC];
__device__ float  g_rstd[HC * SC];
__device__ float  g_cs_part[8][BHC][SC];         // ns_scale partials
__device__ float  g_rm_part[8][BHC];

// ============================ helpers ============================================
__device__ __forceinline__ uint32_t smem_to_u32(const void* p) {
    uint32_t a;
    asm("{ .reg .u64 t; cvta.to.shared.u64 t, %1; cvt.u32.u64 %0, t; }" : "=r"(a) : "l"(p));
    return a;
}
__device__ __forceinline__ void cpa16h(uint32_t dst, const __half* src) {
    asm volatile("cp.async.cg.shared.global [%0], [%1], 16;" :: "r"(dst), "l"(src));
}
__device__ __forceinline__ void cpa_commit() {
    asm volatile("cp.async.commit_group;" ::: "memory");
}
__device__ __forceinline__ void mma16(float d[4], const uint32_t a[4],
                                      uint32_t b0, uint32_t b1) {
    asm volatile(
        "mma.sync.aligned.m16n8k16.row.col.f32.f16.f16.f32 "
        "{%0,%1,%2,%3}, {%4,%5,%6,%7}, {%8,%9}, {%0,%1,%2,%3};"
        : "+f"(d[0]), "+f"(d[1]), "+f"(d[2]), "+f"(d[3])
        : "r"(a[0]), "r"(a[1]), "r"(a[2]), "r"(a[3]), "r"(b0), "r"(b1));
}
#define LDM4(r0, r1, r2, r3, addr) \
    asm volatile("ldmatrix.sync.aligned.m8n8.x4.shared.b16 {%0,%1,%2,%3}, [%4];" \
        : "=r"(r0), "=r"(r1), "=r"(r2), "=r"(r3) : "r"(addr))
__device__ __forceinline__ void h_split(float v, __half& h, __half& l) {
    h = __float2half_rn(v);
    l = __float2half_rn(v - __half2float(h));
}

// ---------------- elementwise fp16 split ----------------------------------------
__global__ __launch_bounds__(256) void split_f16(
    const float* __restrict__ in, __half* __restrict__ oh, __half* __restrict__ ol)
{
    const int i = blockIdx.x * 256 + threadIdx.x;
    const float4 v = ((const float4*)in)[i];
    __half h0, h1, h2, h3, l0, l1, l2, l3;
    h_split(v.x, h0, l0); h_split(v.y, h1, l1);
    h_split(v.z, h2, l2); h_split(v.w, h3, l3);
    ((__half2*)oh)[2 * i]     = __halves2half2(h0, h1);
    ((__half2*)oh)[2 * i + 1] = __halves2half2(h2, h3);
    ((__half2*)ol)[2 * i]     = __halves2half2(l0, l1);
    ((__half2*)ol)[2 * i + 1] = __halves2half2(l2, l3);
}

// ================= fp16 multi-term GEMM (mma.sync m16n8k16), all NT ==============
// C[m][n] = sum_k A[m][k] * B[n][k].
// TERMS: 3 = AhBh+AhBl+AlBh, 2 = AhBh+AhBl, 1 = AhBh (ldmatrix fast path).
// TRIMA: 1 -> A lower-tri (k<=m): kb_end=(m0>>5)+4; 2 -> A upper-tri: kb_start=m0>>5.
// TRIMB: 1 -> B lower-tri (k<=n): kb_end=(n0>>5)+4.
// LO: write low-half output arrays (only when a >=2-term GEMM consumes C's B-side
//     or a 3-term GEMM consumes C's A-side).
// Trimmed axes are remapped through P[(idx+z)&3] so co-resident CTA pairs
// (bid, bid+148) carry near-equal total k-block cost (NS grids are 4x4x16).
#define MH_ROW 40                    // halves per smem row (32 + pad 8)
#define MH_ARR 5120                  // 128 * 40 halves per array
#define MH_STG_BYTES 40960           // 4 arrays * 10240 B
#define MH_SMEM 81920                // 2 stages

template<int TERMS>
__device__ __forceinline__ void mh_issue(
    const __half* __restrict__ Ah, const __half* __restrict__ Al,
    const __half* __restrict__ Bh, const __half* __restrict__ Bl,
    int lda, int ldb, int m0, int n0, int t, int k0, uint32_t base)
{
#pragma unroll
    for (int i = 0; i < 4; i++) {
        const int idx = t + i * 128;
        const int r = idx >> 2, c8 = (idx & 3) * 8;
        const uint32_t so = (uint32_t)(r * MH_ROW + c8) * 2u;
        cpa16h(base + so,          Ah + (long)(m0 + r) * lda + k0 + c8);
        if (TERMS == 3)
            cpa16h(base + 10240u + so, Al + (long)(m0 + r) * lda + k0 + c8);
        cpa16h(base + 20480u + so, Bh + (long)(n0 + r) * ldb + k0 + c8);
        if (TERMS >= 2)
            cpa16h(base + 30720u + so, Bl + (long)(n0 + r) * ldb + k0 + c8);
    }
    cpa_commit();
}

template<int TERMS, int TRIMA, int TRIMB, int ZDIAG, int SCALE, int BIAS,
         int OF32, int OH, int OT, int LO>
__global__ __launch_bounds__(128, 2) void mma_h(
    const __half* __restrict__ Ah, const __half* __restrict__ Al,
    const __half* __restrict__ Bh, const __half* __restrict__ Bl,
    __half* __restrict__ Ch, __half* __restrict__ Cl,
    __half* __restrict__ CtH, __half* __restrict__ CtL,
    float* __restrict__ Cf, const float* __restrict__ bias,
    int lda, int ldb, int ldc, long aB, long bB, long cB)
{
    extern __shared__ char dsm[];
    const uint32_t sb = smem_to_u32(dsm);
    const int t = threadIdx.x;
    const int w = t >> 5, lane = t & 31;
    const int tg = lane >> 2, tig = lane & 3;
    const int wm = (w & 1) * 64, wn = (w >> 1) * 64;

    // pair-balance remap of trimmed axes (bijective per z; correctness-neutral)
    int nIdx = blockIdx.x, mIdx = blockIdx.y;
    if (TRIMB == 1) {
        const int P[4] = {0, 3, 1, 2};
        nIdx = P[(blockIdx.x + blockIdx.z) & 3];
    }
    if (TRIMA == 2) {
        const int P[4] = {0, 3, 1, 2};
        mIdx = P[(blockIdx.y + blockIdx.z) & 3];
    }
    const int m0 = mIdx * 128, n0 = nIdx * 128;
    const long zb = blockIdx.z;
    const __half* pAh = Ah + zb * aB;
    const __half* pAl = Al + zb * aB;
    const __half* pBh = Bh + zb * bB;
    const __half* pBl = Bl + zb * bB;

    // ldmatrix per-lane base offsets (bytes) within a stage (TERMS==1 fast path)
    const uint32_t aLane = (uint32_t)(((wm + (lane & 15)) * MH_ROW + (lane >> 4) * 8) * 2);
    const uint32_t bLane = 20480u + (uint32_t)(((wn + (lane & 7) + ((lane >> 4) & 1) * 8) * MH_ROW
                                               + ((lane >> 3) & 1) * 8) * 2);

    int kbs = 0, kbe = 16;
    if (TRIMA == 1) { const int e = (m0 >> 5) + 4; if (e < kbe) kbe = e; }
    if (TRIMA == 2) kbs = m0 >> 5;
    if (TRIMB == 1) { const int e = (n0 >> 5) + 4; if (e < kbe) kbe = e; }

    float acc[4][8][4];
#pragma unroll
    for (int i = 0; i < 4; i++)
#pragma unroll
        for (int j = 0; j < 8; j++)
#pragma unroll
            for (int p = 0; p < 4; p++) acc[i][j][p] = 0.f;

    mh_issue<TERMS>(pAh, pAl, pBh, pBl, lda, ldb, m0, n0, t, kbs * 32,
                    sb + (kbs & 1) * MH_STG_BYTES);

    for (int kb = kbs; kb < kbe; kb++) {
        if (kb + 1 < kbe) {
            mh_issue<TERMS>(pAh, pAl, pBh, pBl, lda, ldb, m0, n0, t,
                            (kb + 1) * 32, sb + ((kb + 1) & 1) * MH_STG_BYTES);
            asm volatile("cp.async.wait_group 1;" ::: "memory");
        } else {
            asm volatile("cp.async.wait_group 0;" ::: "memory");
        }
        __syncthreads();

        const uint32_t stg = sb + (kb & 1) * MH_STG_BYTES;
        const __half* S   = (const __half*)(dsm + (kb & 1) * MH_STG_BYTES);
        const __half* AsH = S;
        const __half* AsL = S + MH_ARR;
        const __half* BsH = S + 2 * MH_ARR;
        const __half* BsL = S + 3 * MH_ARR;

#pragma unroll
        for (int kk = 0; kk < 2; kk++) {
            if (TERMS == 1) {
                // ldmatrix fast path: 8 LDM4 + 32 HMMA per kk
                const uint32_t kOff = (uint32_t)(kk * 32);
                uint32_t ah[4][4], bh4[4][4];
#pragma unroll
                for (int mt = 0; mt < 4; mt++) {
                    const uint32_t ad = stg + aLane + (uint32_t)(mt * 16 * MH_ROW * 2) + kOff;
                    LDM4(ah[mt][0], ah[mt][1], ah[mt][2], ah[mt][3], ad);
                }
#pragma unroll
                for (int np = 0; np < 4; np++) {
                    const uint32_t bd = stg + bLane + (uint32_t)(np * 16 * MH_ROW * 2) + kOff;
                    LDM4(bh4[np][0], bh4[np][1], bh4[np][2], bh4[np][3], bd);
                }
#pragma unroll
                for (int nt = 0; nt < 8; nt++) {
                    const int np = nt >> 1, sel = (nt & 1) * 2;
#pragma unroll
                    for (int mt = 0; mt < 4; mt++)
                        mma16(acc[mt][nt], ah[mt], bh4[np][sel], bh4[np][sel + 1]);
                }
            } else {
                const int ko = kk * 16 + 2 * tig;
                uint32_t ah[4][4], al[4][4];
#pragma unroll
                for (int mt = 0; mt < 4; mt++) {
                    const int rr = (wm + 16 * mt + tg) * MH_ROW + ko;
                    ah[mt][0] = *(const uint32_t*)(AsH + rr);
                    ah[mt][1] = *(const uint32_t*)(AsH + rr + 8 * MH_ROW);
                    ah[mt][2] = *(const uint32_t*)(AsH + rr + 8);
                    ah[mt][3] = *(const uint32_t*)(AsH + rr + 8 * MH_ROW + 8);
                    if (TERMS == 3) {
                        al[mt][0] = *(const uint32_t*)(AsL + rr);
                        al[mt][1] = *(const uint32_t*)(AsL + rr + 8 * MH_ROW);
                        al[mt][2] = *(const uint32_t*)(AsL + rr + 8);
                        al[mt][3] = *(const uint32_t*)(AsL + rr + 8 * MH_ROW + 8);
                    }
                }
#pragma unroll
                for (int nt = 0; nt < 8; nt++) {
                    const int rb = (wn + 8 * nt + tg) * MH_ROW + ko;
                    const uint32_t bh0 = *(const uint32_t*)(BsH + rb);
                    const uint32_t bh1 = *(const uint32_t*)(BsH + rb + 8);
                    uint32_t bl0 = 0, bl1 = 0;
                    if (TERMS >= 2) {
                        bl0 = *(const uint32_t*)(BsL + rb);
                        bl1 = *(const uint32_t*)(BsL + rb + 8);
                    }
#pragma unroll
                    for (int mt = 0; mt < 4; mt++) {
                        mma16(acc[mt][nt], ah[mt], bh0, bh1);            // Ah*Bh
                        if (TERMS >= 2) mma16(acc[mt][nt], ah[mt], bl0, bl1);  // Ah*Bl
                        if (TERMS == 3) mma16(acc[mt][nt], al[mt], bh0, bh1);  // Al*Bh
                    }
                }
            }
        }
        __syncthreads();
    }

    // ---------------- epilogue ----------------
    float s = 1.f;
    if (SCALE) s = g_scale[zb];
    __half* tsH = (__half*)dsm;
    __half* tsL = (__half*)(dsm + 34816);

#pragma unroll
    for (int mt = 0; mt < 4; mt++) {
        const int r = wm + 16 * mt + tg;
#pragma unroll
        for (int nt = 0; nt < 8; nt++) {
            const int c = wn + 8 * nt + 2 * tig;
            float v0 = acc[mt][nt][0], v1 = acc[mt][nt][1];
            float v2 = acc[mt][nt][2], v3 = acc[mt][nt][3];
            if (SCALE) { v0 *= s; v1 *= s; v2 *= s; v3 *= s; }
            if (ZDIAG) {
                const int gr = m0 + r, gc = n0 + c;
                v0 = (gr == gc)         ? 2.f - v0 : -v0;
                v1 = (gr == gc + 1)     ? 2.f - v1 : -v1;
                v2 = (gr + 8 == gc)     ? 2.f - v2 : -v2;
                v3 = (gr + 8 == gc + 1) ? 2.f - v3 : -v3;
            }
            if (OF32) {
                float b0 = 0.f, b1 = 0.f;
                if (BIAS) { b0 = bias[n0 + c]; b1 = bias[n0 + c + 1]; }
                float* cf = Cf + zb * cB;
                *(float2*)&cf[(long)(m0 + r) * ldc + n0 + c] = make_float2(v0 + b0, v1 + b1);
                *(float2*)&cf[(long)(m0 + r + 8) * ldc + n0 + c] = make_float2(v2 + b0, v3 + b1);
            }
            if (OH || OT) {
                __half h0, h1, h2, h3, l0, l1, l2, l3;
                if (LO) {
                    h_split(v0, h0, l0); h_split(v1, h1, l1);
                    h_split(v2, h2, l2); h_split(v3, h3, l3);
                } else {
                    h0 = __float2half_rn(v0); h1 = __float2half_rn(v1);
                    h2 = __float2half_rn(v2); h3 = __float2half_rn(v3);
                }
                if (OH) {
                    __half* ch = Ch + zb * cB;
                    *(__half2*)&ch[(long)(m0 + r) * ldc + n0 + c]     = __halves2half2(h0, h1);
                    *(__half2*)&ch[(long)(m0 + r + 8) * ldc + n0 + c] = __halves2half2(h2, h3);
                    if (LO) {
                        __half* cl = Cl + zb * cB;
                        *(__half2*)&cl[(long)(m0 + r) * ldc + n0 + c]     = __halves2half2(l0, l1);
                        *(__half2*)&cl[(long)(m0 + r + 8) * ldc + n0 + c] = __halves2half2(l2, l3);
                    }
                }
                if (OT) {
                    tsH[c * 136 + r]           = h0;
                    tsH[(c + 1) * 136 + r]     = h1;
                    tsH[c * 136 + r + 8]       = h2;
                    tsH[(c + 1) * 136 + r + 8] = h3;
                    if (LO) {
                        tsL[c * 136 + r]           = l0;
                        tsL[(c + 1) * 136 + r]     = l1;
                        tsL[c * 136 + r + 8]       = l2;
                        tsL[(c + 1) * 136 + r + 8] = l3;
                    }
                }
            }
        }
    }
    if (OT) {
        __syncthreads();
        const uint4* srcH = (const uint4*)(tsH + t * 136);
        uint4* dH = (uint4*)(CtH + zb * cB + (long)(n0 + t) * ldc + m0);
#pragma unroll
        for (int j = 0; j < 16; j++) dH[j] = srcH[j];
        if (LO) {
            const uint4* srcL = (const uint4*)(tsL + t * 136);
            uint4* dL = (uint4*)(CtL + zb * cB + (long)(n0 + t) * ldc + m0);
#pragma unroll
            for (int j = 0; j < 16; j++) dL[j] = srcL[j];
        }
    }
}

// ---------------- small-N SGEMM: 64(M)x64(N) tile, BK=16, 256 threads, 4x4 ------
// TRIMK: 1 -> (TRANSA path, A=W lower-tri) contributions need k >= m0.
// OSPLIT: 1 -> write fp16 hi/lo split (ChG/ClG) instead of fp32.
template<int TRANSA, int ANORM, int TRIMK, int OSPLIT>
__global__ __launch_bounds__(256) void sgemm_n64(
    const float* __restrict__ Ag, const float* __restrict__ Bg, float* __restrict__ Cg,
    __half* __restrict__ ChG, __half* __restrict__ ClG,
    int K, int lda, int ldb, int ldc,
    long aO, long aI, long bO, long bI, long cO, long cI)
{
    const int z = blockIdx.z;
    const float* A = Ag + (long)(z >> 3) * aO + (long)(z & 7) * aI;
    const float* B = Bg + (long)(z >> 3) * bO + (long)(z & 7) * bI;
    const long coff = (long)(z >> 3) * cO + (long)(z & 7) * cI;
    const float* mu   = g_mu   + (z & 7) * SC;
    const float* rstd = g_rstd + (z & 7) * SC;

    const int m0 = blockIdx.x * 64;
    const int t  = threadIdx.x;
    const int ty = t >> 4, tx = t & 15;

    __shared__ float As[16][64];
    __shared__ float Bs[16][64];

    float acc[4][4];
#pragma unroll
    for (int i = 0; i < 4; i++)
#pragma unroll
        for (int j = 0; j < 4; j++) acc[i][j] = 0.f;

    const int kstart = TRIMK ? m0 : 0;
    for (int k0 = kstart; k0 < K; k0 += 16) {
        if (TRANSA) {
            const int kr = t >> 4, mc = (t & 15) * 4;
            *(float4*)&As[kr][mc] = *(const float4*)&A[(long)(k0 + kr) * lda + m0 + mc];
        } else {
            const int ar = t >> 2, ac = (t & 3) * 4;
            float4 v = *(const float4*)&A[(long)(m0 + ar) * lda + k0 + ac];
            if (ANORM) {
                v.x = (v.x - mu[k0 + ac + 0]) * rstd[k0 + ac + 0];
                v.y = (v.y - mu[k0 + ac + 1]) * rstd[k0 + ac + 1];
                v.z = (v.z - mu[k0 + ac + 2]) * rstd[k0 + ac + 2];
                v.w = (v.w - mu[k0 + ac + 3]) * rstd[k0 + ac + 3];
            }
            As[ac + 0][ar] = v.x;
            As[ac + 1][ar] = v.y;
            As[ac + 2][ar] = v.z;
            As[ac + 3][ar] = v.w;
        }
        {
            const int kr = t >> 4, nc = (t & 15) * 4;
            *(float4*)&Bs[kr][nc] = *(const float4*)&B[(long)(k0 + kr) * ldb + nc];
        }
        __syncthreads();
#pragma unroll
        for (int kk = 0; kk < 16; kk++) {
            float a[4], b[4];
            *(float4*)a = *(const float4*)&As[kk][ty * 4];
            *(float4*)b = *(const float4*)&Bs[kk][tx * 4];
#pragma unroll
            for (int i = 0; i < 4; i++)
#pragma unroll
                for (int j = 0; j < 4; j++)
                    acc[i][j] = fmaf(a[i], b[j], acc[i][j]);
        }
        __syncthreads();
    }

#pragma unroll
    for (int i = 0; i < 4; i++) {
        const long rowo = (long)(m0 + ty * 4 + i) * ldc + tx * 4;
        if (OSPLIT) {
            __half* ch = ChG + coff;
            __half* cl = ClG + coff;
#pragma unroll
            for (int j = 0; j < 4; j += 2) {
                __half h0, h1, l0, l1;
                h_split(acc[i][j],     h0, l0);
                h_split(acc[i][j + 1], h1, l1);
                *(__half2*)&ch[rowo + j] = __halves2half2(h0, h1);
                *(__half2*)&cl[rowo + j] = __halves2half2(l0, l1);
            }
        } else {
            float* C = Cg + coff;
#pragma unroll
            for (int j = 0; j < 4; j++)
                C[rowo + j] = acc[i][j];
        }
    }
}

// ---------------- Laplacian: W = tril(exp(-L1/4)); writes W, Wh/l, Wth/l --------
__global__ __launch_bounds__(1024) void laplacian_kernel()
{
    const int z = blockIdx.z;
    const int b = z >> 3, h = z & 7;
    const int i0 = blockIdx.y * 32, j0 = blockIdx.x * 32;
    const int tx = threadIdx.x, ty = threadIdx.y;
    const int tid = ty * 32 + tx;

    float*  Wp  = g_W   + (long)z * SC * SC;
    __half* Whp = g_Wh  + (long)z * SC * SC;
    __half* Wlp = g_Wl  + (long)z * SC * SC;
    __half* Wth = g_Wth + (long)z * SC * SC;
    __half* Wtl = g_Wtl + (long)z * SC * SC;

    if (j0 > i0 + 31) {   // fully masked tile (uniform per block)
        const long o  = (long)(i0 + ty) * SC + j0 + tx;
        const long ot = (long)(j0 + ty) * SC + i0 + tx;
        Wp[o] = 0.f;
        Whp[o] = __float2half(0.f); Wlp[o] = __float2half(0.f);
        Wth[ot] = __float2half(0.f); Wtl[ot] = __float2half(0.f);
        return;
    }

    const float* qp = g_qkv + (long)b * SC * 3 * DIMC + h * HDC;
    const float* kp = g_qkv + (long)b * SC * 3 * DIMC + DIMC + h * HDC;

    __shared__ float qs[32][65];
    __shared__ float ks[32][65];
    __shared__ float tr[32][33];

    for (int idx = tid; idx < 2048; idx += 1024) {
        const int r = idx >> 6, d = idx & 63;
        qs[r][d] = qp[(long)(i0 + r) * (3 * DIMC) + d];
        ks[r][d] = kp[(long)(j0 + r) * (3 * DIMC) + d];
    }
    __syncthreads();

    const int i = i0 + ty, j = j0 + tx;
    float out = 0.f;
    if (j <= i) {
        float s = 0.f;
#pragma unroll
        for (int d = 0; d < 64; d++)
            s += fabsf(qs[ty][d] - ks[tx][d]);
        out = expf(-0.25f * s);
    }
    const long o = (long)i * SC + j;
    Wp[o] = out;
    __half hh, hl;
    h_split(out, hh, hl);
    Whp[o] = hh; Wlp[o] = hl;

    tr[ty][tx] = out;
    __syncthreads();
    const float tv = tr[tx][ty];              // = W(i0+tx, j0+ty)
    h_split(tv, hh, hl);
    const long ot = (long)(j0 + ty) * SC + i0 + tx;
    Wth[ot] = hh; Wtl[ot] = hl;
}

// ---------------- NS init scale, phase 1: per-slice partials --------------------
__global__ __launch_bounds__(512) void ns_scale_p1()
{
    const int sl = blockIdx.x, z = blockIdx.y;
    const float* W = g_W + (long)z * SC * SC;
    const int t = threadIdx.x, wid = t >> 5, lid = t & 31;
    const int r0 = sl * 64;

    float cs = 0.f;
    for (int i = r0; i < r0 + 64; i++) cs += W[(long)i * SC + t];
    g_cs_part[sl][z][t] = cs;

    float rmax = 0.f;
    for (int r = r0 + wid * 4; r < r0 + wid * 4 + 4; r++) {
        const float4* row = (const float4*)&W[(long)r * SC];
        float s = 0.f;
#pragma unroll
        for (int p = 0; p < 4; p++) {
            const float4 v = row[lid + p * 32];
            s += v.x + v.y + v.z + v.w;
        }
#pragma unroll
        for (int o = 16; o > 0; o >>= 1) s += __shfl_xor_sync(0xFFFFFFFFu, s, o);
        rmax = fmaxf(rmax, s);
    }
    __shared__ float red[16];
    if (lid == 0) red[wid] = rmax;
    __syncthreads();
    if (t == 0) {
        float m = red[0];
#pragma unroll
        for (int i = 1; i < 16; i++) m = fmaxf(m, red[i]);
        g_rm_part[sl][z] = m;
    }
}

// ---------------- NS init scale, phase 2: combine -------------------------------
__global__ __launch_bounds__(512) void ns_scale_p2()
{
    const int z = blockIdx.x, t = threadIdx.x;
    float cs = 0.f;
#pragma unroll
    for (int sl = 0; sl < 8; sl++) cs += g_cs_part[sl][z][t];

    __shared__ float red[512];
    red[t] = cs; __syncthreads();
    for (int s = 256; s > 0; s >>= 1) {
        if (t < s) red[t] = fmaxf(red[t], red[t + s]);
        __syncthreads();
    }
    if (t == 0) {
        float rmax = g_rm_part[0][z];
#pragma unroll
        for (int sl = 1; sl < 8; sl++) rmax = fmaxf(rmax, g_rm_part[sl][z]);
        g_scale[z] = 1.f / (red[0] * rmax);
    }
}

// ---------------- whitening stats per (h, key column j) -------------------------
__global__ __launch_bounds__(256) void stats_kernel()
{
    const int jc = blockIdx.x, h = blockIdx.y;
    const int t = threadIdx.x;
    const int j = jc * 64 + (t & 63);
    const int slice = t >> 6;

    float s = 0.f, s2 = 0.f;
    for (int b = 0; b < BC; b++) {
        const float* Wp = g_W + (long)(b * HC + h) * SC * SC + j;
        for (int i = slice * 128; i < slice * 128 + 128; i++) {
            const float v = Wp[(long)i * SC];
            s += v; s2 += v * v;
        }
    }
    __shared__ float S1[256], S2[256];
    S1[t] = s; S2[t] = s2;
    __syncthreads();
    if (slice == 0) {
        s  = S1[t] + S1[t + 64] + S1[t + 128] + S1[t + 192];
        s2 = S2[t] + S2[t + 64] + S2[t + 128] + S2[t + 192];
        const float n = (float)(BC * SC);
        const float m = s / n;
        const float var = (s2 - n * m * m) / (n - 1.f);
        g_mu[h * SC + j]   = m;
        g_rstd[h * SC + j] = rsqrtf(var + EPSC);
    }
}

// ---------------- launch --------------------------------------------------------
extern "C" void kernel_launch(void* const* d_in, const int* in_sizes, int n_in,
                              void* d_out, int out_size)
{
    (void)in_sizes; (void)n_in; (void)out_size;
    const float* x      = (const float*)d_in[0];
    const float* qkv_w  = (const float*)d_in[1];
    const float* qkv_b  = (const float*)d_in[2];
    const float* proj_w = (const float*)d_in[3];
    const float* proj_b = (const float*)d_in[4];
    float* out = (float*)d_out;

    static float *pQKV = nullptr, *pW, *pXf, *pCTX, *pCTX2;
    static __half *pWh, *pWl, *pWth, *pWtl, *pZth, *pZtl;
    static __half *pXh[2], *pXl[2], *pXth[2], *pXtl[2];
    static __half *pxh, *pxl, *pwqh, *pwql, *ppwh, *ppwl, *pgah, *pgal;
    if (!pQKV) {
        cudaGetSymbolAddress((void**)&pQKV, g_qkv);
        cudaGetSymbolAddress((void**)&pW,   g_W);
        cudaGetSymbolAddress((void**)&pWh,  g_Wh);
        cudaGetSymbolAddress((void**)&pWl,  g_Wl);
        cudaGetSymbolAddress((void**)&pWth, g_Wth);
        cudaGetSymbolAddress((void**)&pWtl, g_Wtl);
        cudaGetSymbolAddress((void**)&pZth, g_Zth);
        cudaGetSymbolAddress((void**)&pZtl, g_Ztl);
        cudaGetSymbolAddress((void**)&pXh[0],  g_Xh0);
        cudaGetSymbolAddress((void**)&pXl[0],  g_Xl0);
        cudaGetSymbolAddress((void**)&pXh[1],  g_Xh1);
        cudaGetSymbolAddress((void**)&pXl[1],  g_Xl1);
        cudaGetSymbolAddress((void**)&pXth[0], g_Xth0);
        cudaGetSymbolAddress((void**)&pXtl[0], g_Xtl0);
        cudaGetSymbolAddress((void**)&pXth[1], g_Xth1);
        cudaGetSymbolAddress((void**)&pXtl[1], g_Xtl1);
        cudaGetSymbolAddress((void**)&pXf,  g_Xf);
        cudaGetSymbolAddress((void**)&pxh,  g_xh);
        cudaGetSymbolAddress((void**)&pxl,  g_xl);
        cudaGetSymbolAddress((void**)&pwqh, g_wqh);
        cudaGetSymbolAddress((void**)&pwql, g_wql);
        cudaGetSymbolAddress((void**)&ppwh, g_pwh);
        cudaGetSymbolAddress((void**)&ppwl, g_pwl);
        cudaGetSymbolAddress((void**)&pgah, g_gah);
        cudaGetSymbolAddress((void**)&pgal, g_gal);
        cudaGetSymbolAddress((void**)&pCTX, g_ctx);
        cudaGetSymbolAddress((void**)&pCTX2,g_ctx2);
        cudaFuncSetAttribute(mma_h<3,0,0,0,0,1,1,0,0,0>, cudaFuncAttributeMaxDynamicSharedMemorySize, MH_SMEM);
        cudaFuncSetAttribute(mma_h<1,1,1,1,1,0,0,1,0,0>, cudaFuncAttributeMaxDynamicSharedMemorySize, MH_SMEM);
        cudaFuncSetAttribute(mma_h<1,2,0,0,1,0,0,1,1,0>, cudaFuncAttributeMaxDynamicSharedMemorySize, MH_SMEM);
        cudaFuncSetAttribute(mma_h<1,0,1,1,0,0,0,1,0,0>, cudaFuncAttributeMaxDynamicSharedMemorySize, MH_SMEM);
        cudaFuncSetAttribute(mma_h<1,0,0,0,0,0,0,1,1,0>, cudaFuncAttributeMaxDynamicSharedMemorySize, MH_SMEM);
        cudaFuncSetAttribute(mma_h<2,0,1,1,0,0,0,1,0,1>, cudaFuncAttributeMaxDynamicSharedMemorySize, MH_SMEM);
        cudaFuncSetAttribute(mma_h<2,0,0,0,0,0,1,0,0,0>, cudaFuncAttributeMaxDynamicSharedMemorySize, MH_SMEM);
    }

    const long MS = (long)SC * SC;
    const long CS = (long)SC * HDC;

    // 0) split static operands
    split_f16<<<512, 256>>>(x, pxh, pxl);
    split_f16<<<768, 256>>>(qkv_w, pwqh, pwql);
    split_f16<<<256, 256>>>(proj_w, ppwh, ppwl);

    // 1) qkv = x @ qkv_w^T + qkv_b   (NT, 3-term, fp32 out)
    mma_h<3,0,0,0,0,1,1,0,0,0><<<dim3(12, 8, 1), 128, MH_SMEM>>>(
        pxh, pxl, pwqh, pwql, nullptr, nullptr, nullptr, nullptr,
        pQKV, qkv_b, 512, 512, 1536, 0, 0, 0);

    // 2) W = tril(exp(-L1/4)) + splits of W and W^T
    laplacian_kernel<<<dim3(16, 16, 16), dim3(32, 32)>>>();

    // 3) scale = 1/(n1*ninf), parallel two-phase
    ns_scale_p1<<<dim3(8, 16), 512>>>();
    ns_scale_p2<<<16, 512>>>();

    // 5) Newton-Schulz (dual-orientation, all NT):
    //    Zt = 2I - Xt@W^T ; X' = X@Z (B = Zt) ; Xt' via transposed epilogue.
    //    Precision: it0-3 1-term (ldmatrix); it4 2-term (A-lo dropped; direct
    //    error ~2e-4, under the 1e-3 gate with margin). X' its never write lo.
    mma_h<1,1,1,1,1,0,0,1,0,0><<<dim3(4, 4, 16), 128, MH_SMEM>>>(   // Zt0 = 2I - s*(W W^T)
        pWh, pWl, pWh, pWl, pZth, pZtl, nullptr, nullptr, nullptr, nullptr,
        512, 512, 512, MS, MS, MS);
    mma_h<1,2,0,0,1,0,0,1,1,0><<<dim3(4, 4, 16), 128, MH_SMEM>>>(   // X1 = s*(Wt Z0)
        pWth, pWtl, pZth, pZtl, pXh[0], pXl[0], pXth[0], pXtl[0], nullptr, nullptr,
        512, 512, 512, MS, MS, MS);
    int cur = 0;
    for (int it = 1; it < 4; it++) {
        mma_h<1,0,1,1,0,0,0,1,0,0><<<dim3(4, 4, 16), 128, MH_SMEM>>>(   // Zt = 2I - Xt W^T
            pXth[cur], pXtl[cur], pWh, pWl, pZth, pZtl, nullptr, nullptr, nullptr, nullptr,
            512, 512, 512, MS, MS, MS);
        mma_h<1,0,0,0,0,0,0,1,1,0><<<dim3(4, 4, 16), 128, MH_SMEM>>>(   // X' = X Z
            pXh[cur], pXl[cur], pZth, pZtl,
            pXh[1 - cur], pXl[1 - cur], pXth[1 - cur], pXtl[1 - cur], nullptr, nullptr,
            512, 512, 512, MS, MS, MS);
        cur = 1 - cur;
    }
    // it4: 2-term -> fp32 X5
    mma_h<2,0,1,1,0,0,0,1,0,1><<<dim3(4, 4, 16), 128, MH_SMEM>>>(   // Zt4 = 2I - Xt4 W^T
        pXth[cur], pXtl[cur], pWh, pWl, pZth, pZtl, nullptr, nullptr, nullptr, nullptr,
        512, 512, 512, MS, MS, MS);
    mma_h<2,0,0,0,0,0,1,0,0,0><<<dim3(4, 4, 16), 128, MH_SMEM>>>(   // X5 = X4 Z4
        pXh[cur], pXl[cur], pZth, pZtl, nullptr, nullptr, nullptr, nullptr,
        pXf, nullptr, 512, 512, 512, MS, MS, MS);

    // 6) whitening stats
    stats_kernel<<<dim3(8, 8), 256>>>();

    // 7) ctx = W^T @ v   (A=W lower-tri via TRANSA access: k >= m0 only)
    sgemm_n64<1, 0, 1, 0><<<dim3(8, 1, 16), 256>>>(
        pW, pQKV + 2 * DIMC, pCTX, nullptr, nullptr, 512, 512, 3 * DIMC, HDC,
        8 * MS, MS, (long)SC * 3 * DIMC, HDC, 8 * CS, CS);

    // 8) ctx2 = W_inv @ ctx  (W_inv = X5, dense)
    sgemm_n64<0, 0, 0, 0><<<dim3(8, 1, 16), 256>>>(
        pXf, pCTX, pCTX2, nullptr, nullptr, 512, 512, HDC, HDC,
        8 * MS, MS, 8 * CS, CS, 8 * CS, CS);

    // 9) ga = W_norm @ ctx2 -> [b, s, h*64+d], fused fp16 split (no fp32 ga)
    sgemm_n64<0, 1, 0, 1><<<dim3(8, 1, 16), 256>>>(
        pW, pCTX2, nullptr, pgah, pgal, 512, 512, HDC, 512,
        8 * MS, MS, 8 * CS, CS, MS, HDC);

    // 10) out = ga @ proj_w^T + proj_b   (NT, 3-term, fp32 out)
    mma_h<3,0,0,0,0,1,1,0,0,0><<<dim3(4, 8, 1), 128, MH_SMEM>>>(
        pgah, pgal, ppwh, ppwl, nullptr, nullptr, nullptr, nullptr,
        out, proj_b, 512, 512, 512, 0, 0, 0);
}

// round 16
// speedup vs baseline: 1.7045x; 1.0015x over previous
#include <cuda_runtime.h>
#include <cuda_fp16.h>
#include <math.h>
#include <stdint.h>

#define DIMC 512
#define HC 8
#define HDC 64
#define BC 2
#define SC 512
#define BHC 16
#define EPSC 1e-5f

// ---------------- scratch (device globals; no allocation allowed) ----------------
__device__ float  g_qkv[BC * SC * 3 * DIMC];     // [1024][1536] fp32
__device__ float  g_W  [BHC * SC * SC];          // fp32 W
__device__ __half g_Wh [BHC * SC * SC];          // fp16 hi/lo of W
__device__ __half g_Wl [BHC * SC * SC];
__device__ __half g_Wth[BHC * SC * SC];          // fp16 hi/lo of W^T
__device__ __half g_Wtl[BHC * SC * SC];
__device__ __half g_Zth[BHC * SC * SC];          // fp16 hi/lo of Z^T
__device__ __half g_Ztl[BHC * SC * SC];
__device__ __half g_Xh0[BHC * SC * SC];          // X double buffer (hi/lo)
__device__ __half g_Xl0[BHC * SC * SC];
__device__ __half g_Xh1[BHC * SC * SC];
__device__ __half g_Xl1[BHC * SC * SC];
__device__ __half g_Xth0[BHC * SC * SC];         // X^T double buffer (hi/lo)
__device__ __half g_Xtl0[BHC * SC * SC];
__device__ __half g_Xth1[BHC * SC * SC];
__device__ __half g_Xtl1[BHC * SC * SC];
__device__ float  g_Xf [BHC * SC * SC];          // fp32 X4
__device__ float  g_Zf [BHC * SC * SC];          // fp32 Zt4
__device__ __half g_xh [BC * SC * DIMC];         // splits of x
__device__ __half g_xl [BC * SC * DIMC];
__device__ __half g_wqh[3 * DIMC * DIMC];        // splits of qkv_w
__device__ __half g_wql[3 * DIMC * DIMC];
__device__ __half g_pwh[DIMC * DIMC];            // splits of proj_w
__device__ __half g_pwl[DIMC * DIMC];
__device__ __half g_gah[BC * SC * DIMC];         // splits of ga
__device__ __half g_gal[BC * SC * DIMC];
__device__ float  g_ctx [BHC * SC * HDC];
__device__ float  g_ctx2[BHC * SC * HDC];
__device__ float  g_scale[BHC];
__device__ float  g_mu  [HC * SC];
__device__ float  g_rstd[HC * SC];
__device__ float  g_cs_part[8][BHC][SC];         // ns_scale partials
__device__ float  g_rm_part[8][BHC];

// ============================ helpers ============================================
__device__ __forceinline__ uint32_t smem_to_u32(const void* p) {
    uint32_t a;
    asm("{ .reg .u64 t; cvta.to.shared.u64 t, %1; cvt.u32.u64 %0, t; }" : "=r"(a) : "l"(p));
    return a;
}
__device__ __forceinline__ void cpa16h(uint32_t dst, const __half* src) {
    asm volatile("cp.async.cg.shared.global [%0], [%1], 16;" :: "r"(dst), "l"(src));
}
__device__ __forceinline__ void cpa_commit() {
    asm volatile("cp.async.commit_group;" ::: "memory");
}
__device__ __forceinline__ void mma16(float d[4], const uint32_t a[4],
                                      uint32_t b0, uint32_t b1) {
    asm volatile(
        "mma.sync.aligned.m16n8k16.row.col.f32.f16.f16.f32 "
        "{%0,%1,%2,%3}, {%4,%5,%6,%7}, {%8,%9}, {%0,%1,%2,%3};"
        : "+f"(d[0]), "+f"(d[1]), "+f"(d[2]), "+f"(d[3])
        : "r"(a[0]), "r"(a[1]), "r"(a[2]), "r"(a[3]), "r"(b0), "r"(b1));
}
#define LDM4(r0, r1, r2, r3, addr) \
    asm volatile("ldmatrix.sync.aligned.m8n8.x4.shared.b16 {%0,%1,%2,%3}, [%4];" \
        : "=r"(r0), "=r"(r1), "=r"(r2), "=r"(r3) : "r"(addr))
__device__ __forceinline__ void h_split(float v, __half& h, __half& l) {
    h = __float2half_rn(v);
    l = __float2half_rn(v - __half2float(h));
}

// ---------------- elementwise fp16 split ----------------------------------------
__global__ __launch_bounds__(256) void split_f16(
    const float* __restrict__ in, __half* __restrict__ oh, __half* __restrict__ ol)
{
    const int i = blockIdx.x * 256 + threadIdx.x;
    const float4 v = ((const float4*)in)[i];
    __half h0, h1, h2, h3, l0, l1, l2, l3;
    h_split(v.x, h0, l0); h_split(v.y, h1, l1);
    h_split(v.z, h2, l2); h_split(v.w, h3, l3);
    ((__half2*)oh)[2 * i]     = __halves2half2(h0, h1);
    ((__half2*)oh)[2 * i + 1] = __halves2half2(h2, h3);
    ((__half2*)ol)[2 * i]     = __halves2half2(l0, l1);
    ((__half2*)ol)[2 * i + 1] = __halves2half2(l2, l3);
}

// ================= fp16 multi-term GEMM (mma.sync m16n8k16), all NT ==============
// C[m][n] = sum_k A[m][k] * B[n][k].
// TERMS: 3 = AhBh+AhBl+AlBh, 2 = AhBh+AhBl, 1 = AhBh (ldmatrix fast path).
// TRIMA: 1 -> A lower-tri (k<=m): kb_end=(m0>>5)+4; 2 -> A upper-tri: kb_start=m0>>5.
// TRIMB: 1 -> B lower-tri (k<=n): kb_end=(n0>>5)+4.
// LO: write low-half output arrays.
// Trimmed axes are remapped through P[(idx+z)&3] so co-resident CTA pairs
// (bid, bid+148) carry near-equal total k-block cost (NS grids are 4x4x16).
#define MH_ROW 40                    // halves per smem row (32 + pad 8)
#define MH_ARR 5120                  // 128 * 40 halves per array
#define MH_STG_BYTES 40960           // 4 arrays * 10240 B
#define MH_SMEM 81920                // 2 stages

template<int TERMS>
__device__ __forceinline__ void mh_issue(
    const __half* __restrict__ Ah, const __half* __restrict__ Al,
    const __half* __restrict__ Bh, const __half* __restrict__ Bl,
    int lda, int ldb, int m0, int n0, int t, int k0, uint32_t base)
{
#pragma unroll
    for (int i = 0; i < 4; i++) {
        const int idx = t + i * 128;
        const int r = idx >> 2, c8 = (idx & 3) * 8;
        const uint32_t so = (uint32_t)(r * MH_ROW + c8) * 2u;
        cpa16h(base + so,          Ah + (long)(m0 + r) * lda + k0 + c8);
        if (TERMS == 3)
            cpa16h(base + 10240u + so, Al + (long)(m0 + r) * lda + k0 + c8);
        cpa16h(base + 20480u + so, Bh + (long)(n0 + r) * ldb + k0 + c8);
        if (TERMS >= 2)
            cpa16h(base + 30720u + so, Bl + (long)(n0 + r) * ldb + k0 + c8);
    }
    cpa_commit();
}

template<int TERMS, int TRIMA, int TRIMB, int ZDIAG, int SCALE, int BIAS,
         int OF32, int OH, int OT, int LO>
__global__ __launch_bounds__(128, 2) void mma_h(
    const __half* __restrict__ Ah, const __half* __restrict__ Al,
    const __half* __restrict__ Bh, const __half* __restrict__ Bl,
    __half* __restrict__ Ch, __half* __restrict__ Cl,
    __half* __restrict__ CtH, __half* __restrict__ CtL,
    float* __restrict__ Cf, const float* __restrict__ bias,
    int lda, int ldb, int ldc, long aB, long bB, long cB)
{
    extern __shared__ char dsm[];
    const uint32_t sb = smem_to_u32(dsm);
    const int t = threadIdx.x;
    const int w = t >> 5, lane = t & 31;
    const int tg = lane >> 2, tig = lane & 3;
    const int wm = (w & 1) * 64, wn = (w >> 1) * 64;

    // pair-balance remap of trimmed axes (bijective per z; correctness-neutral)
    int nIdx = blockIdx.x, mIdx = blockIdx.y;
    if (TRIMB == 1) {
        const int P[4] = {0, 3, 1, 2};
        nIdx = P[(blockIdx.x + blockIdx.z) & 3];
    }
    if (TRIMA == 2) {
        const int P[4] = {0, 3, 1, 2};
        mIdx = P[(blockIdx.y + blockIdx.z) & 3];
    }
    const int m0 = mIdx * 128, n0 = nIdx * 128;
    const long zb = blockIdx.z;
    const __half* pAh = Ah + zb * aB;
    const __half* pAl = Al + zb * aB;
    const __half* pBh = Bh + zb * bB;
    const __half* pBl = Bl + zb * bB;

    // ldmatrix per-lane base offsets (bytes) within a stage (TERMS==1 fast path)
    const uint32_t aLane = (uint32_t)(((wm + (lane & 15)) * MH_ROW + (lane >> 4) * 8) * 2);
    const uint32_t bLane = 20480u + (uint32_t)(((wn + (lane & 7) + ((lane >> 4) & 1) * 8) * MH_ROW
                                               + ((lane >> 3) & 1) * 8) * 2);

    int kbs = 0, kbe = 16;
    if (TRIMA == 1) { const int e = (m0 >> 5) + 4; if (e < kbe) kbe = e; }
    if (TRIMA == 2) kbs = m0 >> 5;
    if (TRIMB == 1) { const int e = (n0 >> 5) + 4; if (e < kbe) kbe = e; }

    float acc[4][8][4];
#pragma unroll
    for (int i = 0; i < 4; i++)
#pragma unroll
        for (int j = 0; j < 8; j++)
#pragma unroll
            for (int p = 0; p < 4; p++) acc[i][j][p] = 0.f;

    mh_issue<TERMS>(pAh, pAl, pBh, pBl, lda, ldb, m0, n0, t, kbs * 32,
                    sb + (kbs & 1) * MH_STG_BYTES);

    for (int kb = kbs; kb < kbe; kb++) {
        if (kb + 1 < kbe) {
            mh_issue<TERMS>(pAh, pAl, pBh, pBl, lda, ldb, m0, n0, t,
                            (kb + 1) * 32, sb + ((kb + 1) & 1) * MH_STG_BYTES);
            asm volatile("cp.async.wait_group 1;" ::: "memory");
        } else {
            asm volatile("cp.async.wait_group 0;" ::: "memory");
        }
        __syncthreads();

        const uint32_t stg = sb + (kb & 1) * MH_STG_BYTES;
        const __half* S   = (const __half*)(dsm + (kb & 1) * MH_STG_BYTES);
        const __half* AsH = S;
        const __half* AsL = S + MH_ARR;
        const __half* BsH = S + 2 * MH_ARR;
        const __half* BsL = S + 3 * MH_ARR;

#pragma unroll
        for (int kk = 0; kk < 2; kk++) {
            if (TERMS == 1) {
                // ldmatrix fast path: 8 LDM4 + 32 HMMA per kk
                const uint32_t kOff = (uint32_t)(kk * 32);
                uint32_t ah[4][4], bh4[4][4];
#pragma unroll
                for (int mt = 0; mt < 4; mt++) {
                    const uint32_t ad = stg + aLane + (uint32_t)(mt * 16 * MH_ROW * 2) + kOff;
                    LDM4(ah[mt][0], ah[mt][1], ah[mt][2], ah[mt][3], ad);
                }
#pragma unroll
                for (int np = 0; np < 4; np++) {
                    const uint32_t bd = stg + bLane + (uint32_t)(np * 16 * MH_ROW * 2) + kOff;
                    LDM4(bh4[np][0], bh4[np][1], bh4[np][2], bh4[np][3], bd);
                }
#pragma unroll
                for (int nt = 0; nt < 8; nt++) {
                    const int np = nt >> 1, sel = (nt & 1) * 2;
#pragma unroll
                    for (int mt = 0; mt < 4; mt++)
                        mma16(acc[mt][nt], ah[mt], bh4[np][sel], bh4[np][sel + 1]);
                }
            } else {
                const int ko = kk * 16 + 2 * tig;
                uint32_t ah[4][4], al[4][4];
#pragma unroll
                for (int mt = 0; mt < 4; mt++) {
                    const int rr = (wm + 16 * mt + tg) * MH_ROW + ko;
                    ah[mt][0] = *(const uint32_t*)(AsH + rr);
                    ah[mt][1] = *(const uint32_t*)(AsH + rr + 8 * MH_ROW);
                    ah[mt][2] = *(const uint32_t*)(AsH + rr + 8);
                    ah[mt][3] = *(const uint32_t*)(AsH + rr + 8 * MH_ROW + 8);
                    if (TERMS == 3) {
                        al[mt][0] = *(const uint32_t*)(AsL + rr);
                        al[mt][1] = *(const uint32_t*)(AsL + rr + 8 * MH_ROW);
                        al[mt][2] = *(const uint32_t*)(AsL + rr + 8);
                        al[mt][3] = *(const uint32_t*)(AsL + rr + 8 * MH_ROW + 8);
                    }
                }
#pragma unroll
                for (int nt = 0; nt < 8; nt++) {
                    const int rb = (wn + 8 * nt + tg) * MH_ROW + ko;
                    const uint32_t bh0 = *(const uint32_t*)(BsH + rb);
                    const uint32_t bh1 = *(const uint32_t*)(BsH + rb + 8);
                    uint32_t bl0 = 0, bl1 = 0;
                    if (TERMS >= 2) {
                        bl0 = *(const uint32_t*)(BsL + rb);
                        bl1 = *(const uint32_t*)(BsL + rb + 8);
                    }
#pragma unroll
                    for (int mt = 0; mt < 4; mt++) {
                        mma16(acc[mt][nt], ah[mt], bh0, bh1);            // Ah*Bh
                        if (TERMS >= 2) mma16(acc[mt][nt], ah[mt], bl0, bl1);  // Ah*Bl
                        if (TERMS == 3) mma16(acc[mt][nt], al[mt], bh0, bh1);  // Al*Bh
                    }
                }
            }
        }
        __syncthreads();
    }

    // ---------------- epilogue ----------------
    float s = 1.f;
    if (SCALE) s = g_scale[zb];
    __half* tsH = (__half*)dsm;
    __half* tsL = (__half*)(dsm + 34816);

#pragma unroll
    for (int mt = 0; mt < 4; mt++) {
        const int r = wm + 16 * mt + tg;
#pragma unroll
        for (int nt = 0; nt < 8; nt++) {
            const int c = wn + 8 * nt + 2 * tig;
            float v0 = acc[mt][nt][0], v1 = acc[mt][nt][1];
            float v2 = acc[mt][nt][2], v3 = acc[mt][nt][3];
            if (SCALE) { v0 *= s; v1 *= s; v2 *= s; v3 *= s; }
            if (ZDIAG) {
                const int gr = m0 + r, gc = n0 + c;
                v0 = (gr == gc)         ? 2.f - v0 : -v0;
                v1 = (gr == gc + 1)     ? 2.f - v1 : -v1;
                v2 = (gr + 8 == gc)     ? 2.f - v2 : -v2;
                v3 = (gr + 8 == gc + 1) ? 2.f - v3 : -v3;
            }
            if (OF32) {
                float b0 = 0.f, b1 = 0.f;
                if (BIAS) { b0 = bias[n0 + c]; b1 = bias[n0 + c + 1]; }
                float* cf = Cf + zb * cB;
                *(float2*)&cf[(long)(m0 + r) * ldc + n0 + c] = make_float2(v0 + b0, v1 + b1);
                *(float2*)&cf[(long)(m0 + r + 8) * ldc + n0 + c] = make_float2(v2 + b0, v3 + b1);
            }
            if (OH || OT) {
                __half h0, h1, h2, h3, l0, l1, l2, l3;
                if (LO) {
                    h_split(v0, h0, l0); h_split(v1, h1, l1);
                    h_split(v2, h2, l2); h_split(v3, h3, l3);
                } else {
                    h0 = __float2half_rn(v0); h1 = __float2half_rn(v1);
                    h2 = __float2half_rn(v2); h3 = __float2half_rn(v3);
                }
                if (OH) {
                    __half* ch = Ch + zb * cB;
                    *(__half2*)&ch[(long)(m0 + r) * ldc + n0 + c]     = __halves2half2(h0, h1);
                    *(__half2*)&ch[(long)(m0 + r + 8) * ldc + n0 + c] = __halves2half2(h2, h3);
                    if (LO) {
                        __half* cl = Cl + zb * cB;
                        *(__half2*)&cl[(long)(m0 + r) * ldc + n0 + c]     = __halves2half2(l0, l1);
                        *(__half2*)&cl[(long)(m0 + r + 8) * ldc + n0 + c] = __halves2half2(l2, l3);
                    }
                }
                if (OT) {
                    tsH[c * 136 + r]           = h0;
                    tsH[(c + 1) * 136 + r]     = h1;
                    tsH[c * 136 + r + 8]       = h2;
                    tsH[(c + 1) * 136 + r + 8] = h3;
                    if (LO) {
                        tsL[c * 136 + r]           = l0;
                        tsL[(c + 1) * 136 + r]     = l1;
                        tsL[c * 136 + r + 8]       = l2;
                        tsL[(c + 1) * 136 + r + 8] = l3;
                    }
                }
            }
        }
    }
    if (OT) {
        __syncthreads();
        const uint4* srcH = (const uint4*)(tsH + t * 136);
        uint4* dH = (uint4*)(CtH + zb * cB + (long)(n0 + t) * ldc + m0);
#pragma unroll
        for (int j = 0; j < 16; j++) dH[j] = srcH[j];
        if (LO) {
            const uint4* srcL = (const uint4*)(tsL + t * 136);
            uint4* dL = (uint4*)(CtL + zb * cB + (long)(n0 + t) * ldc + m0);
#pragma unroll
            for (int j = 0; j < 16; j++) dL[j] = srcL[j];
        }
    }
}

// ---------------- small-N SGEMM: 64(M)x64(N) tile, BK=16, 256 threads, 4x4 ------
// TRIMK: 1 -> (TRANSA path, A=W lower-tri) contributions need k >= m0.
// OSPLIT: 1 -> write fp16 hi/lo split (ChG/ClG) instead of fp32.
template<int TRANSA, int ANORM, int TRIMK, int OSPLIT>
__global__ __launch_bounds__(256) void sgemm_n64(
    const float* __restrict__ Ag, const float* __restrict__ Bg, float* __restrict__ Cg,
    __half* __restrict__ ChG, __half* __restrict__ ClG,
    int K, int lda, int ldb, int ldc,
    long aO, long aI, long bO, long bI, long cO, long cI)
{
    const int z = blockIdx.z;
    const float* A = Ag + (long)(z >> 3) * aO + (long)(z & 7) * aI;
    const float* B = Bg + (long)(z >> 3) * bO + (long)(z & 7) * bI;
    const long coff = (long)(z >> 3) * cO + (long)(z & 7) * cI;
    const float* mu   = g_mu   + (z & 7) * SC;
    const float* rstd = g_rstd + (z & 7) * SC;

    const int m0 = blockIdx.x * 64;
    const int t  = threadIdx.x;
    const int ty = t >> 4, tx = t & 15;

    __shared__ float As[16][64];
    __shared__ float Bs[16][64];

    float acc[4][4];
#pragma unroll
    for (int i = 0; i < 4; i++)
#pragma unroll
        for (int j = 0; j < 4; j++) acc[i][j] = 0.f;

    const int kstart = TRIMK ? m0 : 0;
    for (int k0 = kstart; k0 < K; k0 += 16) {
        if (TRANSA) {
            const int kr = t >> 4, mc = (t & 15) * 4;
            *(float4*)&As[kr][mc] = *(const float4*)&A[(long)(k0 + kr) * lda + m0 + mc];
        } else {
            const int ar = t >> 2, ac = (t & 3) * 4;
            float4 v = *(const float4*)&A[(long)(m0 + ar) * lda + k0 + ac];
            if (ANORM) {
                v.x = (v.x - mu[k0 + ac + 0]) * rstd[k0 + ac + 0];
                v.y = (v.y - mu[k0 + ac + 1]) * rstd[k0 + ac + 1];
                v.z = (v.z - mu[k0 + ac + 2]) * rstd[k0 + ac + 2];
                v.w = (v.w - mu[k0 + ac + 3]) * rstd[k0 + ac + 3];
            }
            As[ac + 0][ar] = v.x;
            As[ac + 1][ar] = v.y;
            As[ac + 2][ar] = v.z;
            As[ac + 3][ar] = v.w;
        }
        {
            const int kr = t >> 4, nc = (t & 15) * 4;
            *(float4*)&Bs[kr][nc] = *(const float4*)&B[(long)(k0 + kr) * ldb + nc];
        }
        __syncthreads();
#pragma unroll
        for (int kk = 0; kk < 16; kk++) {
            float a[4], b[4];
            *(float4*)a = *(const float4*)&As[kk][ty * 4];
            *(float4*)b = *(const float4*)&Bs[kk][tx * 4];
#pragma unroll
            for (int i = 0; i < 4; i++)
#pragma unroll
                for (int j = 0; j < 4; j++)
                    acc[i][j] = fmaf(a[i], b[j], acc[i][j]);
        }
        __syncthreads();
    }

#pragma unroll
    for (int i = 0; i < 4; i++) {
        const long rowo = (long)(m0 + ty * 4 + i) * ldc + tx * 4;
        if (OSPLIT) {
            __half* ch = ChG + coff;
            __half* cl = ClG + coff;
#pragma unroll
            for (int j = 0; j < 4; j += 2) {
                __half h0, h1, l0, l1;
                h_split(acc[i][j],     h0, l0);
                h_split(acc[i][j + 1], h1, l1);
                *(__half2*)&ch[rowo + j] = __halves2half2(h0, h1);
                *(__half2*)&cl[rowo + j] = __halves2half2(l0, l1);
            }
        } else {
            float* C = Cg + coff;
#pragma unroll
            for (int j = 0; j < 4; j++)
                C[rowo + j] = acc[i][j];
        }
    }
}

// ---------------- Laplacian: W = tril(exp(-L1/4)); writes W, Wh/l, Wth/l --------
__global__ __launch_bounds__(1024) void laplacian_kernel()
{
    const int z = blockIdx.z;
    const int b = z >> 3, h = z & 7;
    const int i0 = blockIdx.y * 32, j0 = blockIdx.x * 32;
    const int tx = threadIdx.x, ty = threadIdx.y;
    const int tid = ty * 32 + tx;

    float*  Wp  = g_W   + (long)z * SC * SC;
    __half* Whp = g_Wh  + (long)z * SC * SC;
    __half* Wlp = g_Wl  + (long)z * SC * SC;
    __half* Wth = g_Wth + (long)z * SC * SC;
    __half* Wtl = g_Wtl + (long)z * SC * SC;

    if (j0 > i0 + 31) {   // fully masked tile (uniform per block)
        const long o  = (long)(i0 + ty) * SC + j0 + tx;
        const long ot = (long)(j0 + ty) * SC + i0 + tx;
        Wp[o] = 0.f;
        Whp[o] = __float2half(0.f); Wlp[o] = __float2half(0.f);
        Wth[ot] = __float2half(0.f); Wtl[ot] = __float2half(0.f);
        return;
    }

    const float* qp = g_qkv + (long)b * SC * 3 * DIMC + h * HDC;
    const float* kp = g_qkv + (long)b * SC * 3 * DIMC + DIMC + h * HDC;

    __shared__ float qs[32][65];
    __shared__ float ks[32][65];
    __shared__ float tr[32][33];

    for (int idx = tid; idx < 2048; idx += 1024) {
        const int r = idx >> 6, d = idx & 63;
        qs[r][d] = qp[(long)(i0 + r) * (3 * DIMC) + d];
        ks[r][d] = kp[(long)(j0 + r) * (3 * DIMC) + d];
    }
    __syncthreads();

    const int i = i0 + ty, j = j0 + tx;
    float out = 0.f;
    if (j <= i) {
        float s = 0.f;
#pragma unroll
        for (int d = 0; d < 64; d++)
            s += fabsf(qs[ty][d] - ks[tx][d]);
        out = expf(-0.25f * s);
    }
    const long o = (long)i * SC + j;
    Wp[o] = out;
    __half hh, hl;
    h_split(out, hh, hl);
    Whp[o] = hh; Wlp[o] = hl;

    tr[ty][tx] = out;
    __syncthreads();
    const float tv = tr[tx][ty];              // = W(i0+tx, j0+ty)
    h_split(tv, hh, hl);
    const long ot = (long)(j0 + ty) * SC + i0 + tx;
    Wth[ot] = hh; Wtl[ot] = hl;
}

// ---------------- NS init scale, phase 1: per-slice partials --------------------
__global__ __launch_bounds__(512) void ns_scale_p1()
{
    const int sl = blockIdx.x, z = blockIdx.y;
    const float* W = g_W + (long)z * SC * SC;
    const int t = threadIdx.x, wid = t >> 5, lid = t & 31;
    const int r0 = sl * 64;

    float cs = 0.f;
    for (int i = r0; i < r0 + 64; i++) cs += W[(long)i * SC + t];
    g_cs_part[sl][z][t] = cs;

    float rmax = 0.f;
    for (int r = r0 + wid * 4; r < r0 + wid * 4 + 4; r++) {
        const float4* row = (const float4*)&W[(long)r * SC];
        float s = 0.f;
#pragma unroll
        for (int p = 0; p < 4; p++) {
            const float4 v = row[lid + p * 32];
            s += v.x + v.y + v.z + v.w;
        }
#pragma unroll
        for (int o = 16; o > 0; o >>= 1) s += __shfl_xor_sync(0xFFFFFFFFu, s, o);
        rmax = fmaxf(rmax, s);
    }
    __shared__ float red[16];
    if (lid == 0) red[wid] = rmax;
    __syncthreads();
    if (t == 0) {
        float m = red[0];
#pragma unroll
        for (int i = 1; i < 16; i++) m = fmaxf(m, red[i]);
        g_rm_part[sl][z] = m;
    }
}

// ---------------- NS init scale, phase 2: combine -------------------------------
__global__ __launch_bounds__(512) void ns_scale_p2()
{
    const int z = blockIdx.x, t = threadIdx.x;
    float cs = 0.f;
#pragma unroll
    for (int sl = 0; sl < 8; sl++) cs += g_cs_part[sl][z][t];

    __shared__ float red[512];
    red[t] = cs; __syncthreads();
    for (int s = 256; s > 0; s >>= 1) {
        if (t < s) red[t] = fmaxf(red[t], red[t + s]);
        __syncthreads();
    }
    if (t == 0) {
        float rmax = g_rm_part[0][z];
#pragma unroll
        for (int sl = 1; sl < 8; sl++) rmax = fmaxf(rmax, g_rm_part[sl][z]);
        g_scale[z] = 1.f / (red[0] * rmax);
    }
}

// ---------------- whitening stats per (h, key column j) -------------------------
__global__ __launch_bounds__(256) void stats_kernel()
{
    const int jc = blockIdx.x, h = blockIdx.y;
    const int t = threadIdx.x;
    const int j = jc * 64 + (t & 63);
    const int slice = t >> 6;

    float s = 0.f, s2 = 0.f;
    for (int b = 0; b < BC; b++) {
        const float* Wp = g_W + (long)(b * HC + h) * SC * SC + j;
        for (int i = slice * 128; i < slice * 128 + 128; i++) {
            const float v = Wp[(long)i * SC];
            s += v; s2 += v * v;
        }
    }
    __shared__ float S1[256], S2[256];
    S1[t] = s; S2[t] = s2;
    __syncthreads();
    if (slice == 0) {
        s  = S1[t] + S1[t + 64] + S1[t + 128] + S1[t + 192];
        s2 = S2[t] + S2[t + 64] + S2[t + 128] + S2[t + 192];
        const float n = (float)(BC * SC);
        const float m = s / n;
        const float var = (s2 - n * m * m) / (n - 1.f);
        g_mu[h * SC + j]   = m;
        g_rstd[h * SC + j] = rsqrtf(var + EPSC);
    }
}

// ---------------- launch --------------------------------------------------------
extern "C" void kernel_launch(void* const* d_in, const int* in_sizes, int n_in,
                              void* d_out, int out_size)
{
    (void)in_sizes; (void)n_in; (void)out_size;
    const float* x      = (const float*)d_in[0];
    const float* qkv_w  = (const float*)d_in[1];
    const float* qkv_b  = (const float*)d_in[2];
    const float* proj_w = (const float*)d_in[3];
    const float* proj_b = (const float*)d_in[4];
    float* out = (float*)d_out;

    static float *pQKV = nullptr, *pW, *pXf, *pZf, *pCTX, *pCTX2;
    static __half *pWh, *pWl, *pWth, *pWtl, *pZth, *pZtl;
    static __half *pXh[2], *pXl[2], *pXth[2], *pXtl[2];
    static __half *pxh, *pxl, *pwqh, *pwql, *ppwh, *ppwl, *pgah, *pgal;
    if (!pQKV) {
        cudaGetSymbolAddress((void**)&pQKV, g_qkv);
        cudaGetSymbolAddress((void**)&pW,   g_W);
        cudaGetSymbolAddress((void**)&pWh,  g_Wh);
        cudaGetSymbolAddress((void**)&pWl,  g_Wl);
        cudaGetSymbolAddress((void**)&pWth, g_Wth);
        cudaGetSymbolAddress((void**)&pWtl, g_Wtl);
        cudaGetSymbolAddress((void**)&pZth, g_Zth);
        cudaGetSymbolAddress((void**)&pZtl, g_Ztl);
        cudaGetSymbolAddress((void**)&pXh[0],  g_Xh0);
        cudaGetSymbolAddress((void**)&pXl[0],  g_Xl0);
        cudaGetSymbolAddress((void**)&pXh[1],  g_Xh1);
        cudaGetSymbolAddress((void**)&pXl[1],  g_Xl1);
        cudaGetSymbolAddress((void**)&pXth[0], g_Xth0);
        cudaGetSymbolAddress((void**)&pXtl[0], g_Xtl0);
        cudaGetSymbolAddress((void**)&pXth[1], g_Xth1);
        cudaGetSymbolAddress((void**)&pXtl[1], g_Xtl1);
        cudaGetSymbolAddress((void**)&pXf,  g_Xf);
        cudaGetSymbolAddress((void**)&pZf,  g_Zf);
        cudaGetSymbolAddress((void**)&pxh,  g_xh);
        cudaGetSymbolAddress((void**)&pxl,  g_xl);
        cudaGetSymbolAddress((void**)&pwqh, g_wqh);
        cudaGetSymbolAddress((void**)&pwql, g_wql);
        cudaGetSymbolAddress((void**)&ppwh, g_pwh);
        cudaGetSymbolAddress((void**)&ppwl, g_pwl);
        cudaGetSymbolAddress((void**)&pgah, g_gah);
        cudaGetSymbolAddress((void**)&pgal, g_gal);
        cudaGetSymbolAddress((void**)&pCTX, g_ctx);
        cudaGetSymbolAddress((void**)&pCTX2,g_ctx2);
        cudaFuncSetAttribute(mma_h<3,0,0,0,0,1,1,0,0,0>, cudaFuncAttributeMaxDynamicSharedMemorySize, MH_SMEM);
        cudaFuncSetAttribute(mma_h<1,1,1,1,1,0,0,1,0,0>, cudaFuncAttributeMaxDynamicSharedMemorySize, MH_SMEM);
        cudaFuncSetAttribute(mma_h<1,2,0,0,1,0,0,1,1,0>, cudaFuncAttributeMaxDynamicSharedMemorySize, MH_SMEM);
        cudaFuncSetAttribute(mma_h<1,0,1,1,0,0,0,1,0,0>, cudaFuncAttributeMaxDynamicSharedMemorySize, MH_SMEM);
        cudaFuncSetAttribute(mma_h<1,0,0,0,0,0,0,1,1,0>, cudaFuncAttributeMaxDynamicSharedMemorySize, MH_SMEM);
        cudaFuncSetAttribute(mma_h<1,0,0,0,0,0,1,1,1,0>, cudaFuncAttributeMaxDynamicSharedMemorySize, MH_SMEM);
        cudaFuncSetAttribute(mma_h<2,0,1,1,0,0,1,0,0,0>, cudaFuncAttributeMaxDynamicSharedMemorySize, MH_SMEM);
    }

    const long MS = (long)SC * SC;
    const long CS = (long)SC * HDC;

    // 0) split static operands
    split_f16<<<512, 256>>>(x, pxh, pxl);
    split_f16<<<768, 256>>>(qkv_w, pwqh, pwql);
    split_f16<<<256, 256>>>(proj_w, ppwh, ppwl);

    // 1) qkv = x @ qkv_w^T + qkv_b   (NT, 3-term, fp32 out)
    mma_h<3,0,0,0,0,1,1,0,0,0><<<dim3(12, 8, 1), 128, MH_SMEM>>>(
        pxh, pxl, pwqh, pwql, nullptr, nullptr, nullptr, nullptr,
        pQKV, qkv_b, 512, 512, 1536, 0, 0, 0);

    // 2) W = tril(exp(-L1/4)) + splits of W and W^T
    laplacian_kernel<<<dim3(16, 16, 16), dim3(32, 32)>>>();

    // 3) scale = 1/(n1*ninf), parallel two-phase
    ns_scale_p1<<<dim3(8, 16), 512>>>();
    ns_scale_p2<<<16, 512>>>();

    // 5) Newton-Schulz (dual-orientation, all NT):
    //    Zt = 2I - Xt@W^T ; X' = X@Z (B = Zt) ; Xt' via transposed epilogue.
    //    Precision: it0-3 1-term (ldmatrix); it4 Zt 2-term.
    //    it4's X5 GEMM is ELIMINATED by reassociation:
    //      ctx2 = X5 @ ctx = X4 @ (Z4 @ ctx)  (thin fp32 GEMMs below).
    //    -> it3 X' also writes fp32 X4 (g_Xf); it4 Zt writes fp32 Zt4 (g_Zf).
    mma_h<1,1,1,1,1,0,0,1,0,0><<<dim3(4, 4, 16), 128, MH_SMEM>>>(   // Zt0 = 2I - s*(W W^T)
        pWh, pWl, pWh, pWl, pZth, pZtl, nullptr, nullptr, nullptr, nullptr,
        512, 512, 512, MS, MS, MS);
    mma_h<1,2,0,0,1,0,0,1,1,0><<<dim3(4, 4, 16), 128, MH_SMEM>>>(   // X1 = s*(Wt Z0)
        pWth, pWtl, pZth, pZtl, pXh[0], pXl[0], pXth[0], pXtl[0], nullptr, nullptr,
        512, 512, 512, MS, MS, MS);
    int cur = 0;
    for (int it = 1; it < 4; it++) {
        mma_h<1,0,1,1,0,0,0,1,0,0><<<dim3(4, 4, 16), 128, MH_SMEM>>>(   // Zt = 2I - Xt W^T
            pXth[cur], pXtl[cur], pWh, pWl, pZth, pZtl, nullptr, nullptr, nullptr, nullptr,
            512, 512, 512, MS, MS, MS);
        if (it < 3) {
            mma_h<1,0,0,0,0,0,0,1,1,0><<<dim3(4, 4, 16), 128, MH_SMEM>>>(   // X' = X Z
                pXh[cur], pXl[cur], pZth, pZtl,
                pXh[1 - cur], pXl[1 - cur], pXth[1 - cur], pXtl[1 - cur], nullptr, nullptr,
                512, 512, 512, MS, MS, MS);
        } else {
            mma_h<1,0,0,0,0,0,1,1,1,0><<<dim3(4, 4, 16), 128, MH_SMEM>>>(   // X4 (+fp32)
                pXh[cur], pXl[cur], pZth, pZtl,
                pXh[1 - cur], pXl[1 - cur], pXth[1 - cur], pXtl[1 - cur], pXf, nullptr,
                512, 512, 512, MS, MS, MS);
        }
        cur = 1 - cur;
    }
    // it4: Zt4 = 2I - Xt4 W^T (2-term, fp32 out). X5 GEMM removed.
    mma_h<2,0,1,1,0,0,1,0,0,0><<<dim3(4, 4, 16), 128, MH_SMEM>>>(
        pXth[cur], pXtl[cur], pWh, pWl, nullptr, nullptr, nullptr, nullptr,
        pZf, nullptr, 512, 512, 512, MS, MS, MS);

    // 6) whitening stats
    stats_kernel<<<dim3(8, 8), 256>>>();

    // 7) ctx = W^T @ v   (A=W lower-tri via TRANSA access: k >= m0 only)
    sgemm_n64<1, 0, 1, 0><<<dim3(8, 1, 16), 256>>>(
        pW, pQKV + 2 * DIMC, pCTX, nullptr, nullptr, 512, 512, 3 * DIMC, HDC,
        8 * MS, MS, (long)SC * 3 * DIMC, HDC, 8 * CS, CS);

    // 8a) tmp = Z4 @ ctx = (Zt4)^T @ ctx   (fp32)
    sgemm_n64<1, 0, 0, 0><<<dim3(8, 1, 16), 256>>>(
        pZf, pCTX, pCTX2, nullptr, nullptr, 512, 512, HDC, HDC,
        8 * MS, MS, 8 * CS, CS, 8 * CS, CS);

    // 8b) ctx2 = X4 @ tmp   (fp32; result into pCTX, ctx no longer needed)
    sgemm_n64<0, 0, 0, 0><<<dim3(8, 1, 16), 256>>>(
        pXf, pCTX2, pCTX, nullptr, nullptr, 512, 512, HDC, HDC,
        8 * MS, MS, 8 * CS, CS, 8 * CS, CS);

    // 9) ga = W_norm @ ctx2 -> [b, s, h*64+d], fused fp16 split (no fp32 ga)
    sgemm_n64<0, 1, 0, 1><<<dim3(8, 1, 16), 256>>>(
        pW, pCTX, nullptr, pgah, pgal, 512, 512, HDC, 512,
        8 * MS, MS, 8 * CS, CS, MS, HDC);

    // 10) out = ga @ proj_w^T + proj_b   (NT, 3-term, fp32 out)
    mma_h<3,0,0,0,0,1,1,0,0,0><<<dim3(4, 8, 1), 128, MH_SMEM>>>(
        pgah, pgal, ppwh, ppwl, nullptr, nullptr, nullptr, nullptr,
        out, proj_b, 512, 512, 512, 0, 0, 0);
}

// round 17
// speedup vs baseline: 1.8045x; 1.0586x over previous
#include <cuda_runtime.h>
#include <cuda_fp16.h>
#include <math.h>
#include <stdint.h>

#define DIMC 512
#define HC 8
#define HDC 64
#define BC 2
#define SC 512
#define BHC 16
#define EPSC 1e-5f

// ---------------- scratch (device globals; no allocation allowed) ----------------
__device__ float  g_qkv[BC * SC * 3 * DIMC];     // [1024][1536] fp32
__device__ float  g_W  [BHC * SC * SC];          // fp32 W
__device__ __half g_Wh [BHC * SC * SC];          // fp16 hi/lo of W
__device__ __half g_Wl [BHC * SC * SC];
__device__ __half g_Wth[BHC * SC * SC];          // fp16 hi/lo of W^T
__device__ __half g_Wtl[BHC * SC * SC];
__device__ __half g_Zth[BHC * SC * SC];          // fp16 hi/lo of Z^T
__device__ __half g_Ztl[BHC * SC * SC];
__device__ __half g_Xh0[BHC * SC * SC];          // X double buffer (hi/lo)
__device__ __half g_Xl0[BHC * SC * SC];
__device__ __half g_Xh1[BHC * SC * SC];
__device__ __half g_Xl1[BHC * SC * SC];
__device__ __half g_Xth0[BHC * SC * SC];         // X^T double buffer (hi/lo)
__device__ __half g_Xtl0[BHC * SC * SC];
__device__ __half g_Xth1[BHC * SC * SC];
__device__ __half g_Xtl1[BHC * SC * SC];
__device__ float  g_Xf [BHC * SC * SC];          // fp32 X4
__device__ float  g_Zf [BHC * SC * SC];          // fp32 Zt4
__device__ __half g_xh [BC * SC * DIMC];         // splits of x
__device__ __half g_xl [BC * SC * DIMC];
__device__ __half g_wqh[3 * DIMC * DIMC];        // splits of qkv_w
__device__ __half g_wql[3 * DIMC * DIMC];
__device__ __half g_pwh[DIMC * DIMC];            // splits of proj_w
__device__ __half g_pwl[DIMC * DIMC];
__device__ __half g_gah[BC * SC * DIMC];         // splits of ga
__device__ __half g_gal[BC * SC * DIMC];
__device__ float  g_ctx [BHC * SC * HDC];
__device__ float  g_ctx2[BHC * SC * HDC];
__device__ float  g_scale[BHC];
__device__ float  g_mu  [HC * SC];
__device__ float  g_rstd[HC * SC];
__device__ float  g_cs_part[8][BHC][SC];         // ns_scale partials
__device__ float  g_rm_part[8][BHC];

// ============================ helpers ============================================
__device__ __forceinline__ uint32_t smem_to_u32(const void* p) {
    uint32_t a;
    asm("{ .reg .u64 t; cvta.to.shared.u64 t, %1; cvt.u32.u64 %0, t; }" : "=r"(a) : "l"(p));
    return a;
}
__device__ __forceinline__ void cpa16h(uint32_t dst, const __half* src) {
    asm volatile("cp.async.cg.shared.global [%0], [%1], 16;" :: "r"(dst), "l"(src));
}
__device__ __forceinline__ void cpa_commit() {
    asm volatile("cp.async.commit_group;" ::: "memory");
}
__device__ __forceinline__ void mma16(float d[4], const uint32_t a[4],
                                      uint32_t b0, uint32_t b1) {
    asm volatile(
        "mma.sync.aligned.m16n8k16.row.col.f32.f16.f16.f32 "
        "{%0,%1,%2,%3}, {%4,%5,%6,%7}, {%8,%9}, {%0,%1,%2,%3};"
        : "+f"(d[0]), "+f"(d[1]), "+f"(d[2]), "+f"(d[3])
        : "r"(a[0]), "r"(a[1]), "r"(a[2]), "r"(a[3]), "r"(b0), "r"(b1));
}
#define LDM4(r0, r1, r2, r3, addr) \
    asm volatile("ldmatrix.sync.aligned.m8n8.x4.shared.b16 {%0,%1,%2,%3}, [%4];" \
        : "=r"(r0), "=r"(r1), "=r"(r2), "=r"(r3) : "r"(addr))
__device__ __forceinline__ void h_split(float v, __half& h, __half& l) {
    h = __float2half_rn(v);
    l = __float2half_rn(v - __half2float(h));
}

// ---------------- elementwise fp16 split ----------------------------------------
__global__ __launch_bounds__(256) void split_f16(
    const float* __restrict__ in, __half* __restrict__ oh, __half* __restrict__ ol)
{
    const int i = blockIdx.x * 256 + threadIdx.x;
    const float4 v = ((const float4*)in)[i];
    __half h0, h1, h2, h3, l0, l1, l2, l3;
    h_split(v.x, h0, l0); h_split(v.y, h1, l1);
    h_split(v.z, h2, l2); h_split(v.w, h3, l3);
    ((__half2*)oh)[2 * i]     = __halves2half2(h0, h1);
    ((__half2*)oh)[2 * i + 1] = __halves2half2(h2, h3);
    ((__half2*)ol)[2 * i]     = __halves2half2(l0, l1);
    ((__half2*)ol)[2 * i + 1] = __halves2half2(l2, l3);
}

// ================= fp16 multi-term GEMM (mma.sync m16n8k16), all NT ==============
// C[m][n] = sum_k A[m][k] * B[n][k].
// TERMS: 3 = AhBh+AhBl+AlBh, 2 = AhBh+AhBl, 1 = AhBh (ldmatrix fast path).
// TRIMA: 1 -> A lower-tri (k<=m): kb_end=(m0>>5)+4; 2 -> A upper-tri: kb_start=m0>>5.
// TRIMB: 1 -> B lower-tri (k<=n): kb_end=(n0>>5)+4.
// LO: write low-half output arrays.
// Trimmed axes are remapped through P[(idx+z)&3] so co-resident CTA pairs
// (bid, bid+148) carry near-equal total k-block cost (NS grids are 4x4x16).
#define MH_ROW 40                    // halves per smem row (32 + pad 8)
#define MH_ARR 5120                  // 128 * 40 halves per array
#define MH_STG_BYTES 40960           // 4 arrays * 10240 B
#define MH_SMEM 81920                // 2 stages

template<int TERMS>
__device__ __forceinline__ void mh_issue(
    const __half* __restrict__ Ah, const __half* __restrict__ Al,
    const __half* __restrict__ Bh, const __half* __restrict__ Bl,
    int lda, int ldb, int m0, int n0, int t, int k0, uint32_t base)
{
#pragma unroll
    for (int i = 0; i < 4; i++) {
        const int idx = t + i * 128;
        const int r = idx >> 2, c8 = (idx & 3) * 8;
        const uint32_t so = (uint32_t)(r * MH_ROW + c8) * 2u;
        cpa16h(base + so,          Ah + (long)(m0 + r) * lda + k0 + c8);
        if (TERMS == 3)
            cpa16h(base + 10240u + so, Al + (long)(m0 + r) * lda + k0 + c8);
        cpa16h(base + 20480u + so, Bh + (long)(n0 + r) * ldb + k0 + c8);
        if (TERMS >= 2)
            cpa16h(base + 30720u + so, Bl + (long)(n0 + r) * ldb + k0 + c8);
    }
    cpa_commit();
}

template<int TERMS, int TRIMA, int TRIMB, int ZDIAG, int SCALE, int BIAS,
         int OF32, int OH, int OT, int LO>
__global__ __launch_bounds__(128, 2) void mma_h(
    const __half* __restrict__ Ah, const __half* __restrict__ Al,
    const __half* __restrict__ Bh, const __half* __restrict__ Bl,
    __half* __restrict__ Ch, __half* __restrict__ Cl,
    __half* __restrict__ CtH, __half* __restrict__ CtL,
    float* __restrict__ Cf, const float* __restrict__ bias,
    int lda, int ldb, int ldc, long aB, long bB, long cB)
{
    extern __shared__ char dsm[];
    const uint32_t sb = smem_to_u32(dsm);
    const int t = threadIdx.x;
    const int w = t >> 5, lane = t & 31;
    const int tg = lane >> 2, tig = lane & 3;
    const int wm = (w & 1) * 64, wn = (w >> 1) * 64;

    // pair-balance remap of trimmed axes (bijective per z; correctness-neutral)
    int nIdx = blockIdx.x, mIdx = blockIdx.y;
    if (TRIMB == 1) {
        const int P[4] = {0, 3, 1, 2};
        nIdx = P[(blockIdx.x + blockIdx.z) & 3];
    }
    if (TRIMA == 2) {
        const int P[4] = {0, 3, 1, 2};
        mIdx = P[(blockIdx.y + blockIdx.z) & 3];
    }
    const int m0 = mIdx * 128, n0 = nIdx * 128;
    const long zb = blockIdx.z;
    const __half* pAh = Ah + zb * aB;
    const __half* pAl = Al + zb * aB;
    const __half* pBh = Bh + zb * bB;
    const __half* pBl = Bl + zb * bB;

    // ldmatrix per-lane base offsets (bytes) within a stage (TERMS==1 fast path)
    const uint32_t aLane = (uint32_t)(((wm + (lane & 15)) * MH_ROW + (lane >> 4) * 8) * 2);
    const uint32_t bLane = 20480u + (uint32_t)(((wn + (lane & 7) + ((lane >> 4) & 1) * 8) * MH_ROW
                                               + ((lane >> 3) & 1) * 8) * 2);

    int kbs = 0, kbe = 16;
    if (TRIMA == 1) { const int e = (m0 >> 5) + 4; if (e < kbe) kbe = e; }
    if (TRIMA == 2) kbs = m0 >> 5;
    if (TRIMB == 1) { const int e = (n0 >> 5) + 4; if (e < kbe) kbe = e; }

    float acc[4][8][4];
#pragma unroll
    for (int i = 0; i < 4; i++)
#pragma unroll
        for (int j = 0; j < 8; j++)
#pragma unroll
            for (int p = 0; p < 4; p++) acc[i][j][p] = 0.f;

    mh_issue<TERMS>(pAh, pAl, pBh, pBl, lda, ldb, m0, n0, t, kbs * 32,
                    sb + (kbs & 1) * MH_STG_BYTES);

    for (int kb = kbs; kb < kbe; kb++) {
        if (kb + 1 < kbe) {
            mh_issue<TERMS>(pAh, pAl, pBh, pBl, lda, ldb, m0, n0, t,
                            (kb + 1) * 32, sb + ((kb + 1) & 1) * MH_STG_BYTES);
            asm volatile("cp.async.wait_group 1;" ::: "memory");
        } else {
            asm volatile("cp.async.wait_group 0;" ::: "memory");
        }
        __syncthreads();

        const uint32_t stg = sb + (kb & 1) * MH_STG_BYTES;
        const __half* S   = (const __half*)(dsm + (kb & 1) * MH_STG_BYTES);
        const __half* AsH = S;
        const __half* AsL = S + MH_ARR;
        const __half* BsH = S + 2 * MH_ARR;
        const __half* BsL = S + 3 * MH_ARR;

#pragma unroll
        for (int kk = 0; kk < 2; kk++) {
            if (TERMS == 1) {
                // ldmatrix fast path: 8 LDM4 + 32 HMMA per kk
                const uint32_t kOff = (uint32_t)(kk * 32);
                uint32_t ah[4][4], bh4[4][4];
#pragma unroll
                for (int mt = 0; mt < 4; mt++) {
                    const uint32_t ad = stg + aLane + (uint32_t)(mt * 16 * MH_ROW * 2) + kOff;
                    LDM4(ah[mt][0], ah[mt][1], ah[mt][2], ah[mt][3], ad);
                }
#pragma unroll
                for (int np = 0; np < 4; np++) {
                    const uint32_t bd = stg + bLane + (uint32_t)(np * 16 * MH_ROW * 2) + kOff;
                    LDM4(bh4[np][0], bh4[np][1], bh4[np][2], bh4[np][3], bd);
                }
#pragma unroll
                for (int nt = 0; nt < 8; nt++) {
                    const int np = nt >> 1, sel = (nt & 1) * 2;
#pragma unroll
                    for (int mt = 0; mt < 4; mt++)
                        mma16(acc[mt][nt], ah[mt], bh4[np][sel], bh4[np][sel + 1]);
                }
            } else {
                const int ko = kk * 16 + 2 * tig;
                uint32_t ah[4][4], al[4][4];
#pragma unroll
                for (int mt = 0; mt < 4; mt++) {
                    const int rr = (wm + 16 * mt + tg) * MH_ROW + ko;
                    ah[mt][0] = *(const uint32_t*)(AsH + rr);
                    ah[mt][1] = *(const uint32_t*)(AsH + rr + 8 * MH_ROW);
                    ah[mt][2] = *(const uint32_t*)(AsH + rr + 8);
                    ah[mt][3] = *(const uint32_t*)(AsH + rr + 8 * MH_ROW + 8);
                    if (TERMS == 3) {
                        al[mt][0] = *(const uint32_t*)(AsL + rr);
                        al[mt][1] = *(const uint32_t*)(AsL + rr + 8 * MH_ROW);
                        al[mt][2] = *(const uint32_t*)(AsL + rr + 8);
                        al[mt][3] = *(const uint32_t*)(AsL + rr + 8 * MH_ROW + 8);
                    }
                }
#pragma unroll
                for (int nt = 0; nt < 8; nt++) {
                    const int rb = (wn + 8 * nt + tg) * MH_ROW + ko;
                    const uint32_t bh0 = *(const uint32_t*)(BsH + rb);
                    const uint32_t bh1 = *(const uint32_t*)(BsH + rb + 8);
                    uint32_t bl0 = 0, bl1 = 0;
                    if (TERMS >= 2) {
                        bl0 = *(const uint32_t*)(BsL + rb);
                        bl1 = *(const uint32_t*)(BsL + rb + 8);
                    }
#pragma unroll
                    for (int mt = 0; mt < 4; mt++) {
                        mma16(acc[mt][nt], ah[mt], bh0, bh1);            // Ah*Bh
                        if (TERMS >= 2) mma16(acc[mt][nt], ah[mt], bl0, bl1);  // Ah*Bl
                        if (TERMS == 3) mma16(acc[mt][nt], al[mt], bh0, bh1);  // Al*Bh
                    }
                }
            }
        }
        __syncthreads();
    }

    // ---------------- epilogue ----------------
    float s = 1.f;
    if (SCALE) s = g_scale[zb];
    __half* tsH = (__half*)dsm;
    __half* tsL = (__half*)(dsm + 34816);

#pragma unroll
    for (int mt = 0; mt < 4; mt++) {
        const int r = wm + 16 * mt + tg;
#pragma unroll
        for (int nt = 0; nt < 8; nt++) {
            const int c = wn + 8 * nt + 2 * tig;
            float v0 = acc[mt][nt][0], v1 = acc[mt][nt][1];
            float v2 = acc[mt][nt][2], v3 = acc[mt][nt][3];
            if (SCALE) { v0 *= s; v1 *= s; v2 *= s; v3 *= s; }
            if (ZDIAG) {
                const int gr = m0 + r, gc = n0 + c;
                v0 = (gr == gc)         ? 2.f - v0 : -v0;
                v1 = (gr == gc + 1)     ? 2.f - v1 : -v1;
                v2 = (gr + 8 == gc)     ? 2.f - v2 : -v2;
                v3 = (gr + 8 == gc + 1) ? 2.f - v3 : -v3;
            }
            if (OF32) {
                float b0 = 0.f, b1 = 0.f;
                if (BIAS) { b0 = bias[n0 + c]; b1 = bias[n0 + c + 1]; }
                float* cf = Cf + zb * cB;
                *(float2*)&cf[(long)(m0 + r) * ldc + n0 + c] = make_float2(v0 + b0, v1 + b1);
                *(float2*)&cf[(long)(m0 + r + 8) * ldc + n0 + c] = make_float2(v2 + b0, v3 + b1);
            }
            if (OH || OT) {
                __half h0, h1, h2, h3, l0, l1, l2, l3;
                if (LO) {
                    h_split(v0, h0, l0); h_split(v1, h1, l1);
                    h_split(v2, h2, l2); h_split(v3, h3, l3);
                } else {
                    h0 = __float2half_rn(v0); h1 = __float2half_rn(v1);
                    h2 = __float2half_rn(v2); h3 = __float2half_rn(v3);
                }
                if (OH) {
                    __half* ch = Ch + zb * cB;
                    *(__half2*)&ch[(long)(m0 + r) * ldc + n0 + c]     = __halves2half2(h0, h1);
                    *(__half2*)&ch[(long)(m0 + r + 8) * ldc + n0 + c] = __halves2half2(h2, h3);
                    if (LO) {
                        __half* cl = Cl + zb * cB;
                        *(__half2*)&cl[(long)(m0 + r) * ldc + n0 + c]     = __halves2half2(l0, l1);
                        *(__half2*)&cl[(long)(m0 + r + 8) * ldc + n0 + c] = __halves2half2(l2, l3);
                    }
                }
                if (OT) {
                    tsH[c * 136 + r]           = h0;
                    tsH[(c + 1) * 136 + r]     = h1;
                    tsH[c * 136 + r + 8]       = h2;
                    tsH[(c + 1) * 136 + r + 8] = h3;
                    if (LO) {
                        tsL[c * 136 + r]           = l0;
                        tsL[(c + 1) * 136 + r]     = l1;
                        tsL[c * 136 + r + 8]       = l2;
                        tsL[(c + 1) * 136 + r + 8] = l3;
                    }
                }
            }
        }
    }
    if (OT) {
        __syncthreads();
        const uint4* srcH = (const uint4*)(tsH + t * 136);
        uint4* dH = (uint4*)(CtH + zb * cB + (long)(n0 + t) * ldc + m0);
#pragma unroll
        for (int j = 0; j < 16; j++) dH[j] = srcH[j];
        if (LO) {
            const uint4* srcL = (const uint4*)(tsL + t * 136);
            uint4* dL = (uint4*)(CtL + zb * cB + (long)(n0 + t) * ldc + m0);
#pragma unroll
            for (int j = 0; j < 16; j++) dL[j] = srcL[j];
        }
    }
}

// ---------------- small-N SGEMM: 64(M)x64(N) tile, BK=16, 256 threads, 4x4 ------
// TRIMK: 1 -> (TRANSA path, A=W lower-tri) contributions need k >= m0.
// OSPLIT: 1 -> write fp16 hi/lo split (ChG/ClG) instead of fp32.
template<int TRANSA, int ANORM, int TRIMK, int OSPLIT>
__global__ __launch_bounds__(256) void sgemm_n64(
    const float* __restrict__ Ag, const float* __restrict__ Bg, float* __restrict__ Cg,
    __half* __restrict__ ChG, __half* __restrict__ ClG,
    int K, int lda, int ldb, int ldc,
    long aO, long aI, long bO, long bI, long cO, long cI)
{
    const int z = blockIdx.z;
    const float* A = Ag + (long)(z >> 3) * aO + (long)(z & 7) * aI;
    const float* B = Bg + (long)(z >> 3) * bO + (long)(z & 7) * bI;
    const long coff = (long)(z >> 3) * cO + (long)(z & 7) * cI;
    const float* mu   = g_mu   + (z & 7) * SC;
    const float* rstd = g_rstd + (z & 7) * SC;

    const int m0 = blockIdx.x * 64;
    const int t  = threadIdx.x;
    const int ty = t >> 4, tx = t & 15;

    __shared__ float As[16][64];
    __shared__ float Bs[16][64];

    float acc[4][4];
#pragma unroll
    for (int i = 0; i < 4; i++)
#pragma unroll
        for (int j = 0; j < 4; j++) acc[i][j] = 0.f;

    const int kstart = TRIMK ? m0 : 0;
    for (int k0 = kstart; k0 < K; k0 += 16) {
        if (TRANSA) {
            const int kr = t >> 4, mc = (t & 15) * 4;
            *(float4*)&As[kr][mc] = *(const float4*)&A[(long)(k0 + kr) * lda + m0 + mc];
        } else {
            const int ar = t >> 2, ac = (t & 3) * 4;
            float4 v = *(const float4*)&A[(long)(m0 + ar) * lda + k0 + ac];
            if (ANORM) {
                v.x = (v.x - mu[k0 + ac + 0]) * rstd[k0 + ac + 0];
                v.y = (v.y - mu[k0 + ac + 1]) * rstd[k0 + ac + 1];
                v.z = (v.z - mu[k0 + ac + 2]) * rstd[k0 + ac + 2];
                v.w = (v.w - mu[k0 + ac + 3]) * rstd[k0 + ac + 3];
            }
            As[ac + 0][ar] = v.x;
            As[ac + 1][ar] = v.y;
            As[ac + 2][ar] = v.z;
            As[ac + 3][ar] = v.w;
        }
        {
            const int kr = t >> 4, nc = (t & 15) * 4;
            *(float4*)&Bs[kr][nc] = *(const float4*)&B[(long)(k0 + kr) * ldb + nc];
        }
        __syncthreads();
#pragma unroll
        for (int kk = 0; kk < 16; kk++) {
            float a[4], b[4];
            *(float4*)a = *(const float4*)&As[kk][ty * 4];
            *(float4*)b = *(const float4*)&Bs[kk][tx * 4];
#pragma unroll
            for (int i = 0; i < 4; i++)
#pragma unroll
                for (int j = 0; j < 4; j++)
                    acc[i][j] = fmaf(a[i], b[j], acc[i][j]);
        }
        __syncthreads();
    }

#pragma unroll
    for (int i = 0; i < 4; i++) {
        const long rowo = (long)(m0 + ty * 4 + i) * ldc + tx * 4;
        if (OSPLIT) {
            __half* ch = ChG + coff;
            __half* cl = ClG + coff;
#pragma unroll
            for (int j = 0; j < 4; j += 2) {
                __half h0, h1, l0, l1;
                h_split(acc[i][j],     h0, l0);
                h_split(acc[i][j + 1], h1, l1);
                *(__half2*)&ch[rowo + j] = __halves2half2(h0, h1);
                *(__half2*)&cl[rowo + j] = __halves2half2(l0, l1);
            }
        } else {
            float* C = Cg + coff;
#pragma unroll
            for (int j = 0; j < 4; j++)
                C[rowo + j] = acc[i][j];
        }
    }
}

// ---------------- Laplacian: W = tril(exp(-L1/4)); writes W, Wh/l, Wth/l --------
__global__ __launch_bounds__(1024) void laplacian_kernel()
{
    const int z = blockIdx.z;
    const int b = z >> 3, h = z & 7;
    const int i0 = blockIdx.y * 32, j0 = blockIdx.x * 32;
    const int tx = threadIdx.x, ty = threadIdx.y;
    const int tid = ty * 32 + tx;

    float*  Wp  = g_W   + (long)z * SC * SC;
    __half* Whp = g_Wh  + (long)z * SC * SC;
    __half* Wlp = g_Wl  + (long)z * SC * SC;
    __half* Wth = g_Wth + (long)z * SC * SC;
    __half* Wtl = g_Wtl + (long)z * SC * SC;

    if (j0 > i0 + 31) {   // fully masked tile (uniform per block)
        const long o  = (long)(i0 + ty) * SC + j0 + tx;
        const long ot = (long)(j0 + ty) * SC + i0 + tx;
        Wp[o] = 0.f;
        Whp[o] = __float2half(0.f); Wlp[o] = __float2half(0.f);
        Wth[ot] = __float2half(0.f); Wtl[ot] = __float2half(0.f);
        return;
    }

    const float* qp = g_qkv + (long)b * SC * 3 * DIMC + h * HDC;
    const float* kp = g_qkv + (long)b * SC * 3 * DIMC + DIMC + h * HDC;

    __shared__ float qs[32][65];
    __shared__ float ks[32][65];
    __shared__ float tr[32][33];

    for (int idx = tid; idx < 2048; idx += 1024) {
        const int r = idx >> 6, d = idx & 63;
        qs[r][d] = qp[(long)(i0 + r) * (3 * DIMC) + d];
        ks[r][d] = kp[(long)(j0 + r) * (3 * DIMC) + d];
    }
    __syncthreads();

    const int i = i0 + ty, j = j0 + tx;
    float out = 0.f;
    if (j <= i) {
        float s = 0.f;
#pragma unroll
        for (int d = 0; d < 64; d++)
            s += fabsf(qs[ty][d] - ks[tx][d]);
        out = expf(-0.25f * s);
    }
    const long o = (long)i * SC + j;
    Wp[o] = out;
    __half hh, hl;
    h_split(out, hh, hl);
    Whp[o] = hh; Wlp[o] = hl;

    tr[ty][tx] = out;
    __syncthreads();
    const float tv = tr[tx][ty];              // = W(i0+tx, j0+ty)
    h_split(tv, hh, hl);
    const long ot = (long)(j0 + ty) * SC + i0 + tx;
    Wth[ot] = hh; Wtl[ot] = hl;
}

// ---------------- NS init scale, phase 1: per-slice partials --------------------
__global__ __launch_bounds__(512) void ns_scale_p1()
{
    const int sl = blockIdx.x, z = blockIdx.y;
    const float* W = g_W + (long)z * SC * SC;
    const int t = threadIdx.x, wid = t >> 5, lid = t & 31;
    const int r0 = sl * 64;

    float cs = 0.f;
    for (int i = r0; i < r0 + 64; i++) cs += W[(long)i * SC + t];
    g_cs_part[sl][z][t] = cs;

    float rmax = 0.f;
    for (int r = r0 + wid * 4; r < r0 + wid * 4 + 4; r++) {
        const float4* row = (const float4*)&W[(long)r * SC];
        float s = 0.f;
#pragma unroll
        for (int p = 0; p < 4; p++) {
            const float4 v = row[lid + p * 32];
            s += v.x + v.y + v.z + v.w;
        }
#pragma unroll
        for (int o = 16; o > 0; o >>= 1) s += __shfl_xor_sync(0xFFFFFFFFu, s, o);
        rmax = fmaxf(rmax, s);
    }
    __shared__ float red[16];
    if (lid == 0) red[wid] = rmax;
    __syncthreads();
    if (t == 0) {
        float m = red[0];
#pragma unroll
        for (int i = 1; i < 16; i++) m = fmaxf(m, red[i]);
        g_rm_part[sl][z] = m;
    }
}

// ---------------- NS init scale, phase 2: combine -------------------------------
__global__ __launch_bounds__(512) void ns_scale_p2()
{
    const int z = blockIdx.x, t = threadIdx.x;
    float cs = 0.f;
#pragma unroll
    for (int sl = 0; sl < 8; sl++) cs += g_cs_part[sl][z][t];

    __shared__ float red[512];
    red[t] = cs; __syncthreads();
    for (int s = 256; s > 0; s >>= 1) {
        if (t < s) red[t] = fmaxf(red[t], red[t + s]);
        __syncthreads();
    }
    if (t == 0) {
        float rmax = g_rm_part[0][z];
#pragma unroll
        for (int sl = 1; sl < 8; sl++) rmax = fmaxf(rmax, g_rm_part[sl][z]);
        g_scale[z] = 1.f / (red[0] * rmax);
    }
}

// ---------------- whitening stats per (h, key column j) -------------------------
__global__ __launch_bounds__(256) void stats_kernel()
{
    const int jc = blockIdx.x, h = blockIdx.y;
    const int t = threadIdx.x;
    const int j = jc * 64 + (t & 63);
    const int slice = t >> 6;

    float s = 0.f, s2 = 0.f;
    for (int b = 0; b < BC; b++) {
        const float* Wp = g_W + (long)(b * HC + h) * SC * SC + j;
        for (int i = slice * 128; i < slice * 128 + 128; i++) {
            const float v = Wp[(long)i * SC];
            s += v; s2 += v * v;
        }
    }
    __shared__ float S1[256], S2[256];
    S1[t] = s; S2[t] = s2;
    __syncthreads();
    if (slice == 0) {
        s  = S1[t] + S1[t + 64] + S1[t + 128] + S1[t + 192];
        s2 = S2[t] + S2[t + 64] + S2[t + 128] + S2[t + 192];
        const float n = (float)(BC * SC);
        const float m = s / n;
        const float var = (s2 - n * m * m) / (n - 1.f);
        g_mu[h * SC + j]   = m;
        g_rstd[h * SC + j] = rsqrtf(var + EPSC);
    }
}

// ---------------- launch --------------------------------------------------------
extern "C" void kernel_launch(void* const* d_in, const int* in_sizes, int n_in,
                              void* d_out, int out_size)
{
    (void)in_sizes; (void)n_in; (void)out_size;
    const float* x      = (const float*)d_in[0];
    const float* qkv_w  = (const float*)d_in[1];
    const float* qkv_b  = (const float*)d_in[2];
    const float* proj_w = (const float*)d_in[3];
    const float* proj_b = (const float*)d_in[4];
    float* out = (float*)d_out;

    static float *pQKV = nullptr, *pW, *pXf, *pZf, *pCTX, *pCTX2;
    static __half *pWh, *pWl, *pWth, *pWtl, *pZth, *pZtl;
    static __half *pXh[2], *pXl[2], *pXth[2], *pXtl[2];
    static __half *pxh, *pxl, *pwqh, *pwql, *ppwh, *ppwl, *pgah, *pgal;
    static cudaStream_t s1;
    static cudaEvent_t evW, evSide;
    if (!pQKV) {
        cudaGetSymbolAddress((void**)&pQKV, g_qkv);
        cudaGetSymbolAddress((void**)&pW,   g_W);
        cudaGetSymbolAddress((void**)&pWh,  g_Wh);
        cudaGetSymbolAddress((void**)&pWl,  g_Wl);
        cudaGetSymbolAddress((void**)&pWth, g_Wth);
        cudaGetSymbolAddress((void**)&pWtl, g_Wtl);
        cudaGetSymbolAddress((void**)&pZth, g_Zth);
        cudaGetSymbolAddress((void**)&pZtl, g_Ztl);
        cudaGetSymbolAddress((void**)&pXh[0],  g_Xh0);
        cudaGetSymbolAddress((void**)&pXl[0],  g_Xl0);
        cudaGetSymbolAddress((void**)&pXh[1],  g_Xh1);
        cudaGetSymbolAddress((void**)&pXl[1],  g_Xl1);
        cudaGetSymbolAddress((void**)&pXth[0], g_Xth0);
        cudaGetSymbolAddress((void**)&pXtl[0], g_Xtl0);
        cudaGetSymbolAddress((void**)&pXth[1], g_Xth1);
        cudaGetSymbolAddress((void**)&pXtl[1], g_Xtl1);
        cudaGetSymbolAddress((void**)&pXf,  g_Xf);
        cudaGetSymbolAddress((void**)&pZf,  g_Zf);
        cudaGetSymbolAddress((void**)&pxh,  g_xh);
        cudaGetSymbolAddress((void**)&pxl,  g_xl);
        cudaGetSymbolAddress((void**)&pwqh, g_wqh);
        cudaGetSymbolAddress((void**)&pwql, g_wql);
        cudaGetSymbolAddress((void**)&ppwh, g_pwh);
        cudaGetSymbolAddress((void**)&ppwl, g_pwl);
        cudaGetSymbolAddress((void**)&pgah, g_gah);
        cudaGetSymbolAddress((void**)&pgal, g_gal);
        cudaGetSymbolAddress((void**)&pCTX, g_ctx);
        cudaGetSymbolAddress((void**)&pCTX2,g_ctx2);
        cudaStreamCreateWithFlags(&s1, cudaStreamNonBlocking);
        cudaEventCreateWithFlags(&evW,    cudaEventDisableTiming);
        cudaEventCreateWithFlags(&evSide, cudaEventDisableTiming);
        cudaFuncSetAttribute(mma_h<3,0,0,0,0,1,1,0,0,0>, cudaFuncAttributeMaxDynamicSharedMemorySize, MH_SMEM);
        cudaFuncSetAttribute(mma_h<1,1,1,1,1,0,0,1,0,0>, cudaFuncAttributeMaxDynamicSharedMemorySize, MH_SMEM);
        cudaFuncSetAttribute(mma_h<1,2,0,0,1,0,0,1,1,0>, cudaFuncAttributeMaxDynamicSharedMemorySize, MH_SMEM);
        cudaFuncSetAttribute(mma_h<1,0,1,1,0,0,0,1,0,0>, cudaFuncAttributeMaxDynamicSharedMemorySize, MH_SMEM);
        cudaFuncSetAttribute(mma_h<1,0,0,0,0,0,0,1,1,0>, cudaFuncAttributeMaxDynamicSharedMemorySize, MH_SMEM);
        cudaFuncSetAttribute(mma_h<1,0,0,0,0,0,1,0,1,0>, cudaFuncAttributeMaxDynamicSharedMemorySize, MH_SMEM);
        cudaFuncSetAttribute(mma_h<2,0,1,1,0,0,1,0,0,0>, cudaFuncAttributeMaxDynamicSharedMemorySize, MH_SMEM);
    }

    const long MS = (long)SC * SC;
    const long CS = (long)SC * HDC;

    // 0) split static operands
    split_f16<<<512, 256>>>(x, pxh, pxl);
    split_f16<<<768, 256>>>(qkv_w, pwqh, pwql);
    split_f16<<<256, 256>>>(proj_w, ppwh, ppwl);

    // 1) qkv = x @ qkv_w^T + qkv_b   (NT, 3-term, fp32 out)
    mma_h<3,0,0,0,0,1,1,0,0,0><<<dim3(12, 8, 1), 128, MH_SMEM>>>(
        pxh, pxl, pwqh, pwql, nullptr, nullptr, nullptr, nullptr,
        pQKV, qkv_b, 512, 512, 1536, 0, 0, 0);

    // 2) W = tril(exp(-L1/4)) + splits of W and W^T
    laplacian_kernel<<<dim3(16, 16, 16), dim3(32, 32)>>>();

    // ---- fork: ctx + stats depend only on {W, qkv}; run beside the NS chain ----
    cudaEventRecord(evW, 0);
    cudaStreamWaitEvent(s1, evW, 0);

    // 7) ctx = W^T @ v   (side stream; A=W lower-tri via TRANSA: k >= m0 only)
    sgemm_n64<1, 0, 1, 0><<<dim3(8, 1, 16), 256, 0, s1>>>(
        pW, pQKV + 2 * DIMC, pCTX, nullptr, nullptr, 512, 512, 3 * DIMC, HDC,
        8 * MS, MS, (long)SC * 3 * DIMC, HDC, 8 * CS, CS);
    // 6) whitening stats (side stream)
    stats_kernel<<<dim3(8, 8), 256, 0, s1>>>();
    cudaEventRecord(evSide, s1);

    // 3) scale = 1/(n1*ninf), parallel two-phase (main stream)
    ns_scale_p1<<<dim3(8, 16), 512>>>();
    ns_scale_p2<<<16, 512>>>();

    // 5) Newton-Schulz (dual-orientation, all NT):
    //    Zt = 2I - Xt@W^T ; X' = X@Z (B = Zt) ; Xt' via transposed epilogue.
    //    Precision: it0-3 1-term (ldmatrix); it4 Zt 2-term.
    //    ctx2 = X5 @ ctx reassociated as X4 @ (Z4 @ ctx); it3 X' keeps only
    //    Xt4-hi (OT) + fp32 X4 (OF32); fp16 X4 h/l outputs are dead -> dropped.
    mma_h<1,1,1,1,1,0,0,1,0,0><<<dim3(4, 4, 16), 128, MH_SMEM>>>(   // Zt0 = 2I - s*(W W^T)
        pWh, pWl, pWh, pWl, pZth, pZtl, nullptr, nullptr, nullptr, nullptr,
        512, 512, 512, MS, MS, MS);
    mma_h<1,2,0,0,1,0,0,1,1,0><<<dim3(4, 4, 16), 128, MH_SMEM>>>(   // X1 = s*(Wt Z0)
        pWth, pWtl, pZth, pZtl, pXh[0], pXl[0], pXth[0], pXtl[0], nullptr, nullptr,
        512, 512, 512, MS, MS, MS);
    int cur = 0;
    for (int it = 1; it < 4; it++) {
        mma_h<1,0,1,1,0,0,0,1,0,0><<<dim3(4, 4, 16), 128, MH_SMEM>>>(   // Zt = 2I - Xt W^T
            pXth[cur], pXtl[cur], pWh, pWl, pZth, pZtl, nullptr, nullptr, nullptr, nullptr,
            512, 512, 512, MS, MS, MS);
        if (it < 3) {
            mma_h<1,0,0,0,0,0,0,1,1,0><<<dim3(4, 4, 16), 128, MH_SMEM>>>(   // X' = X Z
                pXh[cur], pXl[cur], pZth, pZtl,
                pXh[1 - cur], pXl[1 - cur], pXth[1 - cur], pXtl[1 - cur], nullptr, nullptr,
                512, 512, 512, MS, MS, MS);
        } else {
            mma_h<1,0,0,0,0,0,1,0,1,0><<<dim3(4, 4, 16), 128, MH_SMEM>>>(   // Xt4-hi + X4 fp32
                pXh[cur], pXl[cur], pZth, pZtl,
                nullptr, nullptr, pXth[1 - cur], pXtl[1 - cur], pXf, nullptr,
                512, 512, 512, MS, MS, MS);
        }
        cur = 1 - cur;
    }
    // it4: Zt4 = 2I - Xt4 W^T (2-term, fp32 out).
    mma_h<2,0,1,1,0,0,1,0,0,0><<<dim3(4, 4, 16), 128, MH_SMEM>>>(
        pXth[cur], pXtl[cur], pWh, pWl, nullptr, nullptr, nullptr, nullptr,
        pZf, nullptr, 512, 512, 512, MS, MS, MS);

    // ---- join: need ctx (8a) and stats (ga) ----
    cudaStreamWaitEvent(0, evSide, 0);

    // 8a) tmp = Z4 @ ctx = (Zt4)^T @ ctx   (fp32)
    sgemm_n64<1, 0, 0, 0><<<dim3(8, 1, 16), 256>>>(
        pZf, pCTX, pCTX2, nullptr, nullptr, 512, 512, HDC, HDC,
        8 * MS, MS, 8 * CS, CS, 8 * CS, CS);

    // 8b) ctx2 = X4 @ tmp   (fp32; result into pCTX)
    sgemm_n64<0, 0, 0, 0><<<dim3(8, 1, 16), 256>>>(
        pXf, pCTX2, pCTX, nullptr, nullptr, 512, 512, HDC, HDC,
        8 * MS, MS, 8 * CS, CS, 8 * CS, CS);

    // 9) ga = W_norm @ ctx2 -> [b, s, h*64+d], fused fp16 split
    sgemm_n64<0, 1, 0, 1><<<dim3(8, 1, 16), 256>>>(
        pW, pCTX, nullptr, pgah, pgal, 512, 512, HDC, 512,
        8 * MS, MS, 8 * CS, CS, MS, HDC);

    // 10) out = ga @ proj_w^T + proj_b   (NT, 3-term, fp32 out)
    mma_h<3,0,0,0,0,1,1,0,0,0><<<dim3(4, 8, 1), 128, MH_SMEM>>>(
        pgah, pgal, ppwh, ppwl, nullptr, nullptr, nullptr, nullptr,
        out, proj_b, 512, 512, 512, 0, 0, 0);
}